// round 1
// baseline (speedup 1.0000x reference)
#include <cuda_runtime.h>
#include <math.h>

#define BS 16
#define TT 1024
#define T2 2048
#define FD 512
#define ALPHA 0.1f

// Scratch (no cudaMalloc allowed): 64MB Wh + small per-row vectors.
static __device__ float g_Wh[(size_t)BS * T2 * FD];
static __device__ float g_w1[BS * T2];
static __device__ float g_w2[BS * T2];
static __device__ float g_F1[BS * T2];
static __device__ float g_Fa[BS * T2];
static __device__ float g_E1[BS * T2];
static __device__ float g_Ea[BS * T2];

// ---------------------------------------------------------------------------
// Kernel A: Wh = [x_a ; x_v] @ W   (per batch: 2048x512 = 2048x512 @ 512x512)
// Tiles: TM=128 rows, TN=64 feats, TK=16. 256 threads, each 8x4 accumulators.
// ---------------------------------------------------------------------------
__global__ __launch_bounds__(256) void k_wh(const float* __restrict__ xa,
                                            const float* __restrict__ xv,
                                            const float* __restrict__ W) {
    __shared__ float As[16][132];   // k-major, padded vs bank conflicts
    __shared__ float Bs[16][64];
    const int b  = blockIdx.z;
    const int r0 = blockIdx.y * 128;
    const int f0 = blockIdx.x * 64;
    const int tid = threadIdx.x;
    const int ty = tid >> 4, tx = tid & 15;

    const float* __restrict__ h = (r0 < TT)
        ? (xa + ((size_t)b * TT + r0) * FD)
        : (xv + ((size_t)b * TT + (r0 - TT)) * FD);

    float acc[8][4];
    #pragma unroll
    for (int i = 0; i < 8; i++)
        #pragma unroll
        for (int j = 0; j < 4; j++) acc[i][j] = 0.f;

    for (int k0 = 0; k0 < FD; k0 += 16) {
        #pragma unroll
        for (int s = 0; s < 8; s++) {
            int e = tid + 256 * s;          // 0..2047
            int row = e >> 4, kk = e & 15;
            As[kk][row] = h[(size_t)row * FD + k0 + kk];
        }
        #pragma unroll
        for (int s = 0; s < 4; s++) {
            int e = tid + 256 * s;          // 0..1023
            int kk = e >> 6, ff = e & 63;
            Bs[kk][ff] = W[(size_t)(k0 + kk) * FD + f0 + ff];
        }
        __syncthreads();
        #pragma unroll
        for (int k = 0; k < 16; k++) {
            float av[8], bv[4];
            *(float4*)&av[0] = *(const float4*)&As[k][ty * 8];
            *(float4*)&av[4] = *(const float4*)&As[k][ty * 8 + 4];
            *(float4*)&bv[0] = *(const float4*)&Bs[k][tx * 4];
            #pragma unroll
            for (int i = 0; i < 8; i++)
                #pragma unroll
                for (int j = 0; j < 4; j++)
                    acc[i][j] = fmaf(av[i], bv[j], acc[i][j]);
        }
        __syncthreads();
    }

    float* out = g_Wh + ((size_t)b * T2 + r0) * FD + f0;
    #pragma unroll
    for (int i = 0; i < 8; i++) {
        int row = ty * 8 + i;
        *(float4*)&out[(size_t)row * FD + tx * 4] = *(float4*)&acc[i][0];
    }
}

// ---------------------------------------------------------------------------
// Kernel A2: w1[row] = Wh[row]·a[:512],  w2[row] = Wh[row]·a[512:]
// One warp per row.
// ---------------------------------------------------------------------------
__global__ __launch_bounds__(256) void k_w12(const float* __restrict__ avec) {
    int row  = blockIdx.x * 8 + (threadIdx.x >> 5);
    int lane = threadIdx.x & 31;
    const float* wh = g_Wh + (size_t)row * FD;
    float s1 = 0.f, s2 = 0.f;
    #pragma unroll
    for (int q = 0; q < 4; q++) {
        int f4 = lane + 32 * q;            // float4 index 0..127
        float4 v  = *(const float4*)&wh[f4 * 4];
        float4 a1 = *(const float4*)&avec[f4 * 4];
        float4 a2 = *(const float4*)&avec[FD + f4 * 4];
        s1 += v.x * a1.x + v.y * a1.y + v.z * a1.z + v.w * a1.w;
        s2 += v.x * a2.x + v.y * a2.y + v.z * a2.z + v.w * a2.w;
    }
    #pragma unroll
    for (int o = 16; o > 0; o >>= 1) {
        s1 += __shfl_xor_sync(0xffffffffu, s1, o);
        s2 += __shfl_xor_sync(0xffffffffu, s2, o);
    }
    if (lane == 0) { g_w1[row] = s1; g_w2[row] = s2; }
}

// ---------------------------------------------------------------------------
// Kernel B: per batch, M = max_j w2_j; then F1/Fa (per i) and E1/Ea (per j).
// p_ij = adj * ( s>0 ? F1_i*E1_j : Fa_i*Ea_j ),  all p in [0,1].
// ---------------------------------------------------------------------------
__global__ __launch_bounds__(256) void k_prep() {
    __shared__ float red[256];
    __shared__ float Msh;
    int b = blockIdx.x, tid = threadIdx.x;
    const float* w2 = g_w2 + b * T2;
    float m = -1e30f;
    for (int i = tid; i < T2; i += 256) m = fmaxf(m, w2[i]);
    red[tid] = m; __syncthreads();
    for (int s = 128; s > 0; s >>= 1) {
        if (tid < s) red[tid] = fmaxf(red[tid], red[tid + s]);
        __syncthreads();
    }
    if (tid == 0) Msh = red[0];
    __syncthreads();
    float M = Msh;
    const float* w1 = g_w1 + b * T2;
    for (int i = tid; i < T2; i += 256) {
        float v1 = w1[i], v2 = w2[i];
        float s  = v1 + M;
        float mi = s > 0.f ? s : ALPHA * s;   // leaky(max score) >= all leaky scores
        g_F1[b * T2 + i] = expf(v1 - mi);
        g_Fa[b * T2 + i] = expf(ALPHA * v1 - mi);
        g_E1[b * T2 + i] = expf(v2);
        g_Ea[b * T2 + i] = expf(ALPHA * v2);
    }
}

// ---------------------------------------------------------------------------
// Kernel C: fused masked-softmax-attention @ Wh + elu + split-write.
// Block: (batch, 32-row tile) x all 512 feats. 256 threads = 4 rowgrp x 64 colgrp,
// each thread 8x8 fp32 accumulators. TJ=16 j per iteration; P tile built on the
// fly from adj + factorized exp tables; Z accumulated by warp 0.
// ---------------------------------------------------------------------------
#define TI 32
#define TJ 16
__global__ __launch_bounds__(256, 2) void k_attn(const int* __restrict__ adj,
                                                 float* __restrict__ out) {
    __shared__ float whs[TJ][FD];    // 32KB
    __shared__ float ps[TJ][TI];     // 2KB, [k][i] so GEMM reads are broadcast/float4
    __shared__ float rw1[TI], rF1[TI], rFa[TI], zs[TI];

    const int b  = blockIdx.y;
    const int i0 = blockIdx.x * TI;
    const int tid = threadIdx.x;
    const int r = tid >> 6;          // row group 0..3
    const int c = tid & 63;          // feat group 0..63

    if (tid < TI) {
        int gi = b * T2 + i0 + tid;
        rw1[tid] = g_w1[gi];
        rF1[tid] = g_F1[gi];
        rFa[tid] = g_Fa[gi];
    }
    float acc[8][8];
    #pragma unroll
    for (int i = 0; i < 8; i++)
        #pragma unroll
        for (int j = 0; j < 8; j++) acc[i][j] = 0.f;
    float zreg = 0.f;

    const int pi = tid >> 3;              // p-gen row 0..31
    const int pj = (tid & 7) * 2;         // p-gen j pair 0,2,..,14
    const size_t adjrow = ((size_t)b * T2 + i0 + pi) * T2;
    __syncthreads();

    for (int j0 = 0; j0 < T2; j0 += TJ) {
        // stage Wh tile [TJ][512]
        const float* whsrc = g_Wh + ((size_t)b * T2 + j0) * FD;
        #pragma unroll
        for (int s = 0; s < 8; s++) {
            int e = tid + 256 * s;         // float4 index 0..2047
            int kk = e >> 7, fq = e & 127;
            *(float4*)&whs[kk][fq * 4] =
                *(const float4*)&whsrc[(size_t)kk * FD + fq * 4];
        }
        // build P tile (2 elems/thread), coalesced int2 adj read
        {
            int2 ad = *(const int2*)&adj[adjrow + j0 + pj];
            int gj = b * T2 + j0 + pj;
            float w1i = rw1[pi], f1 = rF1[pi], fa = rFa[pi];
            float w20 = g_w2[gj],     w21 = g_w2[gj + 1];
            float e10 = g_E1[gj],     e11 = g_E1[gj + 1];
            float ea0 = g_Ea[gj],     ea1 = g_Ea[gj + 1];
            float p0 = (w1i + w20 > 0.f) ? f1 * e10 : fa * ea0;
            float p1 = (w1i + w21 > 0.f) ? f1 * e11 : fa * ea1;
            ps[pj][pi]     = (ad.x > 0) ? p0 : 0.f;
            ps[pj + 1][pi] = (ad.y > 0) ? p1 : 0.f;
        }
        __syncthreads();

        if (tid < TI) {                    // warp 0: softmax denominator
            float z = 0.f;
            #pragma unroll
            for (int k = 0; k < TJ; k++) z += ps[k][tid];
            zreg += z;
        }
        #pragma unroll
        for (int k = 0; k < TJ; k++) {
            float pv[8], wv[8];
            *(float4*)&pv[0] = *(const float4*)&ps[k][r * 8];
            *(float4*)&pv[4] = *(const float4*)&ps[k][r * 8 + 4];
            *(float4*)&wv[0] = *(const float4*)&whs[k][c * 8];
            *(float4*)&wv[4] = *(const float4*)&whs[k][c * 8 + 4];
            #pragma unroll
            for (int i = 0; i < 8; i++)
                #pragma unroll
                for (int j = 0; j < 8; j++)
                    acc[i][j] = fmaf(pv[i], wv[j], acc[i][j]);
        }
        __syncthreads();
    }

    if (tid < TI) zs[tid] = zreg;
    __syncthreads();

    // epilogue: normalize, elu, write with [out_a.flat, out_v.flat] split layout
    #pragma unroll
    for (int i = 0; i < 8; i++) {
        int il = r * 8 + i;
        int g  = i0 + il;
        float inv = 1.f / zs[il];
        size_t base;
        if (g < TT) base = ((size_t)b * TT + g) * FD;
        else        base = ((size_t)BS * TT + (size_t)b * TT + (g - TT)) * FD;
        float v[8];
        #pragma unroll
        for (int j = 0; j < 8; j++) {
            float x = acc[i][j] * inv;
            v[j] = x > 0.f ? x : expm1f(x);
        }
        *(float4*)&out[base + c * 8]     = *(float4*)&v[0];
        *(float4*)&out[base + c * 8 + 4] = *(float4*)&v[4];
    }
}

// ---------------------------------------------------------------------------
extern "C" void kernel_launch(void* const* d_in, const int* in_sizes, int n_in,
                              void* d_out, int out_size) {
    const float* xa  = (const float*)d_in[0];
    const float* xv  = (const float*)d_in[1];
    const int*   adj = (const int*)d_in[2];
    const float* W   = (const float*)d_in[3];
    const float* a   = (const float*)d_in[4];
    float* out = (float*)d_out;

    dim3 gA(FD / 64, T2 / 128, BS);          // 8 x 16 x 16 = 2048 blocks
    k_wh<<<gA, 256>>>(xa, xv, W);
    k_w12<<<BS * T2 / 8, 256>>>(a);          // 4096 blocks, warp/row
    k_prep<<<BS, 256>>>();
    dim3 gC(T2 / TI, BS);                    // 64 x 16 = 1024 blocks
    k_attn<<<gC, 256>>>(adj, out);
}

// round 2
// speedup vs baseline: 1.6339x; 1.6339x over previous
#include <cuda_runtime.h>
#include <math.h>

#define BS 16
#define TT 1024
#define T2 2048
#define FD 512
#define ALPHA 0.1f

typedef unsigned long long u64;

// Scratch (no cudaMalloc allowed): 64MB Wh + small per-row vectors.
static __device__ float g_Wh[(size_t)BS * T2 * FD];
static __device__ float g_w1[BS * T2];
static __device__ float g_w2[BS * T2];
static __device__ float g_F1[BS * T2];
static __device__ float g_Fa[BS * T2];
static __device__ float g_E1[BS * T2];
static __device__ float g_Ea[BS * T2];

// ---- packed f32x2 helpers (Blackwell sm_103a) ------------------------------
__device__ __forceinline__ u64 pk2(float x) {
    u64 r;
    asm("mov.b64 %0, {%1, %1};" : "=l"(r) : "f"(x));
    return r;
}
__device__ __forceinline__ void fma2(u64& d, u64 a, u64 b) {
    asm("fma.rn.f32x2 %0, %1, %2, %0;" : "+l"(d) : "l"(a), "l"(b));
}
__device__ __forceinline__ void upk2(float& lo, float& hi, u64 v) {
    asm("mov.b64 {%0, %1}, %2;" : "=f"(lo), "=f"(hi) : "l"(v));
}

// ---------------------------------------------------------------------------
// Kernel A: Wh = [x_a ; x_v] @ W   (per batch: 2048x512 @ 512x512)
// Tiles: TM=128 rows, TN=128 feats, TK=16. 256 threads, thread tile 8x8, FFMA2.
// ---------------------------------------------------------------------------
__global__ __launch_bounds__(256, 2) void k_wh(const float* __restrict__ xa,
                                               const float* __restrict__ xv,
                                               const float* __restrict__ W) {
    __shared__ float As[16][132];   // k-major, padded vs bank conflicts
    __shared__ float Bs[16][128];
    const int b  = blockIdx.z;
    const int r0 = blockIdx.y * 128;
    const int f0 = blockIdx.x * 128;
    const int tid = threadIdx.x;
    const int ty = tid >> 4, tx = tid & 15;

    const float* __restrict__ h = (r0 < TT)
        ? (xa + ((size_t)b * TT + r0) * FD)
        : (xv + ((size_t)b * TT + (r0 - TT)) * FD);

    u64 acc[8][4];
    #pragma unroll
    for (int i = 0; i < 8; i++)
        #pragma unroll
        for (int j = 0; j < 4; j++) acc[i][j] = 0ull;

    for (int k0 = 0; k0 < FD; k0 += 16) {
        #pragma unroll
        for (int s = 0; s < 8; s++) {
            int e = tid + 256 * s;          // 0..2047
            int row = e >> 4, kk = e & 15;
            As[kk][row] = h[(size_t)row * FD + k0 + kk];
        }
        #pragma unroll
        for (int s = 0; s < 8; s++) {
            int e = tid + 256 * s;          // 0..2047
            int kk = e >> 7, ff = e & 127;
            Bs[kk][ff] = W[(size_t)(k0 + kk) * FD + f0 + ff];
        }
        __syncthreads();
        #pragma unroll
        for (int k = 0; k < 16; k++) {
            float av[8];
            *(float4*)&av[0] = *(const float4*)&As[k][ty * 8];
            *(float4*)&av[4] = *(const float4*)&As[k][ty * 8 + 4];
            ulonglong2 q0 = *(const ulonglong2*)&Bs[k][tx * 8];
            ulonglong2 q1 = *(const ulonglong2*)&Bs[k][tx * 8 + 4];
            u64 bv[4] = {q0.x, q0.y, q1.x, q1.y};
            #pragma unroll
            for (int i = 0; i < 8; i++) {
                u64 a2 = pk2(av[i]);
                #pragma unroll
                for (int j = 0; j < 4; j++) fma2(acc[i][j], a2, bv[j]);
            }
        }
        __syncthreads();
    }

    float* out = g_Wh + ((size_t)b * T2 + r0) * FD + f0;
    #pragma unroll
    for (int i = 0; i < 8; i++) {
        int row = ty * 8 + i;
        float v[8];
        #pragma unroll
        for (int j = 0; j < 4; j++) upk2(v[2 * j], v[2 * j + 1], acc[i][j]);
        *(float4*)&out[(size_t)row * FD + tx * 8]     = *(float4*)&v[0];
        *(float4*)&out[(size_t)row * FD + tx * 8 + 4] = *(float4*)&v[4];
    }
}

// ---------------------------------------------------------------------------
// Kernel A2: w1[row] = Wh[row]·a[:512],  w2[row] = Wh[row]·a[512:]
// ---------------------------------------------------------------------------
__global__ __launch_bounds__(256) void k_w12(const float* __restrict__ avec) {
    int row  = blockIdx.x * 8 + (threadIdx.x >> 5);
    int lane = threadIdx.x & 31;
    const float* wh = g_Wh + (size_t)row * FD;
    float s1 = 0.f, s2 = 0.f;
    #pragma unroll
    for (int q = 0; q < 4; q++) {
        int f4 = lane + 32 * q;
        float4 v  = *(const float4*)&wh[f4 * 4];
        float4 a1 = *(const float4*)&avec[f4 * 4];
        float4 a2 = *(const float4*)&avec[FD + f4 * 4];
        s1 += v.x * a1.x + v.y * a1.y + v.z * a1.z + v.w * a1.w;
        s2 += v.x * a2.x + v.y * a2.y + v.z * a2.z + v.w * a2.w;
    }
    #pragma unroll
    for (int o = 16; o > 0; o >>= 1) {
        s1 += __shfl_xor_sync(0xffffffffu, s1, o);
        s2 += __shfl_xor_sync(0xffffffffu, s2, o);
    }
    if (lane == 0) { g_w1[row] = s1; g_w2[row] = s2; }
}

// ---------------------------------------------------------------------------
// Kernel B: per batch, M = max_j w2_j; factorized-exp tables.
// p_ij = adj * ( s>0 ? F1_i*E1_j : Fa_i*Ea_j ),  all p in [0,1].
// ---------------------------------------------------------------------------
__global__ __launch_bounds__(256) void k_prep() {
    __shared__ float red[256];
    __shared__ float Msh;
    int b = blockIdx.x, tid = threadIdx.x;
    const float* w2 = g_w2 + b * T2;
    float m = -1e30f;
    for (int i = tid; i < T2; i += 256) m = fmaxf(m, w2[i]);
    red[tid] = m; __syncthreads();
    for (int s = 128; s > 0; s >>= 1) {
        if (tid < s) red[tid] = fmaxf(red[tid], red[tid + s]);
        __syncthreads();
    }
    if (tid == 0) Msh = red[0];
    __syncthreads();
    float M = Msh;
    const float* w1 = g_w1 + b * T2;
    for (int i = tid; i < T2; i += 256) {
        float v1 = w1[i], v2 = w2[i];
        float s  = v1 + M;
        float mi = s > 0.f ? s : ALPHA * s;
        g_F1[b * T2 + i] = expf(v1 - mi);
        g_Fa[b * T2 + i] = expf(ALPHA * v1 - mi);
        g_E1[b * T2 + i] = expf(v2);
        g_Ea[b * T2 + i] = expf(ALPHA * v2);
    }
}

// ---------------------------------------------------------------------------
// Kernel C: fused masked-softmax-attention @ Wh + elu + split-write, FFMA2.
// ---------------------------------------------------------------------------
#define TI 32
#define TJ 16
__global__ __launch_bounds__(256, 2) void k_attn(const int* __restrict__ adj,
                                                 float* __restrict__ out) {
    __shared__ float whs[TJ][FD];    // 32KB
    __shared__ float ps[TJ][TI];     // 2KB, [k][i]
    __shared__ float rw1[TI], rF1[TI], rFa[TI], zs[TI];

    const int b  = blockIdx.y;
    const int i0 = blockIdx.x * TI;
    const int tid = threadIdx.x;
    const int r = tid >> 6;          // row group 0..3
    const int c = tid & 63;          // feat group 0..63

    if (tid < TI) {
        int gi = b * T2 + i0 + tid;
        rw1[tid] = g_w1[gi];
        rF1[tid] = g_F1[gi];
        rFa[tid] = g_Fa[gi];
    }
    u64 acc[8][4];
    #pragma unroll
    for (int i = 0; i < 8; i++)
        #pragma unroll
        for (int j = 0; j < 4; j++) acc[i][j] = 0ull;
    float zreg = 0.f;

    const int pi = tid >> 3;              // p-gen row 0..31
    const int pj = (tid & 7) * 2;         // p-gen j pair
    const size_t adjrow = ((size_t)b * T2 + i0 + pi) * T2;
    __syncthreads();

    for (int j0 = 0; j0 < T2; j0 += TJ) {
        const float* whsrc = g_Wh + ((size_t)b * T2 + j0) * FD;
        #pragma unroll
        for (int s = 0; s < 8; s++) {
            int e = tid + 256 * s;         // float4 index 0..2047
            int kk = e >> 7, fq = e & 127;
            *(float4*)&whs[kk][fq * 4] =
                *(const float4*)&whsrc[(size_t)kk * FD + fq * 4];
        }
        {
            int2 ad = *(const int2*)&adj[adjrow + j0 + pj];
            int gj = b * T2 + j0 + pj;
            float w1i = rw1[pi], f1 = rF1[pi], fa = rFa[pi];
            float w20 = g_w2[gj],     w21 = g_w2[gj + 1];
            float e10 = g_E1[gj],     e11 = g_E1[gj + 1];
            float ea0 = g_Ea[gj],     ea1 = g_Ea[gj + 1];
            float p0 = (w1i + w20 > 0.f) ? f1 * e10 : fa * ea0;
            float p1 = (w1i + w21 > 0.f) ? f1 * e11 : fa * ea1;
            ps[pj][pi]     = (ad.x > 0) ? p0 : 0.f;
            ps[pj + 1][pi] = (ad.y > 0) ? p1 : 0.f;
        }
        __syncthreads();

        if (tid < TI) {                    // softmax denominator
            float z = 0.f;
            #pragma unroll
            for (int k = 0; k < TJ; k++) z += ps[k][tid];
            zreg += z;
        }
        #pragma unroll
        for (int k = 0; k < TJ; k++) {
            float pv[8];
            *(float4*)&pv[0] = *(const float4*)&ps[k][r * 8];
            *(float4*)&pv[4] = *(const float4*)&ps[k][r * 8 + 4];
            ulonglong2 q0 = *(const ulonglong2*)&whs[k][c * 8];
            ulonglong2 q1 = *(const ulonglong2*)&whs[k][c * 8 + 4];
            u64 wv[4] = {q0.x, q0.y, q1.x, q1.y};
            #pragma unroll
            for (int i = 0; i < 8; i++) {
                u64 a2 = pk2(pv[i]);
                #pragma unroll
                for (int j = 0; j < 4; j++) fma2(acc[i][j], a2, wv[j]);
            }
        }
        __syncthreads();
    }

    if (tid < TI) zs[tid] = zreg;
    __syncthreads();

    // epilogue: normalize, elu, write with [out_a.flat, out_v.flat] split layout
    #pragma unroll
    for (int i = 0; i < 8; i++) {
        int il = r * 8 + i;
        int g  = i0 + il;
        float inv = 1.f / zs[il];
        size_t base;
        if (g < TT) base = ((size_t)b * TT + g) * FD;
        else        base = ((size_t)BS * TT + (size_t)b * TT + (g - TT)) * FD;
        float v[8];
        #pragma unroll
        for (int j = 0; j < 4; j++) upk2(v[2 * j], v[2 * j + 1], acc[i][j]);
        #pragma unroll
        for (int j = 0; j < 8; j++) {
            float x = v[j] * inv;
            v[j] = x > 0.f ? x : expm1f(x);
        }
        *(float4*)&out[base + c * 8]     = *(float4*)&v[0];
        *(float4*)&out[base + c * 8 + 4] = *(float4*)&v[4];
    }
}

// ---------------------------------------------------------------------------
extern "C" void kernel_launch(void* const* d_in, const int* in_sizes, int n_in,
                              void* d_out, int out_size) {
    const float* xa  = (const float*)d_in[0];
    const float* xv  = (const float*)d_in[1];
    const int*   adj = (const int*)d_in[2];
    const float* W   = (const float*)d_in[3];
    const float* a   = (const float*)d_in[4];
    float* out = (float*)d_out;

    dim3 gA(FD / 128, T2 / 128, BS);         // 4 x 16 x 16 = 1024 blocks
    k_wh<<<gA, 256>>>(xa, xv, W);
    k_w12<<<BS * T2 / 8, 256>>>(a);          // 4096 blocks, warp/row
    k_prep<<<BS, 256>>>();
    dim3 gC(T2 / TI, BS);                    // 64 x 16 = 1024 blocks
    k_attn<<<gC, 256>>>(adj, out);
}

// round 5
// speedup vs baseline: 2.5545x; 1.5634x over previous
#include <cuda_runtime.h>
#include <cuda_bf16.h>
#include <math.h>
#include <stdint.h>

#define BS 16
#define TT 1024
#define T2 2048
#define FD 512
#define ALPHA 0.1f
#define KC 64
#define NCHUNK (T2 / KC)   // 32
#define MI 128
#define NF 256

typedef unsigned long long u64;
typedef unsigned int u32;

// ---------------- device scratch (no cudaMalloc allowed) --------------------
static __device__ __nv_bfloat16 g_Bhi[(size_t)BS * T2 * FD];  // Wh hi, [b][j][f]
static __device__ __nv_bfloat16 g_Blo[(size_t)BS * T2 * FD];  // Wh lo
static __device__ float g_uvec[2 * FD];    // W@a1, W@a2
static __device__ float g_w1[BS * T2];
static __device__ float g_w2[BS * T2];
static __device__ float g_F1[BS * T2];
static __device__ float g_Fa[BS * T2];
static __device__ float g_E1[BS * T2];
static __device__ float g_Ea[BS * T2];

// ---------------- helpers ----------------------------------------------------
__device__ __forceinline__ u64 pk2(float x) {
    u64 r; asm("mov.b64 %0, {%1, %1};" : "=l"(r) : "f"(x)); return r;
}
__device__ __forceinline__ void fma2(u64& d, u64 a, u64 b) {
    asm("fma.rn.f32x2 %0, %1, %2, %0;" : "+l"(d) : "l"(a), "l"(b));
}
__device__ __forceinline__ void upk2(float& lo, float& hi, u64 v) {
    asm("mov.b64 {%0, %1}, %2;" : "=f"(lo), "=f"(hi) : "l"(v));
}
__device__ __forceinline__ u32 smem_u32(const void* p) {
    u32 a; asm("{ .reg .u64 t; cvta.to.shared.u64 t, %1; cvt.u32.u64 %0, t; }"
               : "=r"(a) : "l"(p));
    return a;
}
__device__ __forceinline__ void ldsm_x4(u32* r, u32 addr) {
    asm volatile("ldmatrix.sync.aligned.m8n8.x4.shared.b16 {%0,%1,%2,%3}, [%4];"
                 : "=r"(r[0]), "=r"(r[1]), "=r"(r[2]), "=r"(r[3]) : "r"(addr));
}
__device__ __forceinline__ void ldsm_x4t(u32* r, u32 addr) {
    asm volatile("ldmatrix.sync.aligned.m8n8.x4.trans.shared.b16 {%0,%1,%2,%3}, [%4];"
                 : "=r"(r[0]), "=r"(r[1]), "=r"(r[2]), "=r"(r[3]) : "r"(addr));
}
__device__ __forceinline__ void mma_bf16(float* d, const u32* a, u32 b0, u32 b1) {
    asm volatile(
        "mma.sync.aligned.m16n8k16.row.col.f32.bf16.bf16.f32 "
        "{%0,%1,%2,%3}, {%4,%5,%6,%7}, {%8,%9}, {%0,%1,%2,%3};"
        : "+f"(d[0]), "+f"(d[1]), "+f"(d[2]), "+f"(d[3])
        : "r"(a[0]), "r"(a[1]), "r"(a[2]), "r"(a[3]), "r"(b0), "r"(b1));
}

// SMEM layout for k_attn_mma — ALL STRIDES/OFFSETS IN BYTES.
#define WHS_RB  528                 // 256 bf16 (512B) + 16B pad per j-row
#define PS_RB   144                 // 64 bf16 (128B) + 16B pad per i-row
#define SM_WHS_HI  0                // 64*528  = 33792 B
#define SM_WHS_LO  33792
#define SM_PS_HI   67584            // 128*144 = 18432 B
#define SM_PS_LO   86016
#define SM_TBL     104448           // 3*2048*4 = 24576 B
#define SM_ZPART   129024           // 1024
#define SM_ZFIN    130048           // 512
#define SM_ATTN_TOTAL 130560

// ---------------------------------------------------------------------------
// k_u: u1 = W @ a1, u2 = W @ a2. warp per k-row.
// ---------------------------------------------------------------------------
__global__ __launch_bounds__(256) void k_u(const float* __restrict__ W,
                                           const float* __restrict__ avec) {
    int k = blockIdx.x * 8 + (threadIdx.x >> 5);
    int lane = threadIdx.x & 31;
    const float* wr = W + (size_t)k * FD;
    float s1 = 0.f, s2 = 0.f;
    #pragma unroll
    for (int q = 0; q < 4; q++) {
        int f4 = lane + 32 * q;
        float4 w = *(const float4*)&wr[f4 * 4];
        float4 a1 = *(const float4*)&avec[f4 * 4];
        float4 a2 = *(const float4*)&avec[FD + f4 * 4];
        s1 += w.x * a1.x + w.y * a1.y + w.z * a1.z + w.w * a1.w;
        s2 += w.x * a2.x + w.y * a2.y + w.z * a2.z + w.w * a2.w;
    }
    #pragma unroll
    for (int o = 16; o > 0; o >>= 1) {
        s1 += __shfl_xor_sync(0xffffffffu, s1, o);
        s2 += __shfl_xor_sync(0xffffffffu, s2, o);
    }
    if (lane == 0) { g_uvec[k] = s1; g_uvec[FD + k] = s2; }
}

// ---------------------------------------------------------------------------
// k_w12: w1[row] = h_row · u1, w2[row] = h_row · u2  (associativity trick)
// ---------------------------------------------------------------------------
__global__ __launch_bounds__(256) void k_w12(const float* __restrict__ xa,
                                             const float* __restrict__ xv) {
    int row  = blockIdx.x * 8 + (threadIdx.x >> 5);
    int lane = threadIdx.x & 31;
    int b = row >> 11, r = row & (T2 - 1);
    const float* h = (r < TT) ? xa + ((size_t)b * TT + r) * FD
                              : xv + ((size_t)b * TT + (r - TT)) * FD;
    float s1 = 0.f, s2 = 0.f;
    #pragma unroll
    for (int q = 0; q < 4; q++) {
        int f4 = lane + 32 * q;
        float4 v  = *(const float4*)&h[f4 * 4];
        float4 a1 = *(const float4*)&g_uvec[f4 * 4];
        float4 a2 = *(const float4*)&g_uvec[FD + f4 * 4];
        s1 += v.x * a1.x + v.y * a1.y + v.z * a1.z + v.w * a1.w;
        s2 += v.x * a2.x + v.y * a2.y + v.z * a2.z + v.w * a2.w;
    }
    #pragma unroll
    for (int o = 16; o > 0; o >>= 1) {
        s1 += __shfl_xor_sync(0xffffffffu, s1, o);
        s2 += __shfl_xor_sync(0xffffffffu, s2, o);
    }
    if (lane == 0) { g_w1[row] = s1; g_w2[row] = s2; }
}

// ---------------------------------------------------------------------------
// k_prep: factorized-softmax tables.
// ---------------------------------------------------------------------------
__global__ __launch_bounds__(256) void k_prep() {
    __shared__ float red[256];
    __shared__ float Msh;
    int b = blockIdx.x, tid = threadIdx.x;
    const float* w2 = g_w2 + b * T2;
    float m = -1e30f;
    for (int i = tid; i < T2; i += 256) m = fmaxf(m, w2[i]);
    red[tid] = m; __syncthreads();
    for (int s = 128; s > 0; s >>= 1) {
        if (tid < s) red[tid] = fmaxf(red[tid], red[tid + s]);
        __syncthreads();
    }
    if (tid == 0) Msh = red[0];
    __syncthreads();
    float M = Msh;
    const float* w1 = g_w1 + b * T2;
    for (int i = tid; i < T2; i += 256) {
        float v1 = w1[i], v2 = w2[i];
        float s  = v1 + M;
        float mi = s > 0.f ? s : ALPHA * s;
        g_F1[b * T2 + i] = expf(v1 - mi);
        g_Fa[b * T2 + i] = expf(ALPHA * v1 - mi);
        g_E1[b * T2 + i] = expf(v2);
        g_Ea[b * T2 + i] = expf(ALPHA * v2);
    }
}

// ---------------------------------------------------------------------------
// k_wh: Wh GEMM (FFMA2) → writes bf16 hi/lo [b][j][f] (untransposed).
// ---------------------------------------------------------------------------
__global__ __launch_bounds__(256, 2) void k_wh(const float* __restrict__ xa,
                                               const float* __restrict__ xv,
                                               const float* __restrict__ W) {
    __shared__ float As[16][132];
    __shared__ float Bs[16][128];
    const int b  = blockIdx.z;
    const int r0 = blockIdx.y * 128;
    const int f0 = blockIdx.x * 128;
    const int tid = threadIdx.x;
    const int ty = tid >> 4, tx = tid & 15;

    const float* __restrict__ h = (r0 < TT)
        ? (xa + ((size_t)b * TT + r0) * FD)
        : (xv + ((size_t)b * TT + (r0 - TT)) * FD);

    u64 acc[8][4];
    #pragma unroll
    for (int i = 0; i < 8; i++)
        #pragma unroll
        for (int j = 0; j < 4; j++) acc[i][j] = 0ull;

    for (int k0 = 0; k0 < FD; k0 += 16) {
        #pragma unroll
        for (int s = 0; s < 8; s++) {
            int e = tid + 256 * s;
            int row = e >> 4, kk = e & 15;
            As[kk][row] = h[(size_t)row * FD + k0 + kk];
        }
        #pragma unroll
        for (int s = 0; s < 8; s++) {
            int e = tid + 256 * s;
            int kk = e >> 7, ff = e & 127;
            Bs[kk][ff] = W[(size_t)(k0 + kk) * FD + f0 + ff];
        }
        __syncthreads();
        #pragma unroll
        for (int k = 0; k < 16; k++) {
            float av[8];
            *(float4*)&av[0] = *(const float4*)&As[k][ty * 8];
            *(float4*)&av[4] = *(const float4*)&As[k][ty * 8 + 4];
            ulonglong2 q0 = *(const ulonglong2*)&Bs[k][tx * 8];
            ulonglong2 q1 = *(const ulonglong2*)&Bs[k][tx * 8 + 4];
            u64 bv[4] = {q0.x, q0.y, q1.x, q1.y};
            #pragma unroll
            for (int i = 0; i < 8; i++) {
                u64 a2 = pk2(av[i]);
                #pragma unroll
                for (int j = 0; j < 4; j++) fma2(acc[i][j], a2, bv[j]);
            }
        }
        __syncthreads();
    }

    // epilogue: split each fp32 to bf16 hi/lo, write [b][j][f]
    #pragma unroll
    for (int i = 0; i < 8; i++) {
        unsigned short hh[8], ll[8];
        #pragma unroll
        for (int jp = 0; jp < 4; jp++) {
            float lo_, hi_;
            upk2(lo_, hi_, acc[i][jp]);
            float xs[2] = {lo_, hi_};
            #pragma unroll
            for (int e = 0; e < 2; e++) {
                __nv_bfloat16 bh = __float2bfloat16(xs[e]);
                float resid = xs[e] - __bfloat162float(bh);
                hh[2 * jp + e] = __bfloat16_as_ushort(bh);
                ll[2 * jp + e] = __bfloat16_as_ushort(__float2bfloat16(resid));
            }
        }
        size_t off = ((size_t)b * T2 + r0 + ty * 8 + i) * FD + f0 + tx * 8;
        uint4 qh, ql;
        qh.x = (u32)hh[0] | ((u32)hh[1] << 16);
        qh.y = (u32)hh[2] | ((u32)hh[3] << 16);
        qh.z = (u32)hh[4] | ((u32)hh[5] << 16);
        qh.w = (u32)hh[6] | ((u32)hh[7] << 16);
        ql.x = (u32)ll[0] | ((u32)ll[1] << 16);
        ql.y = (u32)ll[2] | ((u32)ll[3] << 16);
        ql.z = (u32)ll[4] | ((u32)ll[5] << 16);
        ql.w = (u32)ll[6] | ((u32)ll[7] << 16);
        *(uint4*)&g_Bhi[off] = qh;
        *(uint4*)&g_Blo[off] = ql;
    }
}

// ---------------------------------------------------------------------------
// k_attn_mma: fused masked-softmax attention via mma.sync bf16 (split-precision).
// Block: 256 thr = 8 warps (4 m x 2 n). Tile: 128 i x 256 f, K chunks of 64 j.
// D = P_hi@B_hi + P_hi@B_lo + P_lo@B_hi  (fp32 accumulators)
// ---------------------------------------------------------------------------
__global__ __launch_bounds__(256, 1) void k_attn_mma(const int* __restrict__ adj,
                                                     float* __restrict__ out) {
    extern __shared__ char sm[];
    const u32 smb = smem_u32(sm);
    const int tid = threadIdx.x;
    const int lane = tid & 31, wid = tid >> 5;
    const int wm = wid & 3, wn = wid >> 2;
    const int b  = blockIdx.z;
    const int i0 = blockIdx.x * MI;
    const int f0 = blockIdx.y * NF;

    float* tw2 = (float*)(sm + SM_TBL);
    float* te1 = tw2 + T2;
    float* tea = tw2 + 2 * T2;

    // preload per-batch tables (once)
    #pragma unroll
    for (int s = 0; s < 8; s++) {
        int j = tid + 256 * s;
        int gj = b * T2 + j;
        tw2[j] = g_w2[gj];
        te1[j] = g_E1[gj];
        tea[j] = g_Ea[gj];
    }

    // P-build thread mapping: thread owns (i = tid>>1, 32 j's per chunk)
    const int it = tid >> 1, half = tid & 1;
    const int gi = b * T2 + i0 + it;
    const float w1i = g_w1[gi], f1 = g_F1[gi], fa = g_Fa[gi];
    float zsum = 0.f;
    const size_t adjbase = ((size_t)(b * T2 + i0 + it)) * T2;

    float acc[2][16][4];
    #pragma unroll
    for (int m = 0; m < 2; m++)
        #pragma unroll
        for (int n = 0; n < 16; n++)
            #pragma unroll
            for (int e = 0; e < 4; e++) acc[m][n][e] = 0.f;

    const __nv_bfloat16* bhsrc = g_Bhi + (size_t)b * T2 * FD;
    const __nv_bfloat16* blsrc = g_Blo + (size_t)b * T2 * FD;

    // ldmatrix per-lane base offsets (BYTES)
    const u32 a_lane = (u32)(lane & 15) * PS_RB + (u32)(lane >> 4) * 16;
    const u32 b_lane = (u32)(lane & 15) * WHS_RB + (u32)(lane >> 4) * 16;
    const u32 pa_hi = smb + SM_PS_HI + (u32)(wm * 32) * PS_RB + a_lane;
    const u32 pa_lo = smb + SM_PS_LO + (u32)(wm * 32) * PS_RB + a_lane;
    const u32 pb_hi = smb + SM_WHS_HI + (u32)(wn * 128) * 2 + b_lane;
    const u32 pb_lo = smb + SM_WHS_LO + (u32)(wn * 128) * 2 + b_lane;

    __syncthreads();   // tables visible

    for (int c = 0; c < NCHUNK; c++) {
        const int j0 = c * KC;
        if (c) __syncthreads();   // previous compute done

        // stage Wh chunk [64 j][256 f] hi/lo
        #pragma unroll
        for (int s = 0; s < 8; s++) {
            int u = tid + 256 * s;
            int row = u >> 5, fq = u & 31;
            const size_t g = (size_t)(j0 + row) * FD + f0 + fq * 8;
            *(uint4*)(sm + SM_WHS_HI + row * WHS_RB + fq * 16) =
                *(const uint4*)(bhsrc + g);
            *(uint4*)(sm + SM_WHS_LO + row * WHS_RB + fq * 16) =
                *(const uint4*)(blsrc + g);
        }

        // build P tile [128 i][64 j] hi/lo
        #pragma unroll
        for (int q = 0; q < 4; q++) {
            int j = half * 32 + q * 8;
            int4 a0 = *(const int4*)&adj[adjbase + j0 + j];
            int4 a1 = *(const int4*)&adj[adjbase + j0 + j + 4];
            int msk[8] = {a0.x, a0.y, a0.z, a0.w, a1.x, a1.y, a1.z, a1.w};
            unsigned short hh[8], ll[8];
            #pragma unroll
            for (int e = 0; e < 8; e++) {
                int jj = j0 + j + e;
                float p = (w1i + tw2[jj] > 0.f) ? f1 * te1[jj] : fa * tea[jj];
                p = (msk[e] > 0) ? p : 0.f;
                zsum += p;
                __nv_bfloat16 bh = __float2bfloat16(p);
                hh[e] = __bfloat16_as_ushort(bh);
                ll[e] = __bfloat16_as_ushort(__float2bfloat16(p - __bfloat162float(bh)));
            }
            uint4 qh, ql;
            qh.x = (u32)hh[0] | ((u32)hh[1] << 16);
            qh.y = (u32)hh[2] | ((u32)hh[3] << 16);
            qh.z = (u32)hh[4] | ((u32)hh[5] << 16);
            qh.w = (u32)hh[6] | ((u32)hh[7] << 16);
            ql.x = (u32)ll[0] | ((u32)ll[1] << 16);
            ql.y = (u32)ll[2] | ((u32)ll[3] << 16);
            ql.z = (u32)ll[4] | ((u32)ll[5] << 16);
            ql.w = (u32)ll[6] | ((u32)ll[7] << 16);
            u32 po = (u32)it * PS_RB + (u32)j * 2;
            *(uint4*)(sm + SM_PS_HI + po) = qh;
            *(uint4*)(sm + SM_PS_LO + po) = ql;
        }
        __syncthreads();

        // compute: 4 k16 steps
        #pragma unroll
        for (int kk = 0; kk < 4; kk++) {
            u32 ahi[2][4], alo[2][4];
            ldsm_x4(ahi[0], pa_hi + kk * 32);
            ldsm_x4(ahi[1], pa_hi + kk * 32 + 16 * PS_RB);
            ldsm_x4(alo[0], pa_lo + kk * 32);
            ldsm_x4(alo[1], pa_lo + kk * 32 + 16 * PS_RB);
            #pragma unroll
            for (int nt = 0; nt < 8; nt++) {
                u32 bhv[4], blv[4];
                u32 boff = (u32)kk * 16 * WHS_RB + (u32)nt * 32;
                ldsm_x4t(bhv, pb_hi + boff);
                ldsm_x4t(blv, pb_lo + boff);
                #pragma unroll
                for (int mt = 0; mt < 2; mt++) {
                    mma_bf16(acc[mt][2 * nt],     ahi[mt], bhv[0], bhv[1]);
                    mma_bf16(acc[mt][2 * nt + 1], ahi[mt], bhv[2], bhv[3]);
                    mma_bf16(acc[mt][2 * nt],     ahi[mt], blv[0], blv[1]);
                    mma_bf16(acc[mt][2 * nt + 1], ahi[mt], blv[2], blv[3]);
                    mma_bf16(acc[mt][2 * nt],     alo[mt], bhv[0], bhv[1]);
                    mma_bf16(acc[mt][2 * nt + 1], alo[mt], bhv[2], bhv[3]);
                }
            }
        }
    }

    // Z reduction (zsum lives in P-build mapping: 2 threads per row)
    float* zpart = (float*)(sm + SM_ZPART);
    float* zfin  = (float*)(sm + SM_ZFIN);
    __syncthreads();
    zpart[tid] = zsum;
    __syncthreads();
    if (tid < 128) zfin[tid] = zpart[2 * tid] + zpart[2 * tid + 1];
    __syncthreads();

    // epilogue: normalize, elu, split-write
    #pragma unroll
    for (int mt = 0; mt < 2; mt++) {
        int il = wm * 32 + mt * 16 + (lane >> 2);
        int g1 = i0 + il, g2 = g1 + 8;
        float inv1 = 1.f / zfin[il];
        float inv2 = 1.f / zfin[il + 8];
        size_t base1 = (g1 < TT) ? ((size_t)b * TT + g1) * FD
                                 : ((size_t)BS * TT + (size_t)b * TT + (g1 - TT)) * FD;
        size_t base2 = (g2 < TT) ? ((size_t)b * TT + g2) * FD
                                 : ((size_t)BS * TT + (size_t)b * TT + (g2 - TT)) * FD;
        #pragma unroll
        for (int nt = 0; nt < 16; nt++) {
            int col = f0 + wn * 128 + nt * 8 + (lane & 3) * 2;
            float2 v1, v2;
            float x;
            x = acc[mt][nt][0] * inv1; v1.x = x > 0.f ? x : expm1f(x);
            x = acc[mt][nt][1] * inv1; v1.y = x > 0.f ? x : expm1f(x);
            x = acc[mt][nt][2] * inv2; v2.x = x > 0.f ? x : expm1f(x);
            x = acc[mt][nt][3] * inv2; v2.y = x > 0.f ? x : expm1f(x);
            *(float2*)&out[base1 + col] = v1;
            *(float2*)&out[base2 + col] = v2;
        }
    }
}

// ---------------------------------------------------------------------------
extern "C" void kernel_launch(void* const* d_in, const int* in_sizes, int n_in,
                              void* d_out, int out_size) {
    const float* xa  = (const float*)d_in[0];
    const float* xv  = (const float*)d_in[1];
    const int*   adj = (const int*)d_in[2];
    const float* W   = (const float*)d_in[3];
    const float* a   = (const float*)d_in[4];
    float* out = (float*)d_out;

    cudaFuncSetAttribute(k_attn_mma, cudaFuncAttributeMaxDynamicSharedMemorySize,
                         SM_ATTN_TOTAL);

    k_u<<<FD / 8, 256>>>(W, a);
    k_w12<<<BS * T2 / 8, 256>>>(xa, xv);
    k_prep<<<BS, 256>>>();
    dim3 gA(FD / 128, T2 / 128, BS);
    k_wh<<<gA, 256>>>(xa, xv, W);
    dim3 gC(T2 / MI, FD / NF, BS);           // 16 x 2 x 16 = 512 blocks
    k_attn_mma<<<gC, 256, SM_ATTN_TOTAL>>>(adj, out);
}

// round 6
// speedup vs baseline: 3.3718x; 1.3199x over previous
#include <cuda_runtime.h>
#include <cuda_bf16.h>
#include <math.h>
#include <stdint.h>

#define BS 16
#define TT 1024
#define T2 2048
#define FD 512
#define ALPHA 0.1f
#define KC 64
#define NCHUNK (T2 / KC)   // 32
#define MI 128
#define NF 256

typedef unsigned long long u64;
typedef unsigned int u32;

// ---------------- device scratch (no cudaMalloc allowed) --------------------
static __device__ __nv_bfloat16 g_Bhi[(size_t)BS * T2 * FD];  // Wh hi, [b][j][f]
static __device__ __nv_bfloat16 g_Blo[(size_t)BS * T2 * FD];  // Wh lo
static __device__ float g_uvec[2 * FD];    // W@a1, W@a2
static __device__ float g_w1[BS * T2];
static __device__ float g_w2[BS * T2];
static __device__ float g_F1[BS * T2];
static __device__ float g_Fa[BS * T2];
static __device__ float g_E1[BS * T2];
static __device__ float g_Ea[BS * T2];

// ---------------- helpers ----------------------------------------------------
__device__ __forceinline__ u64 pk2(float x) {
    u64 r; asm("mov.b64 %0, {%1, %1};" : "=l"(r) : "f"(x)); return r;
}
__device__ __forceinline__ u64 mul2(u64 a, u64 b) {
    u64 d; asm("mul.rn.f32x2 %0, %1, %2;" : "=l"(d) : "l"(a), "l"(b)); return d;
}
__device__ __forceinline__ float2 u2f2(u64 v) {
    float2 r; asm("mov.b64 {%0, %1}, %2;" : "=f"(r.x), "=f"(r.y) : "l"(v)); return r;
}
// packed bf16x2 convert: low16 = bf16(lo), high16 = bf16(hi)
__device__ __forceinline__ u32 packbf(float lo, float hi) {
    u32 r; asm("cvt.rn.bf16x2.f32 %0, %1, %2;" : "=r"(r) : "f"(hi), "f"(lo)); return r;
}
__device__ __forceinline__ u32 smem_u32(const void* p) {
    u32 a; asm("{ .reg .u64 t; cvta.to.shared.u64 t, %1; cvt.u32.u64 %0, t; }"
               : "=r"(a) : "l"(p));
    return a;
}
__device__ __forceinline__ void ldsm_x4(u32* r, u32 addr) {
    asm volatile("ldmatrix.sync.aligned.m8n8.x4.shared.b16 {%0,%1,%2,%3}, [%4];"
                 : "=r"(r[0]), "=r"(r[1]), "=r"(r[2]), "=r"(r[3]) : "r"(addr));
}
__device__ __forceinline__ void ldsm_x4t(u32* r, u32 addr) {
    asm volatile("ldmatrix.sync.aligned.m8n8.x4.trans.shared.b16 {%0,%1,%2,%3}, [%4];"
                 : "=r"(r[0]), "=r"(r[1]), "=r"(r[2]), "=r"(r[3]) : "r"(addr));
}
__device__ __forceinline__ void mma_bf16(float* d, const u32* a, u32 b0, u32 b1) {
    asm volatile(
        "mma.sync.aligned.m16n8k16.row.col.f32.bf16.bf16.f32 "
        "{%0,%1,%2,%3}, {%4,%5,%6,%7}, {%8,%9}, {%0,%1,%2,%3};"
        : "+f"(d[0]), "+f"(d[1]), "+f"(d[2]), "+f"(d[3])
        : "r"(a[0]), "r"(a[1]), "r"(a[2]), "r"(a[3]), "r"(b0), "r"(b1));
}
__device__ __forceinline__ void cpa16(u32 dst, const void* src) {
    asm volatile("{ .reg .u64 g; cvta.to.global.u64 g, %1; "
                 "cp.async.cg.shared.global [%0], [g], 16; }"
                 :: "r"(dst), "l"(src) : "memory");
}

// ---------------------------------------------------------------------------
// k_u: u1 = W @ a1, u2 = W @ a2. warp per k-row.
// ---------------------------------------------------------------------------
__global__ __launch_bounds__(256) void k_u(const float* __restrict__ W,
                                           const float* __restrict__ avec) {
    int k = blockIdx.x * 8 + (threadIdx.x >> 5);
    int lane = threadIdx.x & 31;
    const float* wr = W + (size_t)k * FD;
    float s1 = 0.f, s2 = 0.f;
    #pragma unroll
    for (int q = 0; q < 4; q++) {
        int f4 = lane + 32 * q;
        float4 w = *(const float4*)&wr[f4 * 4];
        float4 a1 = *(const float4*)&avec[f4 * 4];
        float4 a2 = *(const float4*)&avec[FD + f4 * 4];
        s1 += w.x * a1.x + w.y * a1.y + w.z * a1.z + w.w * a1.w;
        s2 += w.x * a2.x + w.y * a2.y + w.z * a2.z + w.w * a2.w;
    }
    #pragma unroll
    for (int o = 16; o > 0; o >>= 1) {
        s1 += __shfl_xor_sync(0xffffffffu, s1, o);
        s2 += __shfl_xor_sync(0xffffffffu, s2, o);
    }
    if (lane == 0) { g_uvec[k] = s1; g_uvec[FD + k] = s2; }
}

// ---------------------------------------------------------------------------
// k_w12: w1[row] = h_row · u1, w2[row] = h_row · u2  (exact fp32, associativity)
// ---------------------------------------------------------------------------
__global__ __launch_bounds__(256) void k_w12(const float* __restrict__ xa,
                                             const float* __restrict__ xv) {
    int row  = blockIdx.x * 8 + (threadIdx.x >> 5);
    int lane = threadIdx.x & 31;
    int b = row >> 11, r = row & (T2 - 1);
    const float* h = (r < TT) ? xa + ((size_t)b * TT + r) * FD
                              : xv + ((size_t)b * TT + (r - TT)) * FD;
    float s1 = 0.f, s2 = 0.f;
    #pragma unroll
    for (int q = 0; q < 4; q++) {
        int f4 = lane + 32 * q;
        float4 v  = *(const float4*)&h[f4 * 4];
        float4 a1 = *(const float4*)&g_uvec[f4 * 4];
        float4 a2 = *(const float4*)&g_uvec[FD + f4 * 4];
        s1 += v.x * a1.x + v.y * a1.y + v.z * a1.z + v.w * a1.w;
        s2 += v.x * a2.x + v.y * a2.y + v.z * a2.z + v.w * a2.w;
    }
    #pragma unroll
    for (int o = 16; o > 0; o >>= 1) {
        s1 += __shfl_xor_sync(0xffffffffu, s1, o);
        s2 += __shfl_xor_sync(0xffffffffu, s2, o);
    }
    if (lane == 0) { g_w1[row] = s1; g_w2[row] = s2; }
}

// ---------------------------------------------------------------------------
// k_prep: factorized-softmax tables.
// ---------------------------------------------------------------------------
__global__ __launch_bounds__(256) void k_prep() {
    __shared__ float red[256];
    __shared__ float Msh;
    int b = blockIdx.x, tid = threadIdx.x;
    const float* w2 = g_w2 + b * T2;
    float m = -1e30f;
    for (int i = tid; i < T2; i += 256) m = fmaxf(m, w2[i]);
    red[tid] = m; __syncthreads();
    for (int s = 128; s > 0; s >>= 1) {
        if (tid < s) red[tid] = fmaxf(red[tid], red[tid + s]);
        __syncthreads();
    }
    if (tid == 0) Msh = red[0];
    __syncthreads();
    float M = Msh;
    const float* w1 = g_w1 + b * T2;
    for (int i = tid; i < T2; i += 256) {
        float v1 = w1[i], v2 = w2[i];
        float s  = v1 + M;
        float mi = s > 0.f ? s : ALPHA * s;
        g_F1[b * T2 + i] = expf(v1 - mi);
        g_Fa[b * T2 + i] = expf(ALPHA * v1 - mi);
        g_E1[b * T2 + i] = expf(v2);
        g_Ea[b * T2 + i] = expf(ALPHA * v2);
    }
}

// ---------------------------------------------------------------------------
// k_wh_mma: Wh = h @ W via mma.sync bf16 split-precision (3 passes).
// Block 256 thr (4m x 2n warps), tile 128 rows x 128 f, K chunks of 64.
// Writes bf16 hi/lo Wh to g_Bhi/g_Blo [b][j][f].
// ---------------------------------------------------------------------------
#define WA_RB 144                   // 64 k bf16 (128B) + 16B pad
#define WW_RB 272                   // 128 f bf16 (256B) + 16B pad
#define SW_A_HI 0                   // 128*144 = 18432
#define SW_A_LO 18432
#define SW_W_HI 36864               // 64*272 = 17408
#define SW_W_LO 54272
#define SW_TOTAL 71680

__global__ __launch_bounds__(256, 2) void k_wh_mma(const float* __restrict__ xa,
                                                   const float* __restrict__ xv,
                                                   const float* __restrict__ W) {
    extern __shared__ char sm[];
    const u32 smb = smem_u32(sm);
    const int tid = threadIdx.x, lane = tid & 31, wid = tid >> 5;
    const int wm = wid & 3, wn = wid >> 2;
    const int b  = blockIdx.z;
    const int r0 = blockIdx.y * 128;
    const int f0 = blockIdx.x * 128;
    const float* __restrict__ h = (r0 < TT)
        ? (xa + ((size_t)b * TT + r0) * FD)
        : (xv + ((size_t)b * TT + (r0 - TT)) * FD);

    float acc[2][8][4];
    #pragma unroll
    for (int m = 0; m < 2; m++)
        #pragma unroll
        for (int n = 0; n < 8; n++)
            #pragma unroll
            for (int e = 0; e < 4; e++) acc[m][n][e] = 0.f;

    const u32 a_lane = (u32)(lane & 15) * WA_RB + (u32)(lane >> 4) * 16;
    const u32 b_lane = (u32)(lane & 15) * WW_RB + (u32)(lane >> 4) * 16;
    const u32 pa_hi = smb + SW_A_HI + (u32)(wm * 32) * WA_RB + a_lane;
    const u32 pa_lo = smb + SW_A_LO + (u32)(wm * 32) * WA_RB + a_lane;
    const u32 pb_hi = smb + SW_W_HI + (u32)(wn * 64) * 2 + b_lane;
    const u32 pb_lo = smb + SW_W_LO + (u32)(wn * 64) * 2 + b_lane;

    for (int k0 = 0; k0 < FD; k0 += KC) {
        if (k0) __syncthreads();
        // stage A (h chunk [128 m][64 k]) with fp32->bf16 hi/lo split
        #pragma unroll
        for (int s = 0; s < 8; s++) {
            int u = tid + 256 * s;
            int row = u >> 4, kq = u & 15;
            float4 v = *(const float4*)(h + (size_t)row * FD + k0 + kq * 4);
            u32 h01 = packbf(v.x, v.y);
            u32 h23 = packbf(v.z, v.w);
            float rx = v.x - __uint_as_float(h01 << 16);
            float ry = v.y - __uint_as_float(h01 & 0xffff0000u);
            float rz = v.z - __uint_as_float(h23 << 16);
            float rw = v.w - __uint_as_float(h23 & 0xffff0000u);
            uint2 qh = make_uint2(h01, h23);
            uint2 ql = make_uint2(packbf(rx, ry), packbf(rz, rw));
            *(uint2*)(sm + SW_A_HI + row * WA_RB + kq * 8) = qh;
            *(uint2*)(sm + SW_A_LO + row * WA_RB + kq * 8) = ql;
        }
        // stage W chunk [64 k][128 f]
        #pragma unroll
        for (int s = 0; s < 8; s++) {
            int u = tid + 256 * s;
            int row = u >> 5, fq = u & 31;
            float4 v = *(const float4*)(W + (size_t)(k0 + row) * FD + f0 + fq * 4);
            u32 h01 = packbf(v.x, v.y);
            u32 h23 = packbf(v.z, v.w);
            float rx = v.x - __uint_as_float(h01 << 16);
            float ry = v.y - __uint_as_float(h01 & 0xffff0000u);
            float rz = v.z - __uint_as_float(h23 << 16);
            float rw = v.w - __uint_as_float(h23 & 0xffff0000u);
            uint2 qh = make_uint2(h01, h23);
            uint2 ql = make_uint2(packbf(rx, ry), packbf(rz, rw));
            *(uint2*)(sm + SW_W_HI + row * WW_RB + fq * 8) = qh;
            *(uint2*)(sm + SW_W_LO + row * WW_RB + fq * 8) = ql;
        }
        __syncthreads();
        #pragma unroll
        for (int kk = 0; kk < 4; kk++) {
            u32 ahi[2][4], alo[2][4];
            ldsm_x4(ahi[0], pa_hi + kk * 32);
            ldsm_x4(ahi[1], pa_hi + kk * 32 + 16 * WA_RB);
            ldsm_x4(alo[0], pa_lo + kk * 32);
            ldsm_x4(alo[1], pa_lo + kk * 32 + 16 * WA_RB);
            #pragma unroll
            for (int nt = 0; nt < 4; nt++) {
                u32 bhv[4], blv[4];
                u32 boff = (u32)kk * 16 * WW_RB + (u32)nt * 32;
                ldsm_x4t(bhv, pb_hi + boff);
                ldsm_x4t(blv, pb_lo + boff);
                #pragma unroll
                for (int mt = 0; mt < 2; mt++) {
                    mma_bf16(acc[mt][2 * nt],     ahi[mt], bhv[0], bhv[1]);
                    mma_bf16(acc[mt][2 * nt + 1], ahi[mt], bhv[2], bhv[3]);
                    mma_bf16(acc[mt][2 * nt],     ahi[mt], blv[0], blv[1]);
                    mma_bf16(acc[mt][2 * nt + 1], ahi[mt], blv[2], blv[3]);
                    mma_bf16(acc[mt][2 * nt],     alo[mt], bhv[0], bhv[1]);
                    mma_bf16(acc[mt][2 * nt + 1], alo[mt], bhv[2], bhv[3]);
                }
            }
        }
    }

    // epilogue: split fp32 result to bf16 hi/lo, write [b][j][f]
    #pragma unroll
    for (int mt = 0; mt < 2; mt++) {
        int row1 = r0 + wm * 32 + mt * 16 + (lane >> 2);
        #pragma unroll
        for (int nt2 = 0; nt2 < 8; nt2++) {
            int col = f0 + wn * 64 + nt2 * 8 + (lane & 3) * 2;
            float d0 = acc[mt][nt2][0], d1 = acc[mt][nt2][1];
            float d2 = acc[mt][nt2][2], d3 = acc[mt][nt2][3];
            u32 h01 = packbf(d0, d1);
            u32 l01 = packbf(d0 - __uint_as_float(h01 << 16),
                             d1 - __uint_as_float(h01 & 0xffff0000u));
            u32 h23 = packbf(d2, d3);
            u32 l23 = packbf(d2 - __uint_as_float(h23 << 16),
                             d3 - __uint_as_float(h23 & 0xffff0000u));
            size_t o1 = ((size_t)b * T2 + row1) * FD + col;
            size_t o2 = o1 + (size_t)8 * FD;
            *(u32*)&g_Bhi[o1] = h01;  *(u32*)&g_Blo[o1] = l01;
            *(u32*)&g_Bhi[o2] = h23;  *(u32*)&g_Blo[o2] = l23;
        }
    }
}

// ---------------------------------------------------------------------------
// k_attn_mma: fused masked-softmax attention, split-precision bf16 mma.sync,
// cp.async double-buffered Wh staging, packed P-build.
// ---------------------------------------------------------------------------
#define WHS_RB  528                 // 256 bf16 (512B) + 16B pad per j-row
#define PS_RB   144                 // 64 bf16 (128B) + 16B pad per i-row
#define WHS_HALF 33792              // hi->lo offset inside one buffer
#define WHS_BUF  67584              // per-buffer size (hi+lo)
#define SM_PS_HI 135168
#define SM_PS_LO 153600
#define SM_TBL   172032             // 3*2048*4 = 24576
#define SM_ZPART 196608
#define SM_ZFIN  197632
#define SM_ATTN_TOTAL 198144

__device__ __forceinline__ void stage_whs(u32 smb, int bsel,
                                          const __nv_bfloat16* bh,
                                          const __nv_bfloat16* bl,
                                          int j0, int f0, int tid) {
    u32 base = smb + (u32)bsel * WHS_BUF;
    #pragma unroll
    for (int s = 0; s < 8; s++) {
        int u = tid + 256 * s;
        int row = u >> 5, fo = u & 31;
        cpa16(base + row * WHS_RB + fo * 16,
              bh + (size_t)(j0 + row) * FD + f0 + fo * 8);
    }
    #pragma unroll
    for (int s = 0; s < 8; s++) {
        int u = tid + 256 * s;
        int row = u >> 5, fo = u & 31;
        cpa16(base + WHS_HALF + row * WHS_RB + fo * 16,
              bl + (size_t)(j0 + row) * FD + f0 + fo * 8);
    }
    asm volatile("cp.async.commit_group;" ::: "memory");
}

__global__ __launch_bounds__(256, 1) void k_attn_mma(const int* __restrict__ adj,
                                                     float* __restrict__ out) {
    extern __shared__ char sm[];
    const u32 smb = smem_u32(sm);
    const int tid = threadIdx.x;
    const int lane = tid & 31, wid = tid >> 5;
    const int wm = wid & 3, wn = wid >> 2;
    const int b  = blockIdx.z;
    const int i0 = blockIdx.x * MI;
    const int f0 = blockIdx.y * NF;

    const __nv_bfloat16* bhsrc = g_Bhi + (size_t)b * T2 * FD;
    const __nv_bfloat16* blsrc = g_Blo + (size_t)b * T2 * FD;

    // kick off chunk-0 staging immediately
    stage_whs(smb, 0, bhsrc, blsrc, 0, f0, tid);

    float* tw2 = (float*)(sm + SM_TBL);
    float* te1 = tw2 + T2;
    float* tea = tw2 + 2 * T2;
    #pragma unroll
    for (int s = 0; s < 8; s++) {
        int j = tid + 256 * s;
        int gj = b * T2 + j;
        tw2[j] = g_w2[gj];
        te1[j] = g_E1[gj];
        tea[j] = g_Ea[gj];
    }

    // P-build mapping: thread owns (i = tid>>1, 32 j's per chunk)
    const int it = tid >> 1, half = tid & 1;
    const int gi = b * T2 + i0 + it;
    const float w1i = g_w1[gi];
    const u64 F1pk = pk2(g_F1[gi]);
    const u64 Fapk = pk2(g_Fa[gi]);
    float zsum = 0.f;
    const size_t adjbase = ((size_t)(b * T2 + i0 + it)) * T2;

    float acc[2][16][4];
    #pragma unroll
    for (int m = 0; m < 2; m++)
        #pragma unroll
        for (int n = 0; n < 16; n++)
            #pragma unroll
            for (int e = 0; e < 4; e++) acc[m][n][e] = 0.f;

    const u32 a_lane = (u32)(lane & 15) * PS_RB + (u32)(lane >> 4) * 16;
    const u32 b_lane = (u32)(lane & 15) * WHS_RB + (u32)(lane >> 4) * 16;
    const u32 pa_hi = smb + SM_PS_HI + (u32)(wm * 32) * PS_RB + a_lane;
    const u32 pa_lo = smb + SM_PS_LO + (u32)(wm * 32) * PS_RB + a_lane;

    __syncthreads();   // tables visible

    for (int c = 0; c < NCHUNK; c++) {
        const int j0 = c * KC;
        if (c) __syncthreads();          // prev compute done (ps + alt buffer free)
        if (c + 1 < NCHUNK)
            stage_whs(smb, (c + 1) & 1, bhsrc, blsrc, j0 + KC, f0, tid);

        // build P tile [128 i][64 j] hi/lo (packed math)
        #pragma unroll
        for (int q = 0; q < 4; q++) {
            int j = half * 32 + q * 8;
            int4 a0 = *(const int4*)&adj[adjbase + j0 + j];
            int4 a1 = *(const int4*)&adj[adjbase + j0 + j + 4];
            int msk[8] = {a0.x, a0.y, a0.z, a0.w, a1.x, a1.y, a1.z, a1.w};
            u32 hw[4], lw[4];
            #pragma unroll
            for (int e2 = 0; e2 < 4; e2++) {
                int jj = j0 + j + e2 * 2;
                float2 w2p = *(const float2*)&tw2[jj];
                u64 e1u = *(const u64*)&te1[jj];
                u64 eau = *(const u64*)&tea[jj];
                float2 v1 = u2f2(mul2(F1pk, e1u));
                float2 va = u2f2(mul2(Fapk, eau));
                float p0 = (w1i + w2p.x > 0.f) ? v1.x : va.x;
                float p1 = (w1i + w2p.y > 0.f) ? v1.y : va.y;
                p0 = (msk[e2 * 2] > 0) ? p0 : 0.f;
                p1 = (msk[e2 * 2 + 1] > 0) ? p1 : 0.f;
                zsum += p0 + p1;
                u32 hp = packbf(p0, p1);
                float r0 = p0 - __uint_as_float(hp << 16);
                float r1 = p1 - __uint_as_float(hp & 0xffff0000u);
                hw[e2] = hp;
                lw[e2] = packbf(r0, r1);
            }
            u32 po = (u32)it * PS_RB + (u32)j * 2;
            *(uint4*)(sm + SM_PS_HI + po) = make_uint4(hw[0], hw[1], hw[2], hw[3]);
            *(uint4*)(sm + SM_PS_LO + po) = make_uint4(lw[0], lw[1], lw[2], lw[3]);
        }

        if (c + 1 < NCHUNK)
            asm volatile("cp.async.wait_group 1;" ::: "memory");
        else
            asm volatile("cp.async.wait_group 0;" ::: "memory");
        __syncthreads();

        // compute on buffer c&1
        const u32 wb_hi = smb + (u32)(c & 1) * WHS_BUF + (u32)(wn * 128) * 2 + b_lane;
        const u32 wb_lo = wb_hi + WHS_HALF;
        #pragma unroll
        for (int kk = 0; kk < 4; kk++) {
            u32 ahi[2][4], alo[2][4];
            ldsm_x4(ahi[0], pa_hi + kk * 32);
            ldsm_x4(ahi[1], pa_hi + kk * 32 + 16 * PS_RB);
            ldsm_x4(alo[0], pa_lo + kk * 32);
            ldsm_x4(alo[1], pa_lo + kk * 32 + 16 * PS_RB);
            #pragma unroll
            for (int nt = 0; nt < 8; nt++) {
                u32 bhv[4], blv[4];
                u32 boff = (u32)kk * 16 * WHS_RB + (u32)nt * 32;
                ldsm_x4t(bhv, wb_hi + boff);
                ldsm_x4t(blv, wb_lo + boff);
                #pragma unroll
                for (int mt = 0; mt < 2; mt++) {
                    mma_bf16(acc[mt][2 * nt],     ahi[mt], bhv[0], bhv[1]);
                    mma_bf16(acc[mt][2 * nt + 1], ahi[mt], bhv[2], bhv[3]);
                    mma_bf16(acc[mt][2 * nt],     ahi[mt], blv[0], blv[1]);
                    mma_bf16(acc[mt][2 * nt + 1], ahi[mt], blv[2], blv[3]);
                    mma_bf16(acc[mt][2 * nt],     alo[mt], bhv[0], bhv[1]);
                    mma_bf16(acc[mt][2 * nt + 1], alo[mt], bhv[2], bhv[3]);
                }
            }
        }
    }

    // Z reduction
    float* zpart = (float*)(sm + SM_ZPART);
    float* zfin  = (float*)(sm + SM_ZFIN);
    __syncthreads();
    zpart[tid] = zsum;
    __syncthreads();
    if (tid < 128) zfin[tid] = zpart[2 * tid] + zpart[2 * tid + 1];
    __syncthreads();

    // epilogue: normalize, elu, split-write
    #pragma unroll
    for (int mt = 0; mt < 2; mt++) {
        int il = wm * 32 + mt * 16 + (lane >> 2);
        int g1 = i0 + il, g2 = g1 + 8;
        float inv1 = 1.f / zfin[il];
        float inv2 = 1.f / zfin[il + 8];
        size_t base1 = (g1 < TT) ? ((size_t)b * TT + g1) * FD
                                 : ((size_t)BS * TT + (size_t)b * TT + (g1 - TT)) * FD;
        size_t base2 = (g2 < TT) ? ((size_t)b * TT + g2) * FD
                                 : ((size_t)BS * TT + (size_t)b * TT + (g2 - TT)) * FD;
        #pragma unroll
        for (int nt = 0; nt < 16; nt++) {
            int col = f0 + wn * 128 + nt * 8 + (lane & 3) * 2;
            float2 v1, v2;
            float x;
            x = acc[mt][nt][0] * inv1; v1.x = x > 0.f ? x : expm1f(x);
            x = acc[mt][nt][1] * inv1; v1.y = x > 0.f ? x : expm1f(x);
            x = acc[mt][nt][2] * inv2; v2.x = x > 0.f ? x : expm1f(x);
            x = acc[mt][nt][3] * inv2; v2.y = x > 0.f ? x : expm1f(x);
            *(float2*)&out[base1 + col] = v1;
            *(float2*)&out[base2 + col] = v2;
        }
    }
}

// ---------------------------------------------------------------------------
extern "C" void kernel_launch(void* const* d_in, const int* in_sizes, int n_in,
                              void* d_out, int out_size) {
    const float* xa  = (const float*)d_in[0];
    const float* xv  = (const float*)d_in[1];
    const int*   adj = (const int*)d_in[2];
    const float* W   = (const float*)d_in[3];
    const float* a   = (const float*)d_in[4];
    float* out = (float*)d_out;

    cudaFuncSetAttribute(k_wh_mma, cudaFuncAttributeMaxDynamicSharedMemorySize,
                         SW_TOTAL);
    cudaFuncSetAttribute(k_attn_mma, cudaFuncAttributeMaxDynamicSharedMemorySize,
                         SM_ATTN_TOTAL);

    k_u<<<FD / 8, 256>>>(W, a);
    k_w12<<<BS * T2 / 8, 256>>>(xa, xv);
    k_prep<<<BS, 256>>>();
    dim3 gA(FD / 128, T2 / 128, BS);         // 4 x 16 x 16 = 1024 blocks
    k_wh_mma<<<gA, 256, SW_TOTAL>>>(xa, xv, W);
    dim3 gC(T2 / MI, FD / NF, BS);           // 16 x 2 x 16 = 512 blocks
    k_attn_mma<<<gC, 256, SM_ATTN_TOTAL>>>(adj, out);
}

// round 7
// speedup vs baseline: 3.6573x; 1.0847x over previous
#include <cuda_runtime.h>
#include <cuda_bf16.h>
#include <math.h>
#include <stdint.h>

#define BS 16
#define TT 1024
#define T2 2048
#define FD 512
#define ALPHA 0.1f
#define KC 64
#define NCHUNK (T2 / KC)   // 32
#define MI 128
#define NF 256

typedef unsigned long long u64;
typedef unsigned int u32;

// ---------------- device scratch (no cudaMalloc allowed) --------------------
static __device__ __nv_bfloat16 g_Bhi[(size_t)BS * T2 * FD];  // Wh hi, [b][j][f]
static __device__ __nv_bfloat16 g_Blo[(size_t)BS * T2 * FD];  // Wh lo
static __device__ float g_uvec[2 * FD];    // W@a1, W@a2
static __device__ float g_w1[BS * T2];
static __device__ float g_w2[BS * T2];
static __device__ float g_F1[BS * T2];
static __device__ float g_Fa[BS * T2];
static __device__ float g_E1[BS * T2];
static __device__ float g_Ea[BS * T2];

// ---------------- helpers ----------------------------------------------------
__device__ __forceinline__ u64 pk2(float x) {
    u64 r; asm("mov.b64 %0, {%1, %1};" : "=l"(r) : "f"(x)); return r;
}
__device__ __forceinline__ u64 mul2(u64 a, u64 b) {
    u64 d; asm("mul.rn.f32x2 %0, %1, %2;" : "=l"(d) : "l"(a), "l"(b)); return d;
}
__device__ __forceinline__ float2 u2f2(u64 v) {
    float2 r; asm("mov.b64 {%0, %1}, %2;" : "=f"(r.x), "=f"(r.y) : "l"(v)); return r;
}
// packed bf16x2 convert: low16 = bf16(lo), high16 = bf16(hi)
__device__ __forceinline__ u32 packbf(float lo, float hi) {
    u32 r; asm("cvt.rn.bf16x2.f32 %0, %1, %2;" : "=r"(r) : "f"(hi), "f"(lo)); return r;
}
__device__ __forceinline__ u32 smem_u32(const void* p) {
    u32 a; asm("{ .reg .u64 t; cvta.to.shared.u64 t, %1; cvt.u32.u64 %0, t; }"
               : "=r"(a) : "l"(p));
    return a;
}
__device__ __forceinline__ void ldsm_x4(u32* r, u32 addr) {
    asm volatile("ldmatrix.sync.aligned.m8n8.x4.shared.b16 {%0,%1,%2,%3}, [%4];"
                 : "=r"(r[0]), "=r"(r[1]), "=r"(r[2]), "=r"(r[3]) : "r"(addr));
}
__device__ __forceinline__ void ldsm_x4t(u32* r, u32 addr) {
    asm volatile("ldmatrix.sync.aligned.m8n8.x4.trans.shared.b16 {%0,%1,%2,%3}, [%4];"
                 : "=r"(r[0]), "=r"(r[1]), "=r"(r[2]), "=r"(r[3]) : "r"(addr));
}
__device__ __forceinline__ void mma_bf16(float* d, const u32* a, u32 b0, u32 b1) {
    asm volatile(
        "mma.sync.aligned.m16n8k16.row.col.f32.bf16.bf16.f32 "
        "{%0,%1,%2,%3}, {%4,%5,%6,%7}, {%8,%9}, {%0,%1,%2,%3};"
        : "+f"(d[0]), "+f"(d[1]), "+f"(d[2]), "+f"(d[3])
        : "r"(a[0]), "r"(a[1]), "r"(a[2]), "r"(a[3]), "r"(b0), "r"(b1));
}
__device__ __forceinline__ void cpa16(u32 dst, const void* src) {
    asm volatile("{ .reg .u64 g; cvta.to.global.u64 g, %1; "
                 "cp.async.cg.shared.global [%0], [g], 16; }"
                 :: "r"(dst), "l"(src) : "memory");
}

// ---------------------------------------------------------------------------
// k_u: u1 = W @ a1, u2 = W @ a2. warp per k-row.
// ---------------------------------------------------------------------------
__global__ __launch_bounds__(256) void k_u(const float* __restrict__ W,
                                           const float* __restrict__ avec) {
    int k = blockIdx.x * 8 + (threadIdx.x >> 5);
    int lane = threadIdx.x & 31;
    const float* wr = W + (size_t)k * FD;
    float s1 = 0.f, s2 = 0.f;
    #pragma unroll
    for (int q = 0; q < 4; q++) {
        int f4 = lane + 32 * q;
        float4 w = *(const float4*)&wr[f4 * 4];
        float4 a1 = *(const float4*)&avec[f4 * 4];
        float4 a2 = *(const float4*)&avec[FD + f4 * 4];
        s1 += w.x * a1.x + w.y * a1.y + w.z * a1.z + w.w * a1.w;
        s2 += w.x * a2.x + w.y * a2.y + w.z * a2.z + w.w * a2.w;
    }
    #pragma unroll
    for (int o = 16; o > 0; o >>= 1) {
        s1 += __shfl_xor_sync(0xffffffffu, s1, o);
        s2 += __shfl_xor_sync(0xffffffffu, s2, o);
    }
    if (lane == 0) { g_uvec[k] = s1; g_uvec[FD + k] = s2; }
}

// ---------------------------------------------------------------------------
// k_w12: w1[row] = h_row · u1, w2[row] = h_row · u2  (exact fp32, associativity)
// ---------------------------------------------------------------------------
__global__ __launch_bounds__(256) void k_w12(const float* __restrict__ xa,
                                             const float* __restrict__ xv) {
    int row  = blockIdx.x * 8 + (threadIdx.x >> 5);
    int lane = threadIdx.x & 31;
    int b = row >> 11, r = row & (T2 - 1);
    const float* h = (r < TT) ? xa + ((size_t)b * TT + r) * FD
                              : xv + ((size_t)b * TT + (r - TT)) * FD;
    float s1 = 0.f, s2 = 0.f;
    #pragma unroll
    for (int q = 0; q < 4; q++) {
        int f4 = lane + 32 * q;
        float4 v  = *(const float4*)&h[f4 * 4];
        float4 a1 = *(const float4*)&g_uvec[f4 * 4];
        float4 a2 = *(const float4*)&g_uvec[FD + f4 * 4];
        s1 += v.x * a1.x + v.y * a1.y + v.z * a1.z + v.w * a1.w;
        s2 += v.x * a2.x + v.y * a2.y + v.z * a2.z + v.w * a2.w;
    }
    #pragma unroll
    for (int o = 16; o > 0; o >>= 1) {
        s1 += __shfl_xor_sync(0xffffffffu, s1, o);
        s2 += __shfl_xor_sync(0xffffffffu, s2, o);
    }
    if (lane == 0) { g_w1[row] = s1; g_w2[row] = s2; }
}

// ---------------------------------------------------------------------------
// k_prep: factorized-softmax tables.
// ---------------------------------------------------------------------------
__global__ __launch_bounds__(256) void k_prep() {
    __shared__ float red[256];
    __shared__ float Msh;
    int b = blockIdx.x, tid = threadIdx.x;
    const float* w2 = g_w2 + b * T2;
    float m = -1e30f;
    for (int i = tid; i < T2; i += 256) m = fmaxf(m, w2[i]);
    red[tid] = m; __syncthreads();
    for (int s = 128; s > 0; s >>= 1) {
        if (tid < s) red[tid] = fmaxf(red[tid], red[tid + s]);
        __syncthreads();
    }
    if (tid == 0) Msh = red[0];
    __syncthreads();
    float M = Msh;
    const float* w1 = g_w1 + b * T2;
    for (int i = tid; i < T2; i += 256) {
        float v1 = w1[i], v2 = w2[i];
        float s  = v1 + M;
        float mi = s > 0.f ? s : ALPHA * s;
        g_F1[b * T2 + i] = expf(v1 - mi);
        g_Fa[b * T2 + i] = expf(ALPHA * v1 - mi);
        g_E1[b * T2 + i] = expf(v2);
        g_Ea[b * T2 + i] = expf(ALPHA * v2);
    }
}

// ---------------------------------------------------------------------------
// k_wh_mma: Wh = h @ W via mma.sync bf16 split-precision (3 passes).
// Block 256 thr (4m x 2n warps), tile 128 rows x 128 f, K chunks of 64.
// ---------------------------------------------------------------------------
#define WA_RB 144                   // 64 k bf16 (128B) + 16B pad
#define WW_RB 272                   // 128 f bf16 (256B) + 16B pad
#define SW_A_HI 0                   // 128*144 = 18432
#define SW_A_LO 18432
#define SW_W_HI 36864               // 64*272 = 17408
#define SW_W_LO 54272
#define SW_TOTAL 71680

__global__ __launch_bounds__(256, 2) void k_wh_mma(const float* __restrict__ xa,
                                                   const float* __restrict__ xv,
                                                   const float* __restrict__ W) {
    extern __shared__ char sm[];
    const u32 smb = smem_u32(sm);
    const int tid = threadIdx.x, lane = tid & 31, wid = tid >> 5;
    const int wm = wid & 3, wn = wid >> 2;
    const int b  = blockIdx.z;
    const int r0 = blockIdx.y * 128;
    const int f0 = blockIdx.x * 128;
    const float* __restrict__ h = (r0 < TT)
        ? (xa + ((size_t)b * TT + r0) * FD)
        : (xv + ((size_t)b * TT + (r0 - TT)) * FD);

    float acc[2][8][4];
    #pragma unroll
    for (int m = 0; m < 2; m++)
        #pragma unroll
        for (int n = 0; n < 8; n++)
            #pragma unroll
            for (int e = 0; e < 4; e++) acc[m][n][e] = 0.f;

    const u32 a_lane = (u32)(lane & 15) * WA_RB + (u32)(lane >> 4) * 16;
    const u32 b_lane = (u32)(lane & 15) * WW_RB + (u32)(lane >> 4) * 16;
    const u32 pa_hi = smb + SW_A_HI + (u32)(wm * 32) * WA_RB + a_lane;
    const u32 pa_lo = smb + SW_A_LO + (u32)(wm * 32) * WA_RB + a_lane;
    const u32 pb_hi = smb + SW_W_HI + (u32)(wn * 64) * 2 + b_lane;
    const u32 pb_lo = smb + SW_W_LO + (u32)(wn * 64) * 2 + b_lane;

    for (int k0 = 0; k0 < FD; k0 += KC) {
        if (k0) __syncthreads();
        #pragma unroll
        for (int s = 0; s < 8; s++) {
            int u = tid + 256 * s;
            int row = u >> 4, kq = u & 15;
            float4 v = *(const float4*)(h + (size_t)row * FD + k0 + kq * 4);
            u32 h01 = packbf(v.x, v.y);
            u32 h23 = packbf(v.z, v.w);
            float rx = v.x - __uint_as_float(h01 << 16);
            float ry = v.y - __uint_as_float(h01 & 0xffff0000u);
            float rz = v.z - __uint_as_float(h23 << 16);
            float rw = v.w - __uint_as_float(h23 & 0xffff0000u);
            uint2 qh = make_uint2(h01, h23);
            uint2 ql = make_uint2(packbf(rx, ry), packbf(rz, rw));
            *(uint2*)(sm + SW_A_HI + row * WA_RB + kq * 8) = qh;
            *(uint2*)(sm + SW_A_LO + row * WA_RB + kq * 8) = ql;
        }
        #pragma unroll
        for (int s = 0; s < 8; s++) {
            int u = tid + 256 * s;
            int row = u >> 5, fq = u & 31;
            float4 v = *(const float4*)(W + (size_t)(k0 + row) * FD + f0 + fq * 4);
            u32 h01 = packbf(v.x, v.y);
            u32 h23 = packbf(v.z, v.w);
            float rx = v.x - __uint_as_float(h01 << 16);
            float ry = v.y - __uint_as_float(h01 & 0xffff0000u);
            float rz = v.z - __uint_as_float(h23 << 16);
            float rw = v.w - __uint_as_float(h23 & 0xffff0000u);
            uint2 qh = make_uint2(h01, h23);
            uint2 ql = make_uint2(packbf(rx, ry), packbf(rz, rw));
            *(uint2*)(sm + SW_W_HI + row * WW_RB + fq * 8) = qh;
            *(uint2*)(sm + SW_W_LO + row * WW_RB + fq * 8) = ql;
        }
        __syncthreads();
        #pragma unroll
        for (int kk = 0; kk < 4; kk++) {
            u32 ahi[2][4], alo[2][4];
            ldsm_x4(ahi[0], pa_hi + kk * 32);
            ldsm_x4(ahi[1], pa_hi + kk * 32 + 16 * WA_RB);
            ldsm_x4(alo[0], pa_lo + kk * 32);
            ldsm_x4(alo[1], pa_lo + kk * 32 + 16 * WA_RB);
            #pragma unroll
            for (int nt = 0; nt < 4; nt++) {
                u32 bhv[4], blv[4];
                u32 boff = (u32)kk * 16 * WW_RB + (u32)nt * 32;
                ldsm_x4t(bhv, pb_hi + boff);
                ldsm_x4t(blv, pb_lo + boff);
                #pragma unroll
                for (int mt = 0; mt < 2; mt++) {
                    mma_bf16(acc[mt][2 * nt],     ahi[mt], bhv[0], bhv[1]);
                    mma_bf16(acc[mt][2 * nt + 1], ahi[mt], bhv[2], bhv[3]);
                    mma_bf16(acc[mt][2 * nt],     ahi[mt], blv[0], blv[1]);
                    mma_bf16(acc[mt][2 * nt + 1], ahi[mt], blv[2], blv[3]);
                    mma_bf16(acc[mt][2 * nt],     alo[mt], bhv[0], bhv[1]);
                    mma_bf16(acc[mt][2 * nt + 1], alo[mt], bhv[2], bhv[3]);
                }
            }
        }
    }

    #pragma unroll
    for (int mt = 0; mt < 2; mt++) {
        int row1 = r0 + wm * 32 + mt * 16 + (lane >> 2);
        #pragma unroll
        for (int nt2 = 0; nt2 < 8; nt2++) {
            int col = f0 + wn * 64 + nt2 * 8 + (lane & 3) * 2;
            float d0 = acc[mt][nt2][0], d1 = acc[mt][nt2][1];
            float d2 = acc[mt][nt2][2], d3 = acc[mt][nt2][3];
            u32 h01 = packbf(d0, d1);
            u32 l01 = packbf(d0 - __uint_as_float(h01 << 16),
                             d1 - __uint_as_float(h01 & 0xffff0000u));
            u32 h23 = packbf(d2, d3);
            u32 l23 = packbf(d2 - __uint_as_float(h23 << 16),
                             d3 - __uint_as_float(h23 & 0xffff0000u));
            size_t o1 = ((size_t)b * T2 + row1) * FD + col;
            size_t o2 = o1 + (size_t)8 * FD;
            *(u32*)&g_Bhi[o1] = h01;  *(u32*)&g_Blo[o1] = l01;
            *(u32*)&g_Bhi[o2] = h23;  *(u32*)&g_Blo[o2] = l23;
        }
    }
}

// ---------------------------------------------------------------------------
// k_attn_mma: 512 threads, 16 warps (4m x 4n), warp tile 32x64.
// Split-precision bf16 mma.sync + cp.async double-buffered Wh staging.
// ---------------------------------------------------------------------------
#define WHS_RB  528                 // 256 bf16 (512B) + 16B pad per j-row
#define PS_RB   144                 // 64 bf16 (128B) + 16B pad per i-row
#define WHS_HALF 33792
#define WHS_BUF  67584
#define SM_PS_HI 135168
#define SM_PS_LO 153600
#define SM_TBL   172032             // 3*2048*4 = 24576
#define SM_ZPART 196608             // 512*4 = 2048
#define SM_ZFIN  198656             // 128*4 = 512
#define SM_ATTN_TOTAL 199168

__device__ __forceinline__ void stage_whs(u32 smb, int bsel,
                                          const __nv_bfloat16* bh,
                                          const __nv_bfloat16* bl,
                                          int j0, int f0, int tid) {
    u32 base = smb + (u32)bsel * WHS_BUF;
    #pragma unroll
    for (int s = 0; s < 4; s++) {
        int u = tid + 512 * s;
        int row = u >> 5, fo = u & 31;
        cpa16(base + row * WHS_RB + fo * 16,
              bh + (size_t)(j0 + row) * FD + f0 + fo * 8);
    }
    #pragma unroll
    for (int s = 0; s < 4; s++) {
        int u = tid + 512 * s;
        int row = u >> 5, fo = u & 31;
        cpa16(base + WHS_HALF + row * WHS_RB + fo * 16,
              bl + (size_t)(j0 + row) * FD + f0 + fo * 8);
    }
    asm volatile("cp.async.commit_group;" ::: "memory");
}

__global__ __launch_bounds__(512, 1) void k_attn_mma(const int* __restrict__ adj,
                                                     float* __restrict__ out) {
    extern __shared__ char sm[];
    const u32 smb = smem_u32(sm);
    const int tid = threadIdx.x;
    const int lane = tid & 31, wid = tid >> 5;
    const int wm = wid & 3, wn = wid >> 2;   // 4 x 4 warp grid
    const int b  = blockIdx.z;
    const int i0 = blockIdx.x * MI;
    const int f0 = blockIdx.y * NF;

    const __nv_bfloat16* bhsrc = g_Bhi + (size_t)b * T2 * FD;
    const __nv_bfloat16* blsrc = g_Blo + (size_t)b * T2 * FD;

    stage_whs(smb, 0, bhsrc, blsrc, 0, f0, tid);

    float* tw2 = (float*)(sm + SM_TBL);
    float* te1 = tw2 + T2;
    float* tea = tw2 + 2 * T2;
    #pragma unroll
    for (int s = 0; s < 4; s++) {
        int j = tid + 512 * s;
        int gj = b * T2 + j;
        tw2[j] = g_w2[gj];
        te1[j] = g_E1[gj];
        tea[j] = g_Ea[gj];
    }

    // P-build mapping: thread owns (i = tid>>2, 16 j's per chunk)
    const int it = tid >> 2, qt = (tid & 3) * 16;
    const int gi = b * T2 + i0 + it;
    const float w1i = g_w1[gi];
    const u64 F1pk = pk2(g_F1[gi]);
    const u64 Fapk = pk2(g_Fa[gi]);
    float zsum = 0.f;
    const size_t adjbase = ((size_t)(b * T2 + i0 + it)) * T2 + qt;

    float acc[2][8][4];
    #pragma unroll
    for (int m = 0; m < 2; m++)
        #pragma unroll
        for (int n = 0; n < 8; n++)
            #pragma unroll
            for (int e = 0; e < 4; e++) acc[m][n][e] = 0.f;

    const u32 a_lane = (u32)(lane & 15) * PS_RB + (u32)(lane >> 4) * 16;
    const u32 b_lane = (u32)(lane & 15) * WHS_RB + (u32)(lane >> 4) * 16;
    const u32 pa_hi = smb + SM_PS_HI + (u32)(wm * 32) * PS_RB + a_lane;
    const u32 pa_lo = smb + SM_PS_LO + (u32)(wm * 32) * PS_RB + a_lane;

    __syncthreads();   // tables visible

    for (int c = 0; c < NCHUNK; c++) {
        const int j0 = c * KC;
        if (c) __syncthreads();          // prev compute done (ps + alt buffer free)
        if (c + 1 < NCHUNK)
            stage_whs(smb, (c + 1) & 1, bhsrc, blsrc, j0 + KC, f0, tid);

        // build P tile [128 i][64 j] hi/lo — 16 j per thread
        #pragma unroll
        for (int q = 0; q < 2; q++) {
            int j = qt + q * 8;
            int4 a0 = *(const int4*)&adj[adjbase + j0 - qt + j];
            int4 a1 = *(const int4*)&adj[adjbase + j0 - qt + j + 4];
            int msk[8] = {a0.x, a0.y, a0.z, a0.w, a1.x, a1.y, a1.z, a1.w};
            u32 hw[4], lw[4];
            #pragma unroll
            for (int e2 = 0; e2 < 4; e2++) {
                int jj = j0 + j + e2 * 2;
                float2 w2p = *(const float2*)&tw2[jj];
                u64 e1u = *(const u64*)&te1[jj];
                u64 eau = *(const u64*)&tea[jj];
                float2 v1 = u2f2(mul2(F1pk, e1u));
                float2 va = u2f2(mul2(Fapk, eau));
                float p0 = (w1i + w2p.x > 0.f) ? v1.x : va.x;
                float p1 = (w1i + w2p.y > 0.f) ? v1.y : va.y;
                p0 = (msk[e2 * 2] > 0) ? p0 : 0.f;
                p1 = (msk[e2 * 2 + 1] > 0) ? p1 : 0.f;
                zsum += p0 + p1;
                u32 hp = packbf(p0, p1);
                float r0 = p0 - __uint_as_float(hp << 16);
                float r1 = p1 - __uint_as_float(hp & 0xffff0000u);
                hw[e2] = hp;
                lw[e2] = packbf(r0, r1);
            }
            u32 po = (u32)it * PS_RB + (u32)j * 2;
            *(uint4*)(sm + SM_PS_HI + po) = make_uint4(hw[0], hw[1], hw[2], hw[3]);
            *(uint4*)(sm + SM_PS_LO + po) = make_uint4(lw[0], lw[1], lw[2], lw[3]);
        }

        if (c + 1 < NCHUNK)
            asm volatile("cp.async.wait_group 1;" ::: "memory");
        else
            asm volatile("cp.async.wait_group 0;" ::: "memory");
        __syncthreads();

        const u32 wb_hi = smb + (u32)(c & 1) * WHS_BUF + (u32)(wn * 64) * 2 + b_lane;
        const u32 wb_lo = wb_hi + WHS_HALF;
        #pragma unroll
        for (int kk = 0; kk < 4; kk++) {
            u32 ahi[2][4], alo[2][4];
            ldsm_x4(ahi[0], pa_hi + kk * 32);
            ldsm_x4(ahi[1], pa_hi + kk * 32 + 16 * PS_RB);
            ldsm_x4(alo[0], pa_lo + kk * 32);
            ldsm_x4(alo[1], pa_lo + kk * 32 + 16 * PS_RB);
            #pragma unroll
            for (int nt = 0; nt < 4; nt++) {
                u32 bhv[4], blv[4];
                u32 boff = (u32)kk * 16 * WHS_RB + (u32)nt * 32;
                ldsm_x4t(bhv, wb_hi + boff);
                ldsm_x4t(blv, wb_lo + boff);
                #pragma unroll
                for (int mt = 0; mt < 2; mt++) {
                    mma_bf16(acc[mt][2 * nt],     ahi[mt], bhv[0], bhv[1]);
                    mma_bf16(acc[mt][2 * nt + 1], ahi[mt], bhv[2], bhv[3]);
                    mma_bf16(acc[mt][2 * nt],     ahi[mt], blv[0], blv[1]);
                    mma_bf16(acc[mt][2 * nt + 1], ahi[mt], blv[2], blv[3]);
                    mma_bf16(acc[mt][2 * nt],     alo[mt], bhv[0], bhv[1]);
                    mma_bf16(acc[mt][2 * nt + 1], alo[mt], bhv[2], bhv[3]);
                }
            }
        }
    }

    // Z reduction: 4 threads per row
    float* zpart = (float*)(sm + SM_ZPART);
    float* zfin  = (float*)(sm + SM_ZFIN);
    __syncthreads();
    zpart[tid] = zsum;
    __syncthreads();
    if (tid < 128)
        zfin[tid] = (zpart[4 * tid] + zpart[4 * tid + 1]) +
                    (zpart[4 * tid + 2] + zpart[4 * tid + 3]);
    __syncthreads();

    // epilogue: normalize, elu, split-write
    #pragma unroll
    for (int mt = 0; mt < 2; mt++) {
        int il = wm * 32 + mt * 16 + (lane >> 2);
        int g1 = i0 + il, g2 = g1 + 8;
        float inv1 = 1.f / zfin[il];
        float inv2 = 1.f / zfin[il + 8];
        size_t base1 = (g1 < TT) ? ((size_t)b * TT + g1) * FD
                                 : ((size_t)BS * TT + (size_t)b * TT + (g1 - TT)) * FD;
        size_t base2 = (g2 < TT) ? ((size_t)b * TT + g2) * FD
                                 : ((size_t)BS * TT + (size_t)b * TT + (g2 - TT)) * FD;
        #pragma unroll
        for (int nt = 0; nt < 8; nt++) {
            int col = f0 + wn * 64 + nt * 8 + (lane & 3) * 2;
            float2 v1, v2;
            float x;
            x = acc[mt][nt][0] * inv1; v1.x = x > 0.f ? x : expm1f(x);
            x = acc[mt][nt][1] * inv1; v1.y = x > 0.f ? x : expm1f(x);
            x = acc[mt][nt][2] * inv2; v2.x = x > 0.f ? x : expm1f(x);
            x = acc[mt][nt][3] * inv2; v2.y = x > 0.f ? x : expm1f(x);
            *(float2*)&out[base1 + col] = v1;
            *(float2*)&out[base2 + col] = v2;
        }
    }
}

// ---------------------------------------------------------------------------
extern "C" void kernel_launch(void* const* d_in, const int* in_sizes, int n_in,
                              void* d_out, int out_size) {
    const float* xa  = (const float*)d_in[0];
    const float* xv  = (const float*)d_in[1];
    const int*   adj = (const int*)d_in[2];
    const float* W   = (const float*)d_in[3];
    const float* a   = (const float*)d_in[4];
    float* out = (float*)d_out;

    cudaFuncSetAttribute(k_wh_mma, cudaFuncAttributeMaxDynamicSharedMemorySize,
                         SW_TOTAL);
    cudaFuncSetAttribute(k_attn_mma, cudaFuncAttributeMaxDynamicSharedMemorySize,
                         SM_ATTN_TOTAL);

    k_u<<<FD / 8, 256>>>(W, a);
    k_w12<<<BS * T2 / 8, 256>>>(xa, xv);
    k_prep<<<BS, 256>>>();
    dim3 gA(FD / 128, T2 / 128, BS);         // 1024 blocks
    k_wh_mma<<<gA, 256, SW_TOTAL>>>(xa, xv, W);
    dim3 gC(T2 / MI, FD / NF, BS);           // 512 blocks x 512 threads
    k_attn_mma<<<gC, 512, SM_ATTN_TOTAL>>>(adj, out);
}

// round 8
// speedup vs baseline: 3.6888x; 1.0086x over previous
#include <cuda_runtime.h>
#include <cuda_bf16.h>
#include <math.h>
#include <stdint.h>

#define BS 16
#define TT 1024
#define T2 2048
#define FD 512
#define ALPHA 0.1f
#define KC 64
#define NCHUNK (T2 / KC)   // 32
#define MI 128
#define NF 256

typedef unsigned long long u64;
typedef unsigned int u32;

// ---------------- device scratch (no cudaMalloc allowed) --------------------
static __device__ __nv_bfloat16 g_Bhi[(size_t)BS * T2 * FD];  // Wh hi, [b][j][f]
static __device__ __nv_bfloat16 g_Blo[(size_t)BS * T2 * FD];  // Wh lo
static __device__ float g_uvec[2 * FD];    // W@a1, W@a2
static __device__ float g_w1[BS * T2];
static __device__ float g_w2[BS * T2];
static __device__ float g_F1[BS * T2];
static __device__ float g_Fa[BS * T2];
static __device__ float g_E1[BS * T2];
static __device__ float g_Ea[BS * T2];

// ---------------- helpers ----------------------------------------------------
__device__ __forceinline__ u64 pk2(float x) {
    u64 r; asm("mov.b64 %0, {%1, %1};" : "=l"(r) : "f"(x)); return r;
}
__device__ __forceinline__ u64 mul2(u64 a, u64 b) {
    u64 d; asm("mul.rn.f32x2 %0, %1, %2;" : "=l"(d) : "l"(a), "l"(b)); return d;
}
__device__ __forceinline__ float2 u2f2(u64 v) {
    float2 r; asm("mov.b64 {%0, %1}, %2;" : "=f"(r.x), "=f"(r.y) : "l"(v)); return r;
}
__device__ __forceinline__ u32 packbf(float lo, float hi) {
    u32 r; asm("cvt.rn.bf16x2.f32 %0, %1, %2;" : "=r"(r) : "f"(hi), "f"(lo)); return r;
}
__device__ __forceinline__ u32 smem_u32(const void* p) {
    u32 a; asm("{ .reg .u64 t; cvta.to.shared.u64 t, %1; cvt.u32.u64 %0, t; }"
               : "=r"(a) : "l"(p));
    return a;
}
__device__ __forceinline__ void ldsm_x4(u32* r, u32 addr) {
    asm volatile("ldmatrix.sync.aligned.m8n8.x4.shared.b16 {%0,%1,%2,%3}, [%4];"
                 : "=r"(r[0]), "=r"(r[1]), "=r"(r[2]), "=r"(r[3]) : "r"(addr));
}
__device__ __forceinline__ void ldsm_x4t(u32* r, u32 addr) {
    asm volatile("ldmatrix.sync.aligned.m8n8.x4.trans.shared.b16 {%0,%1,%2,%3}, [%4];"
                 : "=r"(r[0]), "=r"(r[1]), "=r"(r[2]), "=r"(r[3]) : "r"(addr));
}
__device__ __forceinline__ void mma_bf16(float* d, const u32* a, u32 b0, u32 b1) {
    asm volatile(
        "mma.sync.aligned.m16n8k16.row.col.f32.bf16.bf16.f32 "
        "{%0,%1,%2,%3}, {%4,%5,%6,%7}, {%8,%9}, {%0,%1,%2,%3};"
        : "+f"(d[0]), "+f"(d[1]), "+f"(d[2]), "+f"(d[3])
        : "r"(a[0]), "r"(a[1]), "r"(a[2]), "r"(a[3]), "r"(b0), "r"(b1));
}
__device__ __forceinline__ void cpa16(u32 dst, const void* src) {
    asm volatile("{ .reg .u64 g; cvta.to.global.u64 g, %1; "
                 "cp.async.cg.shared.global [%0], [g], 16; }"
                 :: "r"(dst), "l"(src) : "memory");
}

// ---------------------------------------------------------------------------
// k_u: u1 = W @ a1, u2 = W @ a2. warp per k-row.
// ---------------------------------------------------------------------------
__global__ __launch_bounds__(256) void k_u(const float* __restrict__ W,
                                           const float* __restrict__ avec) {
    int k = blockIdx.x * 8 + (threadIdx.x >> 5);
    int lane = threadIdx.x & 31;
    const float* wr = W + (size_t)k * FD;
    float s1 = 0.f, s2 = 0.f;
    #pragma unroll
    for (int q = 0; q < 4; q++) {
        int f4 = lane + 32 * q;
        float4 w = *(const float4*)&wr[f4 * 4];
        float4 a1 = *(const float4*)&avec[f4 * 4];
        float4 a2 = *(const float4*)&avec[FD + f4 * 4];
        s1 += w.x * a1.x + w.y * a1.y + w.z * a1.z + w.w * a1.w;
        s2 += w.x * a2.x + w.y * a2.y + w.z * a2.z + w.w * a2.w;
    }
    #pragma unroll
    for (int o = 16; o > 0; o >>= 1) {
        s1 += __shfl_xor_sync(0xffffffffu, s1, o);
        s2 += __shfl_xor_sync(0xffffffffu, s2, o);
    }
    if (lane == 0) { g_uvec[k] = s1; g_uvec[FD + k] = s2; }
}

// ---------------------------------------------------------------------------
// k_w12: w1[row] = h_row · u1, w2[row] = h_row · u2  (exact fp32, associativity)
// ---------------------------------------------------------------------------
__global__ __launch_bounds__(256) void k_w12(const float* __restrict__ xa,
                                             const float* __restrict__ xv) {
    int row  = blockIdx.x * 8 + (threadIdx.x >> 5);
    int lane = threadIdx.x & 31;
    int b = row >> 11, r = row & (T2 - 1);
    const float* h = (r < TT) ? xa + ((size_t)b * TT + r) * FD
                              : xv + ((size_t)b * TT + (r - TT)) * FD;
    float s1 = 0.f, s2 = 0.f;
    #pragma unroll
    for (int q = 0; q < 4; q++) {
        int f4 = lane + 32 * q;
        float4 v  = *(const float4*)&h[f4 * 4];
        float4 a1 = *(const float4*)&g_uvec[f4 * 4];
        float4 a2 = *(const float4*)&g_uvec[FD + f4 * 4];
        s1 += v.x * a1.x + v.y * a1.y + v.z * a1.z + v.w * a1.w;
        s2 += v.x * a2.x + v.y * a2.y + v.z * a2.z + v.w * a2.w;
    }
    #pragma unroll
    for (int o = 16; o > 0; o >>= 1) {
        s1 += __shfl_xor_sync(0xffffffffu, s1, o);
        s2 += __shfl_xor_sync(0xffffffffu, s2, o);
    }
    if (lane == 0) { g_w1[row] = s1; g_w2[row] = s2; }
}

// ---------------------------------------------------------------------------
// k_prep: factorized-softmax tables.
// ---------------------------------------------------------------------------
__global__ __launch_bounds__(256) void k_prep() {
    __shared__ float red[256];
    __shared__ float Msh;
    int b = blockIdx.x, tid = threadIdx.x;
    const float* w2 = g_w2 + b * T2;
    float m = -1e30f;
    for (int i = tid; i < T2; i += 256) m = fmaxf(m, w2[i]);
    red[tid] = m; __syncthreads();
    for (int s = 128; s > 0; s >>= 1) {
        if (tid < s) red[tid] = fmaxf(red[tid], red[tid + s]);
        __syncthreads();
    }
    if (tid == 0) Msh = red[0];
    __syncthreads();
    float M = Msh;
    const float* w1 = g_w1 + b * T2;
    for (int i = tid; i < T2; i += 256) {
        float v1 = w1[i], v2 = w2[i];
        float s  = v1 + M;
        float mi = s > 0.f ? s : ALPHA * s;
        g_F1[b * T2 + i] = expf(v1 - mi);
        g_Fa[b * T2 + i] = expf(ALPHA * v1 - mi);
        g_E1[b * T2 + i] = expf(v2);
        g_Ea[b * T2 + i] = expf(ALPHA * v2);
    }
}

// ---------------------------------------------------------------------------
// k_wh_mma: unchanged (R7, validated). Wh = h @ W, 3-pass bf16 split.
// ---------------------------------------------------------------------------
#define WA_RB 144
#define WW_RB 272
#define SW_A_HI 0
#define SW_A_LO 18432
#define SW_W_HI 36864
#define SW_W_LO 54272
#define SW_TOTAL 71680

__global__ __launch_bounds__(256, 2) void k_wh_mma(const float* __restrict__ xa,
                                                   const float* __restrict__ xv,
                                                   const float* __restrict__ W) {
    extern __shared__ char sm[];
    const u32 smb = smem_u32(sm);
    const int tid = threadIdx.x, lane = tid & 31, wid = tid >> 5;
    const int wm = wid & 3, wn = wid >> 2;
    const int b  = blockIdx.z;
    const int r0 = blockIdx.y * 128;
    const int f0 = blockIdx.x * 128;
    const float* __restrict__ h = (r0 < TT)
        ? (xa + ((size_t)b * TT + r0) * FD)
        : (xv + ((size_t)b * TT + (r0 - TT)) * FD);

    float acc[2][8][4];
    #pragma unroll
    for (int m = 0; m < 2; m++)
        #pragma unroll
        for (int n = 0; n < 8; n++)
            #pragma unroll
            for (int e = 0; e < 4; e++) acc[m][n][e] = 0.f;

    const u32 a_lane = (u32)(lane & 15) * WA_RB + (u32)(lane >> 4) * 16;
    const u32 b_lane = (u32)(lane & 15) * WW_RB + (u32)(lane >> 4) * 16;
    const u32 pa_hi = smb + SW_A_HI + (u32)(wm * 32) * WA_RB + a_lane;
    const u32 pa_lo = smb + SW_A_LO + (u32)(wm * 32) * WA_RB + a_lane;
    const u32 pb_hi = smb + SW_W_HI + (u32)(wn * 64) * 2 + b_lane;
    const u32 pb_lo = smb + SW_W_LO + (u32)(wn * 64) * 2 + b_lane;

    for (int k0 = 0; k0 < FD; k0 += KC) {
        if (k0) __syncthreads();
        #pragma unroll
        for (int s = 0; s < 8; s++) {
            int u = tid + 256 * s;
            int row = u >> 4, kq = u & 15;
            float4 v = *(const float4*)(h + (size_t)row * FD + k0 + kq * 4);
            u32 h01 = packbf(v.x, v.y);
            u32 h23 = packbf(v.z, v.w);
            float rx = v.x - __uint_as_float(h01 << 16);
            float ry = v.y - __uint_as_float(h01 & 0xffff0000u);
            float rz = v.z - __uint_as_float(h23 << 16);
            float rw = v.w - __uint_as_float(h23 & 0xffff0000u);
            uint2 qh = make_uint2(h01, h23);
            uint2 ql = make_uint2(packbf(rx, ry), packbf(rz, rw));
            *(uint2*)(sm + SW_A_HI + row * WA_RB + kq * 8) = qh;
            *(uint2*)(sm + SW_A_LO + row * WA_RB + kq * 8) = ql;
        }
        #pragma unroll
        for (int s = 0; s < 8; s++) {
            int u = tid + 256 * s;
            int row = u >> 5, fq = u & 31;
            float4 v = *(const float4*)(W + (size_t)(k0 + row) * FD + f0 + fq * 4);
            u32 h01 = packbf(v.x, v.y);
            u32 h23 = packbf(v.z, v.w);
            float rx = v.x - __uint_as_float(h01 << 16);
            float ry = v.y - __uint_as_float(h01 & 0xffff0000u);
            float rz = v.z - __uint_as_float(h23 << 16);
            float rw = v.w - __uint_as_float(h23 & 0xffff0000u);
            uint2 qh = make_uint2(h01, h23);
            uint2 ql = make_uint2(packbf(rx, ry), packbf(rz, rw));
            *(uint2*)(sm + SW_W_HI + row * WW_RB + fq * 8) = qh;
            *(uint2*)(sm + SW_W_LO + row * WW_RB + fq * 8) = ql;
        }
        __syncthreads();
        #pragma unroll
        for (int kk = 0; kk < 4; kk++) {
            u32 ahi[2][4], alo[2][4];
            ldsm_x4(ahi[0], pa_hi + kk * 32);
            ldsm_x4(ahi[1], pa_hi + kk * 32 + 16 * WA_RB);
            ldsm_x4(alo[0], pa_lo + kk * 32);
            ldsm_x4(alo[1], pa_lo + kk * 32 + 16 * WA_RB);
            #pragma unroll
            for (int nt = 0; nt < 4; nt++) {
                u32 bhv[4], blv[4];
                u32 boff = (u32)kk * 16 * WW_RB + (u32)nt * 32;
                ldsm_x4t(bhv, pb_hi + boff);
                ldsm_x4t(blv, pb_lo + boff);
                #pragma unroll
                for (int mt = 0; mt < 2; mt++) {
                    mma_bf16(acc[mt][2 * nt],     ahi[mt], bhv[0], bhv[1]);
                    mma_bf16(acc[mt][2 * nt + 1], ahi[mt], bhv[2], bhv[3]);
                    mma_bf16(acc[mt][2 * nt],     ahi[mt], blv[0], blv[1]);
                    mma_bf16(acc[mt][2 * nt + 1], ahi[mt], blv[2], blv[3]);
                    mma_bf16(acc[mt][2 * nt],     alo[mt], bhv[0], bhv[1]);
                    mma_bf16(acc[mt][2 * nt + 1], alo[mt], bhv[2], bhv[3]);
                }
            }
        }
    }

    #pragma unroll
    for (int mt = 0; mt < 2; mt++) {
        int row1 = r0 + wm * 32 + mt * 16 + (lane >> 2);
        #pragma unroll
        for (int nt2 = 0; nt2 < 8; nt2++) {
            int col = f0 + wn * 64 + nt2 * 8 + (lane & 3) * 2;
            float d0 = acc[mt][nt2][0], d1 = acc[mt][nt2][1];
            float d2 = acc[mt][nt2][2], d3 = acc[mt][nt2][3];
            u32 h01 = packbf(d0, d1);
            u32 l01 = packbf(d0 - __uint_as_float(h01 << 16),
                             d1 - __uint_as_float(h01 & 0xffff0000u));
            u32 h23 = packbf(d2, d3);
            u32 l23 = packbf(d2 - __uint_as_float(h23 << 16),
                             d3 - __uint_as_float(h23 & 0xffff0000u));
            size_t o1 = ((size_t)b * T2 + row1) * FD + col;
            size_t o2 = o1 + (size_t)8 * FD;
            *(u32*)&g_Bhi[o1] = h01;  *(u32*)&g_Blo[o1] = l01;
            *(u32*)&g_Bhi[o2] = h23;  *(u32*)&g_Blo[o2] = l23;
        }
    }
}

// ---------------------------------------------------------------------------
// k_attn_mma: single-barrier software pipeline.
// Per iter: sync -> stage B(c+1) -> prefetch adj(c+1) -> MMA(c) -> build P(c+1).
// P tiles double-buffered; exp tables read from global (L1/L2 resident).
// ---------------------------------------------------------------------------
#define WHS_RB   528
#define PS_RB    144
#define WHS_HALF 33792
#define WHS_BUF  67584
#define SM_PS    135168
#define PS_HALF  18432
#define PS_BUF   36864
#define SM_ZPART 208896
#define SM_ZFIN  210944
#define SM_ATTN_TOTAL 211456

__device__ __forceinline__ void stage_whs(u32 smb, int bsel,
                                          const __nv_bfloat16* bh,
                                          const __nv_bfloat16* bl,
                                          int j0, int f0, int tid) {
    u32 base = smb + (u32)bsel * WHS_BUF;
    #pragma unroll
    for (int s = 0; s < 4; s++) {
        int u = tid + 512 * s;
        int row = u >> 5, fo = u & 31;
        cpa16(base + row * WHS_RB + fo * 16,
              bh + (size_t)(j0 + row) * FD + f0 + fo * 8);
    }
    #pragma unroll
    for (int s = 0; s < 4; s++) {
        int u = tid + 512 * s;
        int row = u >> 5, fo = u & 31;
        cpa16(base + WHS_HALF + row * WHS_RB + fo * 16,
              bl + (size_t)(j0 + row) * FD + f0 + fo * 8);
    }
    asm volatile("cp.async.commit_group;" ::: "memory");
}

__device__ __forceinline__ void build_p(char* sm, int bufsel, int it, int qt,
                                        const int4* msk4, int j0,
                                        float w1i, u64 F1pk, u64 Fapk,
                                        const float* tw2g, const float* te1g,
                                        const float* teag, float& zsum) {
    char* base = sm + SM_PS + bufsel * PS_BUF;
    #pragma unroll
    for (int q = 0; q < 2; q++) {
        int j = qt + q * 8;
        int4 a0 = msk4[q * 2], a1 = msk4[q * 2 + 1];
        int msk[8] = {a0.x, a0.y, a0.z, a0.w, a1.x, a1.y, a1.z, a1.w};
        u32 hw[4], lw[4];
        #pragma unroll
        for (int e2 = 0; e2 < 4; e2++) {
            int jj = j0 + j + e2 * 2;
            float2 w2p = *(const float2*)(tw2g + jj);
            u64 e1u = *(const u64*)(te1g + jj);
            u64 eau = *(const u64*)(teag + jj);
            float2 v1 = u2f2(mul2(F1pk, e1u));
            float2 va = u2f2(mul2(Fapk, eau));
            float p0 = (w1i + w2p.x > 0.f) ? v1.x : va.x;
            float p1 = (w1i + w2p.y > 0.f) ? v1.y : va.y;
            p0 = (msk[e2 * 2] > 0) ? p0 : 0.f;
            p1 = (msk[e2 * 2 + 1] > 0) ? p1 : 0.f;
            zsum += p0 + p1;
            u32 hp = packbf(p0, p1);
            float r0 = p0 - __uint_as_float(hp << 16);
            float r1 = p1 - __uint_as_float(hp & 0xffff0000u);
            hw[e2] = hp;
            lw[e2] = packbf(r0, r1);
        }
        u32 po = (u32)it * PS_RB + (u32)j * 2;
        *(uint4*)(base + po)           = make_uint4(hw[0], hw[1], hw[2], hw[3]);
        *(uint4*)(base + PS_HALF + po) = make_uint4(lw[0], lw[1], lw[2], lw[3]);
    }
}

__global__ __launch_bounds__(512, 1) void k_attn_mma(const int* __restrict__ adj,
                                                     float* __restrict__ out) {
    extern __shared__ char sm[];
    const u32 smb = smem_u32(sm);
    const int tid = threadIdx.x;
    const int lane = tid & 31, wid = tid >> 5;
    const int wm = wid & 3, wn = wid >> 2;   // 4 x 4 warp grid
    const int b  = blockIdx.z;
    const int i0 = blockIdx.x * MI;
    const int f0 = blockIdx.y * NF;

    const __nv_bfloat16* bhsrc = g_Bhi + (size_t)b * T2 * FD;
    const __nv_bfloat16* blsrc = g_Blo + (size_t)b * T2 * FD;
    const float* tw2g = g_w2 + b * T2;
    const float* te1g = g_E1 + b * T2;
    const float* teag = g_Ea + b * T2;

    stage_whs(smb, 0, bhsrc, blsrc, 0, f0, tid);

    // P-build mapping: thread owns (i = tid>>2, 16 contiguous j per chunk)
    const int it = tid >> 2, qt = (tid & 3) * 16;
    const int gi = b * T2 + i0 + it;
    const float w1i = g_w1[gi];
    const u64 F1pk = pk2(g_F1[gi]);
    const u64 Fapk = pk2(g_Fa[gi]);
    float zsum = 0.f;
    const int* adjrow = adj + ((size_t)(b * T2 + i0 + it)) * T2 + qt;

    float acc[2][8][4];
    #pragma unroll
    for (int m = 0; m < 2; m++)
        #pragma unroll
        for (int n = 0; n < 8; n++)
            #pragma unroll
            for (int e = 0; e < 4; e++) acc[m][n][e] = 0.f;

    const u32 a_lane = (u32)(lane & 15) * PS_RB + (u32)(lane >> 4) * 16;
    const u32 b_lane = (u32)(lane & 15) * WHS_RB + (u32)(lane >> 4) * 16;
    const u32 pa_base = smb + SM_PS + (u32)(wm * 32) * PS_RB + a_lane;

    // prologue: build P(0) into buffer 0
    {
        int4 pre[4];
        pre[0] = *(const int4*)(adjrow);
        pre[1] = *(const int4*)(adjrow + 4);
        pre[2] = *(const int4*)(adjrow + 8);
        pre[3] = *(const int4*)(adjrow + 12);
        build_p(sm, 0, it, qt, pre, 0, w1i, F1pk, Fapk, tw2g, te1g, teag, zsum);
    }
    asm volatile("cp.async.wait_group 0;" ::: "memory");
    __syncthreads();

    for (int c = 0; c < NCHUNK; c++) {
        const int j0 = c * KC;
        if (c) __syncthreads();

        int4 pre[4];
        if (c + 1 < NCHUNK) {
            stage_whs(smb, (c + 1) & 1, bhsrc, blsrc, j0 + KC, f0, tid);
            const int* ap = adjrow + j0 + KC;
            pre[0] = *(const int4*)(ap);
            pre[1] = *(const int4*)(ap + 4);
            pre[2] = *(const int4*)(ap + 8);
            pre[3] = *(const int4*)(ap + 12);
        }

        // MMA(c): P buffer c&1, Wh buffer c&1
        const u32 pa_hi = pa_base + (u32)(c & 1) * PS_BUF;
        const u32 pa_lo = pa_hi + PS_HALF;
        const u32 wb_hi = smb + (u32)(c & 1) * WHS_BUF + (u32)(wn * 64) * 2 + b_lane;
        const u32 wb_lo = wb_hi + WHS_HALF;
        #pragma unroll
        for (int kk = 0; kk < 4; kk++) {
            u32 ahi[2][4], alo[2][4];
            ldsm_x4(ahi[0], pa_hi + kk * 32);
            ldsm_x4(ahi[1], pa_hi + kk * 32 + 16 * PS_RB);
            ldsm_x4(alo[0], pa_lo + kk * 32);
            ldsm_x4(alo[1], pa_lo + kk * 32 + 16 * PS_RB);
            #pragma unroll
            for (int nt = 0; nt < 4; nt++) {
                u32 bhv[4], blv[4];
                u32 boff = (u32)kk * 16 * WHS_RB + (u32)nt * 32;
                ldsm_x4t(bhv, wb_hi + boff);
                ldsm_x4t(blv, wb_lo + boff);
                #pragma unroll
                for (int mt = 0; mt < 2; mt++) {
                    mma_bf16(acc[mt][2 * nt],     ahi[mt], bhv[0], bhv[1]);
                    mma_bf16(acc[mt][2 * nt + 1], ahi[mt], bhv[2], bhv[3]);
                    mma_bf16(acc[mt][2 * nt],     ahi[mt], blv[0], blv[1]);
                    mma_bf16(acc[mt][2 * nt + 1], ahi[mt], blv[2], blv[3]);
                    mma_bf16(acc[mt][2 * nt],     alo[mt], bhv[0], bhv[1]);
                    mma_bf16(acc[mt][2 * nt + 1], alo[mt], bhv[2], bhv[3]);
                }
            }
        }

        if (c + 1 < NCHUNK)
            build_p(sm, (c + 1) & 1, it, qt, pre, j0 + KC,
                    w1i, F1pk, Fapk, tw2g, te1g, teag, zsum);

        asm volatile("cp.async.wait_group 0;" ::: "memory");
    }

    // Z reduction: 4 threads per row
    float* zpart = (float*)(sm + SM_ZPART);
    float* zfin  = (float*)(sm + SM_ZFIN);
    __syncthreads();
    zpart[tid] = zsum;
    __syncthreads();
    if (tid < 128)
        zfin[tid] = (zpart[4 * tid] + zpart[4 * tid + 1]) +
                    (zpart[4 * tid + 2] + zpart[4 * tid + 3]);
    __syncthreads();

    // epilogue: normalize, elu, split-write
    #pragma unroll
    for (int mt = 0; mt < 2; mt++) {
        int il = wm * 32 + mt * 16 + (lane >> 2);
        int g1 = i0 + il, g2 = g1 + 8;
        float inv1 = 1.f / zfin[il];
        float inv2 = 1.f / zfin[il + 8];
        size_t base1 = (g1 < TT) ? ((size_t)b * TT + g1) * FD
                                 : ((size_t)BS * TT + (size_t)b * TT + (g1 - TT)) * FD;
        size_t base2 = (g2 < TT) ? ((size_t)b * TT + g2) * FD
                                 : ((size_t)BS * TT + (size_t)b * TT + (g2 - TT)) * FD;
        #pragma unroll
        for (int nt = 0; nt < 8; nt++) {
            int col = f0 + wn * 64 + nt * 8 + (lane & 3) * 2;
            float2 v1, v2;
            float x;
            x = acc[mt][nt][0] * inv1; v1.x = x > 0.f ? x : expm1f(x);
            x = acc[mt][nt][1] * inv1; v1.y = x > 0.f ? x : expm1f(x);
            x = acc[mt][nt][2] * inv2; v2.x = x > 0.f ? x : expm1f(x);
            x = acc[mt][nt][3] * inv2; v2.y = x > 0.f ? x : expm1f(x);
            *(float2*)&out[base1 + col] = v1;
            *(float2*)&out[base2 + col] = v2;
        }
    }
}

// ---------------------------------------------------------------------------
extern "C" void kernel_launch(void* const* d_in, const int* in_sizes, int n_in,
                              void* d_out, int out_size) {
    const float* xa  = (const float*)d_in[0];
    const float* xv  = (const float*)d_in[1];
    const int*   adj = (const int*)d_in[2];
    const float* W   = (const float*)d_in[3];
    const float* a   = (const float*)d_in[4];
    float* out = (float*)d_out;

    cudaFuncSetAttribute(k_wh_mma, cudaFuncAttributeMaxDynamicSharedMemorySize,
                         SW_TOTAL);
    cudaFuncSetAttribute(k_attn_mma, cudaFuncAttributeMaxDynamicSharedMemorySize,
                         SM_ATTN_TOTAL);

    k_u<<<FD / 8, 256>>>(W, a);
    k_w12<<<BS * T2 / 8, 256>>>(xa, xv);
    k_prep<<<BS, 256>>>();
    dim3 gA(FD / 128, T2 / 128, BS);         // 1024 blocks
    k_wh_mma<<<gA, 256, SW_TOTAL>>>(xa, xv, W);
    dim3 gC(T2 / MI, FD / NF, BS);           // 512 blocks x 512 threads
    k_attn_mma<<<gC, 512, SM_ATTN_TOTAL>>>(adj, out);
}

// round 9
// speedup vs baseline: 4.5540x; 1.2346x over previous
#include <cuda_runtime.h>
#include <cuda_fp16.h>
#include <math.h>
#include <stdint.h>

#define BS 16
#define TT 1024
#define T2 2048
#define FD 512
#define ALPHA 0.1f
#define KC 64
#define NCHUNK (T2 / KC)   // 32
#define MI 128
#define NF 256

typedef unsigned long long u64;
typedef unsigned int u32;

// ---------------- device scratch (no cudaMalloc allowed) --------------------
static __device__ __half g_Bhi[(size_t)BS * T2 * FD];  // Wh hi (fp16), [b][j][f]
static __device__ __half g_Blo[(size_t)BS * T2 * FD];  // Wh lo (fp16)
static __device__ float g_uvec[2 * FD];    // W@a1, W@a2
static __device__ float g_w1[BS * T2];
static __device__ float g_w2[BS * T2];
static __device__ float g_F1[BS * T2];
static __device__ float g_Fa[BS * T2];
static __device__ float g_E1[BS * T2];
static __device__ float g_Ea[BS * T2];

// ---------------- helpers ----------------------------------------------------
__device__ __forceinline__ u64 pk2(float x) {
    u64 r; asm("mov.b64 %0, {%1, %1};" : "=l"(r) : "f"(x)); return r;
}
__device__ __forceinline__ u64 mul2(u64 a, u64 b) {
    u64 d; asm("mul.rn.f32x2 %0, %1, %2;" : "=l"(d) : "l"(a), "l"(b)); return d;
}
__device__ __forceinline__ float2 u2f2(u64 v) {
    float2 r; asm("mov.b64 {%0, %1}, %2;" : "=f"(r.x), "=f"(r.y) : "l"(v)); return r;
}
// packed f16x2 convert: low16 = f16(lo), high16 = f16(hi)
__device__ __forceinline__ u32 packhf(float lo, float hi) {
    u32 r; asm("cvt.rn.f16x2.f32 %0, %1, %2;" : "=r"(r) : "f"(hi), "f"(lo)); return r;
}
__device__ __forceinline__ float2 unpackhf(u32 p) {
    __half2 h = *reinterpret_cast<__half2*>(&p);
    return __half22float2(h);
}
__device__ __forceinline__ u32 smem_u32(const void* p) {
    u32 a; asm("{ .reg .u64 t; cvta.to.shared.u64 t, %1; cvt.u32.u64 %0, t; }"
               : "=r"(a) : "l"(p));
    return a;
}
__device__ __forceinline__ void ldsm_x4(u32* r, u32 addr) {
    asm volatile("ldmatrix.sync.aligned.m8n8.x4.shared.b16 {%0,%1,%2,%3}, [%4];"
                 : "=r"(r[0]), "=r"(r[1]), "=r"(r[2]), "=r"(r[3]) : "r"(addr));
}
__device__ __forceinline__ void ldsm_x4t(u32* r, u32 addr) {
    asm volatile("ldmatrix.sync.aligned.m8n8.x4.trans.shared.b16 {%0,%1,%2,%3}, [%4];"
                 : "=r"(r[0]), "=r"(r[1]), "=r"(r[2]), "=r"(r[3]) : "r"(addr));
}
__device__ __forceinline__ void mma_f16(float* d, const u32* a, u32 b0, u32 b1) {
    asm volatile(
        "mma.sync.aligned.m16n8k16.row.col.f32.f16.f16.f32 "
        "{%0,%1,%2,%3}, {%4,%5,%6,%7}, {%8,%9}, {%0,%1,%2,%3};"
        : "+f"(d[0]), "+f"(d[1]), "+f"(d[2]), "+f"(d[3])
        : "r"(a[0]), "r"(a[1]), "r"(a[2]), "r"(a[3]), "r"(b0), "r"(b1));
}
__device__ __forceinline__ void cpa16(u32 dst, const void* src) {
    asm volatile("{ .reg .u64 g; cvta.to.global.u64 g, %1; "
                 "cp.async.cg.shared.global [%0], [g], 16; }"
                 :: "r"(dst), "l"(src) : "memory");
}

// ---------------------------------------------------------------------------
// k_u: u1 = W @ a1, u2 = W @ a2. warp per k-row.
// ---------------------------------------------------------------------------
__global__ __launch_bounds__(256) void k_u(const float* __restrict__ W,
                                           const float* __restrict__ avec) {
    int k = blockIdx.x * 8 + (threadIdx.x >> 5);
    int lane = threadIdx.x & 31;
    const float* wr = W + (size_t)k * FD;
    float s1 = 0.f, s2 = 0.f;
    #pragma unroll
    for (int q = 0; q < 4; q++) {
        int f4 = lane + 32 * q;
        float4 w = *(const float4*)&wr[f4 * 4];
        float4 a1 = *(const float4*)&avec[f4 * 4];
        float4 a2 = *(const float4*)&avec[FD + f4 * 4];
        s1 += w.x * a1.x + w.y * a1.y + w.z * a1.z + w.w * a1.w;
        s2 += w.x * a2.x + w.y * a2.y + w.z * a2.z + w.w * a2.w;
    }
    #pragma unroll
    for (int o = 16; o > 0; o >>= 1) {
        s1 += __shfl_xor_sync(0xffffffffu, s1, o);
        s2 += __shfl_xor_sync(0xffffffffu, s2, o);
    }
    if (lane == 0) { g_uvec[k] = s1; g_uvec[FD + k] = s2; }
}

// ---------------------------------------------------------------------------
// k_w12: w1[row] = h_row · u1, w2[row] = h_row · u2  (exact fp32, associativity)
// ---------------------------------------------------------------------------
__global__ __launch_bounds__(256) void k_w12(const float* __restrict__ xa,
                                             const float* __restrict__ xv) {
    int row  = blockIdx.x * 8 + (threadIdx.x >> 5);
    int lane = threadIdx.x & 31;
    int b = row >> 11, r = row & (T2 - 1);
    const float* h = (r < TT) ? xa + ((size_t)b * TT + r) * FD
                              : xv + ((size_t)b * TT + (r - TT)) * FD;
    float s1 = 0.f, s2 = 0.f;
    #pragma unroll
    for (int q = 0; q < 4; q++) {
        int f4 = lane + 32 * q;
        float4 v  = *(const float4*)&h[f4 * 4];
        float4 a1 = *(const float4*)&g_uvec[f4 * 4];
        float4 a2 = *(const float4*)&g_uvec[FD + f4 * 4];
        s1 += v.x * a1.x + v.y * a1.y + v.z * a1.z + v.w * a1.w;
        s2 += v.x * a2.x + v.y * a2.y + v.z * a2.z + v.w * a2.w;
    }
    #pragma unroll
    for (int o = 16; o > 0; o >>= 1) {
        s1 += __shfl_xor_sync(0xffffffffu, s1, o);
        s2 += __shfl_xor_sync(0xffffffffu, s2, o);
    }
    if (lane == 0) { g_w1[row] = s1; g_w2[row] = s2; }
}

// ---------------------------------------------------------------------------
// k_prep: factorized-softmax tables.
// ---------------------------------------------------------------------------
__global__ __launch_bounds__(256) void k_prep() {
    __shared__ float red[256];
    __shared__ float Msh;
    int b = blockIdx.x, tid = threadIdx.x;
    const float* w2 = g_w2 + b * T2;
    float m = -1e30f;
    for (int i = tid; i < T2; i += 256) m = fmaxf(m, w2[i]);
    red[tid] = m; __syncthreads();
    for (int s = 128; s > 0; s >>= 1) {
        if (tid < s) red[tid] = fmaxf(red[tid], red[tid + s]);
        __syncthreads();
    }
    if (tid == 0) Msh = red[0];
    __syncthreads();
    float M = Msh;
    const float* w1 = g_w1 + b * T2;
    for (int i = tid; i < T2; i += 256) {
        float v1 = w1[i], v2 = w2[i];
        float s  = v1 + M;
        float mi = s > 0.f ? s : ALPHA * s;
        g_F1[b * T2 + i] = expf(v1 - mi);
        g_Fa[b * T2 + i] = expf(ALPHA * v1 - mi);
        g_E1[b * T2 + i] = expf(v2);
        g_Ea[b * T2 + i] = expf(ALPHA * v2);
    }
}

// ---------------------------------------------------------------------------
// k_wh_mma: Wh = h @ W, fp16 split-precision 3 passes (near-fp32 accuracy).
// Writes fp16 hi/lo Wh to g_Bhi/g_Blo [b][j][f].
// ---------------------------------------------------------------------------
#define WA_RB 144
#define WW_RB 272
#define SW_A_HI 0
#define SW_A_LO 18432
#define SW_W_HI 36864
#define SW_W_LO 54272
#define SW_TOTAL 71680

__global__ __launch_bounds__(256, 2) void k_wh_mma(const float* __restrict__ xa,
                                                   const float* __restrict__ xv,
                                                   const float* __restrict__ W) {
    extern __shared__ char sm[];
    const u32 smb = smem_u32(sm);
    const int tid = threadIdx.x, lane = tid & 31, wid = tid >> 5;
    const int wm = wid & 3, wn = wid >> 2;
    const int b  = blockIdx.z;
    const int r0 = blockIdx.y * 128;
    const int f0 = blockIdx.x * 128;
    const float* __restrict__ h = (r0 < TT)
        ? (xa + ((size_t)b * TT + r0) * FD)
        : (xv + ((size_t)b * TT + (r0 - TT)) * FD);

    float acc[2][8][4];
    #pragma unroll
    for (int m = 0; m < 2; m++)
        #pragma unroll
        for (int n = 0; n < 8; n++)
            #pragma unroll
            for (int e = 0; e < 4; e++) acc[m][n][e] = 0.f;

    const u32 a_lane = (u32)(lane & 15) * WA_RB + (u32)(lane >> 4) * 16;
    const u32 b_lane = (u32)(lane & 15) * WW_RB + (u32)(lane >> 4) * 16;
    const u32 pa_hi = smb + SW_A_HI + (u32)(wm * 32) * WA_RB + a_lane;
    const u32 pa_lo = smb + SW_A_LO + (u32)(wm * 32) * WA_RB + a_lane;
    const u32 pb_hi = smb + SW_W_HI + (u32)(wn * 64) * 2 + b_lane;
    const u32 pb_lo = smb + SW_W_LO + (u32)(wn * 64) * 2 + b_lane;

    for (int k0 = 0; k0 < FD; k0 += KC) {
        if (k0) __syncthreads();
        #pragma unroll
        for (int s = 0; s < 8; s++) {
            int u = tid + 256 * s;
            int row = u >> 4, kq = u & 15;
            float4 v = *(const float4*)(h + (size_t)row * FD + k0 + kq * 4);
            u32 h01 = packhf(v.x, v.y);
            u32 h23 = packhf(v.z, v.w);
            float2 f01 = unpackhf(h01);
            float2 f23 = unpackhf(h23);
            uint2 qh = make_uint2(h01, h23);
            uint2 ql = make_uint2(packhf(v.x - f01.x, v.y - f01.y),
                                  packhf(v.z - f23.x, v.w - f23.y));
            *(uint2*)(sm + SW_A_HI + row * WA_RB + kq * 8) = qh;
            *(uint2*)(sm + SW_A_LO + row * WA_RB + kq * 8) = ql;
        }
        #pragma unroll
        for (int s = 0; s < 8; s++) {
            int u = tid + 256 * s;
            int row = u >> 5, fq = u & 31;
            float4 v = *(const float4*)(W + (size_t)(k0 + row) * FD + f0 + fq * 4);
            u32 h01 = packhf(v.x, v.y);
            u32 h23 = packhf(v.z, v.w);
            float2 f01 = unpackhf(h01);
            float2 f23 = unpackhf(h23);
            uint2 qh = make_uint2(h01, h23);
            uint2 ql = make_uint2(packhf(v.x - f01.x, v.y - f01.y),
                                  packhf(v.z - f23.x, v.w - f23.y));
            *(uint2*)(sm + SW_W_HI + row * WW_RB + fq * 8) = qh;
            *(uint2*)(sm + SW_W_LO + row * WW_RB + fq * 8) = ql;
        }
        __syncthreads();
        #pragma unroll
        for (int kk = 0; kk < 4; kk++) {
            u32 ahi[2][4], alo[2][4];
            ldsm_x4(ahi[0], pa_hi + kk * 32);
            ldsm_x4(ahi[1], pa_hi + kk * 32 + 16 * WA_RB);
            ldsm_x4(alo[0], pa_lo + kk * 32);
            ldsm_x4(alo[1], pa_lo + kk * 32 + 16 * WA_RB);
            #pragma unroll
            for (int nt = 0; nt < 4; nt++) {
                u32 bhv[4], blv[4];
                u32 boff = (u32)kk * 16 * WW_RB + (u32)nt * 32;
                ldsm_x4t(bhv, pb_hi + boff);
                ldsm_x4t(blv, pb_lo + boff);
                #pragma unroll
                for (int mt = 0; mt < 2; mt++) {
                    mma_f16(acc[mt][2 * nt],     ahi[mt], bhv[0], bhv[1]);
                    mma_f16(acc[mt][2 * nt + 1], ahi[mt], bhv[2], bhv[3]);
                    mma_f16(acc[mt][2 * nt],     ahi[mt], blv[0], blv[1]);
                    mma_f16(acc[mt][2 * nt + 1], ahi[mt], blv[2], blv[3]);
                    mma_f16(acc[mt][2 * nt],     alo[mt], bhv[0], bhv[1]);
                    mma_f16(acc[mt][2 * nt + 1], alo[mt], bhv[2], bhv[3]);
                }
            }
        }
    }

    #pragma unroll
    for (int mt = 0; mt < 2; mt++) {
        int row1 = r0 + wm * 32 + mt * 16 + (lane >> 2);
        #pragma unroll
        for (int nt2 = 0; nt2 < 8; nt2++) {
            int col = f0 + wn * 64 + nt2 * 8 + (lane & 3) * 2;
            float d0 = acc[mt][nt2][0], d1 = acc[mt][nt2][1];
            float d2 = acc[mt][nt2][2], d3 = acc[mt][nt2][3];
            u32 h01 = packhf(d0, d1);
            float2 f01 = unpackhf(h01);
            u32 l01 = packhf(d0 - f01.x, d1 - f01.y);
            u32 h23 = packhf(d2, d3);
            float2 f23 = unpackhf(h23);
            u32 l23 = packhf(d2 - f23.x, d3 - f23.y);
            size_t o1 = ((size_t)b * T2 + row1) * FD + col;
            size_t o2 = o1 + (size_t)8 * FD;
            *(u32*)&g_Bhi[o1] = h01;  *(u32*)&g_Blo[o1] = l01;
            *(u32*)&g_Bhi[o2] = h23;  *(u32*)&g_Blo[o2] = l23;
        }
    }
}

// ---------------------------------------------------------------------------
// k_attn_mma: fp16 2-pass (P single fp16, Wh hi/lo). Single-barrier pipeline.
// D = P @ (B_hi + B_lo); P quantization 2^-12 dominates (≈1e-4 output error).
// ---------------------------------------------------------------------------
#define WHS_RB   528
#define PS_RB    144
#define WHS_HALF 33792
#define WHS_BUF  67584
#define SM_PS    135168
#define PS_BUF   18432
#define SM_ZPART 172032
#define SM_ZFIN  174080
#define SM_ATTN_TOTAL 174592

__device__ __forceinline__ void stage_whs(u32 smb, int bsel,
                                          const __half* bh,
                                          const __half* bl,
                                          int j0, int f0, int tid) {
    u32 base = smb + (u32)bsel * WHS_BUF;
    #pragma unroll
    for (int s = 0; s < 4; s++) {
        int u = tid + 512 * s;
        int row = u >> 5, fo = u & 31;
        cpa16(base + row * WHS_RB + fo * 16,
              bh + (size_t)(j0 + row) * FD + f0 + fo * 8);
    }
    #pragma unroll
    for (int s = 0; s < 4; s++) {
        int u = tid + 512 * s;
        int row = u >> 5, fo = u & 31;
        cpa16(base + WHS_HALF + row * WHS_RB + fo * 16,
              bl + (size_t)(j0 + row) * FD + f0 + fo * 8);
    }
    asm volatile("cp.async.commit_group;" ::: "memory");
}

__device__ __forceinline__ void build_p(char* sm, int bufsel, int it, int qt,
                                        const int4* msk4, int j0,
                                        float w1i, u64 F1pk, u64 Fapk,
                                        const float* tw2g, const float* te1g,
                                        const float* teag, float& zsum) {
    char* base = sm + SM_PS + bufsel * PS_BUF;
    #pragma unroll
    for (int q = 0; q < 2; q++) {
        int j = qt + q * 8;
        int4 a0 = msk4[q * 2], a1 = msk4[q * 2 + 1];
        int msk[8] = {a0.x, a0.y, a0.z, a0.w, a1.x, a1.y, a1.z, a1.w};
        u32 hw[4];
        #pragma unroll
        for (int e2 = 0; e2 < 4; e2++) {
            int jj = j0 + j + e2 * 2;
            float2 w2p = *(const float2*)(tw2g + jj);
            u64 e1u = *(const u64*)(te1g + jj);
            u64 eau = *(const u64*)(teag + jj);
            float2 v1 = u2f2(mul2(F1pk, e1u));
            float2 va = u2f2(mul2(Fapk, eau));
            float p0 = (w1i + w2p.x > 0.f) ? v1.x : va.x;
            float p1 = (w1i + w2p.y > 0.f) ? v1.y : va.y;
            p0 = (msk[e2 * 2] > 0) ? p0 : 0.f;
            p1 = (msk[e2 * 2 + 1] > 0) ? p1 : 0.f;
            zsum += p0 + p1;
            hw[e2] = packhf(p0, p1);
        }
        u32 po = (u32)it * PS_RB + (u32)j * 2;
        *(uint4*)(base + po) = make_uint4(hw[0], hw[1], hw[2], hw[3]);
    }
}

__global__ __launch_bounds__(512, 1) void k_attn_mma(const int* __restrict__ adj,
                                                     float* __restrict__ out) {
    extern __shared__ char sm[];
    const u32 smb = smem_u32(sm);
    const int tid = threadIdx.x;
    const int lane = tid & 31, wid = tid >> 5;
    const int wm = wid & 3, wn = wid >> 2;   // 4 x 4 warp grid
    const int b  = blockIdx.z;
    const int i0 = blockIdx.x * MI;
    const int f0 = blockIdx.y * NF;

    const __half* bhsrc = g_Bhi + (size_t)b * T2 * FD;
    const __half* blsrc = g_Blo + (size_t)b * T2 * FD;
    const float* tw2g = g_w2 + b * T2;
    const float* te1g = g_E1 + b * T2;
    const float* teag = g_Ea + b * T2;

    stage_whs(smb, 0, bhsrc, blsrc, 0, f0, tid);

    const int it = tid >> 2, qt = (tid & 3) * 16;
    const int gi = b * T2 + i0 + it;
    const float w1i = g_w1[gi];
    const u64 F1pk = pk2(g_F1[gi]);
    const u64 Fapk = pk2(g_Fa[gi]);
    float zsum = 0.f;
    const int* adjrow = adj + ((size_t)(b * T2 + i0 + it)) * T2 + qt;

    float acc[2][8][4];
    #pragma unroll
    for (int m = 0; m < 2; m++)
        #pragma unroll
        for (int n = 0; n < 8; n++)
            #pragma unroll
            for (int e = 0; e < 4; e++) acc[m][n][e] = 0.f;

    const u32 a_lane = (u32)(lane & 15) * PS_RB + (u32)(lane >> 4) * 16;
    const u32 b_lane = (u32)(lane & 15) * WHS_RB + (u32)(lane >> 4) * 16;
    const u32 pa_base = smb + SM_PS + (u32)(wm * 32) * PS_RB + a_lane;

    // prologue: build P(0)
    {
        int4 pre[4];
        pre[0] = *(const int4*)(adjrow);
        pre[1] = *(const int4*)(adjrow + 4);
        pre[2] = *(const int4*)(adjrow + 8);
        pre[3] = *(const int4*)(adjrow + 12);
        build_p(sm, 0, it, qt, pre, 0, w1i, F1pk, Fapk, tw2g, te1g, teag, zsum);
    }
    asm volatile("cp.async.wait_group 0;" ::: "memory");
    __syncthreads();

    for (int c = 0; c < NCHUNK; c++) {
        const int j0 = c * KC;
        if (c) __syncthreads();

        int4 pre[4];
        if (c + 1 < NCHUNK) {
            stage_whs(smb, (c + 1) & 1, bhsrc, blsrc, j0 + KC, f0, tid);
            const int* ap = adjrow + j0 + KC;
            pre[0] = *(const int4*)(ap);
            pre[1] = *(const int4*)(ap + 4);
            pre[2] = *(const int4*)(ap + 8);
            pre[3] = *(const int4*)(ap + 12);
        }

        const u32 pa = pa_base + (u32)(c & 1) * PS_BUF;
        const u32 wb_hi = smb + (u32)(c & 1) * WHS_BUF + (u32)(wn * 64) * 2 + b_lane;
        const u32 wb_lo = wb_hi + WHS_HALF;
        #pragma unroll
        for (int kk = 0; kk < 4; kk++) {
            u32 ap_[2][4];
            ldsm_x4(ap_[0], pa + kk * 32);
            ldsm_x4(ap_[1], pa + kk * 32 + 16 * PS_RB);
            #pragma unroll
            for (int nt = 0; nt < 4; nt++) {
                u32 bhv[4], blv[4];
                u32 boff = (u32)kk * 16 * WHS_RB + (u32)nt * 32;
                ldsm_x4t(bhv, wb_hi + boff);
                ldsm_x4t(blv, wb_lo + boff);
                #pragma unroll
                for (int mt = 0; mt < 2; mt++) {
                    mma_f16(acc[mt][2 * nt],     ap_[mt], bhv[0], bhv[1]);
                    mma_f16(acc[mt][2 * nt + 1], ap_[mt], bhv[2], bhv[3]);
                    mma_f16(acc[mt][2 * nt],     ap_[mt], blv[0], blv[1]);
                    mma_f16(acc[mt][2 * nt + 1], ap_[mt], blv[2], blv[3]);
                }
            }
        }

        if (c + 1 < NCHUNK)
            build_p(sm, (c + 1) & 1, it, qt, pre, j0 + KC,
                    w1i, F1pk, Fapk, tw2g, te1g, teag, zsum);

        asm volatile("cp.async.wait_group 0;" ::: "memory");
    }

    // Z reduction: 4 threads per row
    float* zpart = (float*)(sm + SM_ZPART);
    float* zfin  = (float*)(sm + SM_ZFIN);
    __syncthreads();
    zpart[tid] = zsum;
    __syncthreads();
    if (tid < 128)
        zfin[tid] = (zpart[4 * tid] + zpart[4 * tid + 1]) +
                    (zpart[4 * tid + 2] + zpart[4 * tid + 3]);
    __syncthreads();

    // epilogue: normalize, elu, split-write
    #pragma unroll
    for (int mt = 0; mt < 2; mt++) {
        int il = wm * 32 + mt * 16 + (lane >> 2);
        int g1 = i0 + il, g2 = g1 + 8;
        float inv1 = 1.f / zfin[il];
        float inv2 = 1.f / zfin[il + 8];
        size_t base1 = (g1 < TT) ? ((size_t)b * TT + g1) * FD
                                 : ((size_t)BS * TT + (size_t)b * TT + (g1 - TT)) * FD;
        size_t base2 = (g2 < TT) ? ((size_t)b * TT + g2) * FD
                                 : ((size_t)BS * TT + (size_t)b * TT + (g2 - TT)) * FD;
        #pragma unroll
        for (int nt = 0; nt < 8; nt++) {
            int col = f0 + wn * 64 + nt * 8 + (lane & 3) * 2;
            float2 v1, v2;
            float x;
            x = acc[mt][nt][0] * inv1; v1.x = x > 0.f ? x : expm1f(x);
            x = acc[mt][nt][1] * inv1; v1.y = x > 0.f ? x : expm1f(x);
            x = acc[mt][nt][2] * inv2; v2.x = x > 0.f ? x : expm1f(x);
            x = acc[mt][nt][3] * inv2; v2.y = x > 0.f ? x : expm1f(x);
            *(float2*)&out[base1 + col] = v1;
            *(float2*)&out[base2 + col] = v2;
        }
    }
}

// ---------------------------------------------------------------------------
extern "C" void kernel_launch(void* const* d_in, const int* in_sizes, int n_in,
                              void* d_out, int out_size) {
    const float* xa  = (const float*)d_in[0];
    const float* xv  = (const float*)d_in[1];
    const int*   adj = (const int*)d_in[2];
    const float* W   = (const float*)d_in[3];
    const float* a   = (const float*)d_in[4];
    float* out = (float*)d_out;

    cudaFuncSetAttribute(k_wh_mma, cudaFuncAttributeMaxDynamicSharedMemorySize,
                         SW_TOTAL);
    cudaFuncSetAttribute(k_attn_mma, cudaFuncAttributeMaxDynamicSharedMemorySize,
                         SM_ATTN_TOTAL);

    k_u<<<FD / 8, 256>>>(W, a);
    k_w12<<<BS * T2 / 8, 256>>>(xa, xv);
    k_prep<<<BS, 256>>>();
    dim3 gA(FD / 128, T2 / 128, BS);         // 1024 blocks
    k_wh_mma<<<gA, 256, SW_TOTAL>>>(xa, xv, W);
    dim3 gC(T2 / MI, FD / NF, BS);           // 512 blocks x 512 threads
    k_attn_mma<<<gC, 512, SM_ATTN_TOTAL>>>(adj, out);
}

// round 10
// speedup vs baseline: 6.0627x; 1.3313x over previous
#include <cuda_runtime.h>
#include <cuda_fp16.h>
#include <math.h>
#include <stdint.h>

#define BS 16
#define TT 1024
#define T2 2048
#define FD 512
#define ALPHA 0.1f
#define KC 64
#define NCHUNK (T2 / KC)   // 32
#define MI 128
#define NF 256

typedef unsigned long long u64;
typedef unsigned int u32;

// ---------------- device scratch (no cudaMalloc allowed) --------------------
static __device__ __half g_B[(size_t)BS * T2 * FD];   // Wh (fp16), [b][j][f]
static __device__ float g_uvec[2 * FD];    // W@a1, W@a2
static __device__ float g_w1[BS * T2];
static __device__ float g_w2[BS * T2];
static __device__ float g_F1[BS * T2];
static __device__ float g_Fa[BS * T2];
static __device__ float g_E1[BS * T2];
static __device__ float g_Ea[BS * T2];

// ---------------- helpers ----------------------------------------------------
__device__ __forceinline__ u64 pk2(float x) {
    u64 r; asm("mov.b64 %0, {%1, %1};" : "=l"(r) : "f"(x)); return r;
}
__device__ __forceinline__ u64 mul2(u64 a, u64 b) {
    u64 d; asm("mul.rn.f32x2 %0, %1, %2;" : "=l"(d) : "l"(a), "l"(b)); return d;
}
__device__ __forceinline__ float2 u2f2(u64 v) {
    float2 r; asm("mov.b64 {%0, %1}, %2;" : "=f"(r.x), "=f"(r.y) : "l"(v)); return r;
}
// packed f16x2 convert: low16 = f16(lo), high16 = f16(hi)
__device__ __forceinline__ u32 packhf(float lo, float hi) {
    u32 r; asm("cvt.rn.f16x2.f32 %0, %1, %2;" : "=r"(r) : "f"(hi), "f"(lo)); return r;
}
__device__ __forceinline__ float2 unpackhf(u32 p) {
    __half2 h = *reinterpret_cast<__half2*>(&p);
    return __half22float2(h);
}
__device__ __forceinline__ u32 smem_u32(const void* p) {
    u32 a; asm("{ .reg .u64 t; cvta.to.shared.u64 t, %1; cvt.u32.u64 %0, t; }"
               : "=r"(a) : "l"(p));
    return a;
}
__device__ __forceinline__ void ldsm_x4(u32* r, u32 addr) {
    asm volatile("ldmatrix.sync.aligned.m8n8.x4.shared.b16 {%0,%1,%2,%3}, [%4];"
                 : "=r"(r[0]), "=r"(r[1]), "=r"(r[2]), "=r"(r[3]) : "r"(addr));
}
__device__ __forceinline__ void ldsm_x4t(u32* r, u32 addr) {
    asm volatile("ldmatrix.sync.aligned.m8n8.x4.trans.shared.b16 {%0,%1,%2,%3}, [%4];"
                 : "=r"(r[0]), "=r"(r[1]), "=r"(r[2]), "=r"(r[3]) : "r"(addr));
}
__device__ __forceinline__ void mma_f16(float* d, const u32* a, u32 b0, u32 b1) {
    asm volatile(
        "mma.sync.aligned.m16n8k16.row.col.f32.f16.f16.f32 "
        "{%0,%1,%2,%3}, {%4,%5,%6,%7}, {%8,%9}, {%0,%1,%2,%3};"
        : "+f"(d[0]), "+f"(d[1]), "+f"(d[2]), "+f"(d[3])
        : "r"(a[0]), "r"(a[1]), "r"(a[2]), "r"(a[3]), "r"(b0), "r"(b1));
}
__device__ __forceinline__ void cpa16(u32 dst, const void* src) {
    asm volatile("{ .reg .u64 g; cvta.to.global.u64 g, %1; "
                 "cp.async.cg.shared.global [%0], [g], 16; }"
                 :: "r"(dst), "l"(src) : "memory");
}

// ---------------------------------------------------------------------------
// k_u: u1 = W @ a1, u2 = W @ a2. warp per k-row.
// ---------------------------------------------------------------------------
__global__ __launch_bounds__(256) void k_u(const float* __restrict__ W,
                                           const float* __restrict__ avec) {
    int k = blockIdx.x * 8 + (threadIdx.x >> 5);
    int lane = threadIdx.x & 31;
    const float* wr = W + (size_t)k * FD;
    float s1 = 0.f, s2 = 0.f;
    #pragma unroll
    for (int q = 0; q < 4; q++) {
        int f4 = lane + 32 * q;
        float4 w = *(const float4*)&wr[f4 * 4];
        float4 a1 = *(const float4*)&avec[f4 * 4];
        float4 a2 = *(const float4*)&avec[FD + f4 * 4];
        s1 += w.x * a1.x + w.y * a1.y + w.z * a1.z + w.w * a1.w;
        s2 += w.x * a2.x + w.y * a2.y + w.z * a2.z + w.w * a2.w;
    }
    #pragma unroll
    for (int o = 16; o > 0; o >>= 1) {
        s1 += __shfl_xor_sync(0xffffffffu, s1, o);
        s2 += __shfl_xor_sync(0xffffffffu, s2, o);
    }
    if (lane == 0) { g_uvec[k] = s1; g_uvec[FD + k] = s2; }
}

// ---------------------------------------------------------------------------
// k_w12: w1[row] = h_row · u1, w2[row] = h_row · u2  (exact fp32, associativity)
// ---------------------------------------------------------------------------
__global__ __launch_bounds__(256) void k_w12(const float* __restrict__ xa,
                                             const float* __restrict__ xv) {
    int row  = blockIdx.x * 8 + (threadIdx.x >> 5);
    int lane = threadIdx.x & 31;
    int b = row >> 11, r = row & (T2 - 1);
    const float* h = (r < TT) ? xa + ((size_t)b * TT + r) * FD
                              : xv + ((size_t)b * TT + (r - TT)) * FD;
    float s1 = 0.f, s2 = 0.f;
    #pragma unroll
    for (int q = 0; q < 4; q++) {
        int f4 = lane + 32 * q;
        float4 v  = *(const float4*)&h[f4 * 4];
        float4 a1 = *(const float4*)&g_uvec[f4 * 4];
        float4 a2 = *(const float4*)&g_uvec[FD + f4 * 4];
        s1 += v.x * a1.x + v.y * a1.y + v.z * a1.z + v.w * a1.w;
        s2 += v.x * a2.x + v.y * a2.y + v.z * a2.z + v.w * a2.w;
    }
    #pragma unroll
    for (int o = 16; o > 0; o >>= 1) {
        s1 += __shfl_xor_sync(0xffffffffu, s1, o);
        s2 += __shfl_xor_sync(0xffffffffu, s2, o);
    }
    if (lane == 0) { g_w1[row] = s1; g_w2[row] = s2; }
}

// ---------------------------------------------------------------------------
// k_prep: factorized-softmax tables.
// ---------------------------------------------------------------------------
__global__ __launch_bounds__(256) void k_prep() {
    __shared__ float red[256];
    __shared__ float Msh;
    int b = blockIdx.x, tid = threadIdx.x;
    const float* w2 = g_w2 + b * T2;
    float m = -1e30f;
    for (int i = tid; i < T2; i += 256) m = fmaxf(m, w2[i]);
    red[tid] = m; __syncthreads();
    for (int s = 128; s > 0; s >>= 1) {
        if (tid < s) red[tid] = fmaxf(red[tid], red[tid + s]);
        __syncthreads();
    }
    if (tid == 0) Msh = red[0];
    __syncthreads();
    float M = Msh;
    const float* w1 = g_w1 + b * T2;
    for (int i = tid; i < T2; i += 256) {
        float v1 = w1[i], v2 = w2[i];
        float s  = v1 + M;
        float mi = s > 0.f ? s : ALPHA * s;
        g_F1[b * T2 + i] = expf(v1 - mi);
        g_Fa[b * T2 + i] = expf(ALPHA * v1 - mi);
        g_E1[b * T2 + i] = expf(v2);
        g_Ea[b * T2 + i] = expf(ALPHA * v2);
    }
}

// ---------------------------------------------------------------------------
// k_wh_mma: Wh = h @ W, fp16 2-pass: x_hi·W_hi + x_hi·W_lo (~1e-4 RMS).
// Writes single fp16 Wh to g_B [b][j][f].
// ---------------------------------------------------------------------------
#define WA_RB 144
#define WW_RB 272
#define SW_A    0                   // 128*144 = 18432
#define SW_W_HI 18432               // 64*272 = 17408
#define SW_W_LO 35840
#define SW_TOTAL 53248

__global__ __launch_bounds__(256, 2) void k_wh_mma(const float* __restrict__ xa,
                                                   const float* __restrict__ xv,
                                                   const float* __restrict__ W) {
    extern __shared__ char sm[];
    const u32 smb = smem_u32(sm);
    const int tid = threadIdx.x, lane = tid & 31, wid = tid >> 5;
    const int wm = wid & 3, wn = wid >> 2;
    const int b  = blockIdx.z;
    const int r0 = blockIdx.y * 128;
    const int f0 = blockIdx.x * 128;
    const float* __restrict__ h = (r0 < TT)
        ? (xa + ((size_t)b * TT + r0) * FD)
        : (xv + ((size_t)b * TT + (r0 - TT)) * FD);

    float acc[2][8][4];
    #pragma unroll
    for (int m = 0; m < 2; m++)
        #pragma unroll
        for (int n = 0; n < 8; n++)
            #pragma unroll
            for (int e = 0; e < 4; e++) acc[m][n][e] = 0.f;

    const u32 a_lane = (u32)(lane & 15) * WA_RB + (u32)(lane >> 4) * 16;
    const u32 b_lane = (u32)(lane & 15) * WW_RB + (u32)(lane >> 4) * 16;
    const u32 pa = smb + SW_A + (u32)(wm * 32) * WA_RB + a_lane;
    const u32 pb_hi = smb + SW_W_HI + (u32)(wn * 64) * 2 + b_lane;
    const u32 pb_lo = smb + SW_W_LO + (u32)(wn * 64) * 2 + b_lane;

    for (int k0 = 0; k0 < FD; k0 += KC) {
        if (k0) __syncthreads();
        // stage A_hi (h chunk [128 m][64 k], fp16 rounded)
        #pragma unroll
        for (int s = 0; s < 8; s++) {
            int u = tid + 256 * s;
            int row = u >> 4, kq = u & 15;
            float4 v = *(const float4*)(h + (size_t)row * FD + k0 + kq * 4);
            uint2 qh = make_uint2(packhf(v.x, v.y), packhf(v.z, v.w));
            *(uint2*)(sm + SW_A + row * WA_RB + kq * 8) = qh;
        }
        // stage W chunk [64 k][128 f] hi + lo
        #pragma unroll
        for (int s = 0; s < 8; s++) {
            int u = tid + 256 * s;
            int row = u >> 5, fq = u & 31;
            float4 v = *(const float4*)(W + (size_t)(k0 + row) * FD + f0 + fq * 4);
            u32 h01 = packhf(v.x, v.y);
            u32 h23 = packhf(v.z, v.w);
            float2 f01 = unpackhf(h01);
            float2 f23 = unpackhf(h23);
            uint2 qh = make_uint2(h01, h23);
            uint2 ql = make_uint2(packhf(v.x - f01.x, v.y - f01.y),
                                  packhf(v.z - f23.x, v.w - f23.y));
            *(uint2*)(sm + SW_W_HI + row * WW_RB + fq * 8) = qh;
            *(uint2*)(sm + SW_W_LO + row * WW_RB + fq * 8) = ql;
        }
        __syncthreads();
        #pragma unroll
        for (int kk = 0; kk < 4; kk++) {
            u32 ahi[2][4];
            ldsm_x4(ahi[0], pa + kk * 32);
            ldsm_x4(ahi[1], pa + kk * 32 + 16 * WA_RB);
            #pragma unroll
            for (int nt = 0; nt < 4; nt++) {
                u32 bhv[4], blv[4];
                u32 boff = (u32)kk * 16 * WW_RB + (u32)nt * 32;
                ldsm_x4t(bhv, pb_hi + boff);
                ldsm_x4t(blv, pb_lo + boff);
                #pragma unroll
                for (int mt = 0; mt < 2; mt++) {
                    mma_f16(acc[mt][2 * nt],     ahi[mt], bhv[0], bhv[1]);
                    mma_f16(acc[mt][2 * nt + 1], ahi[mt], bhv[2], bhv[3]);
                    mma_f16(acc[mt][2 * nt],     ahi[mt], blv[0], blv[1]);
                    mma_f16(acc[mt][2 * nt + 1], ahi[mt], blv[2], blv[3]);
                }
            }
        }
    }

    // epilogue: round fp32 result to fp16, write [b][j][f]
    #pragma unroll
    for (int mt = 0; mt < 2; mt++) {
        int row1 = r0 + wm * 32 + mt * 16 + (lane >> 2);
        #pragma unroll
        for (int nt2 = 0; nt2 < 8; nt2++) {
            int col = f0 + wn * 64 + nt2 * 8 + (lane & 3) * 2;
            u32 h01 = packhf(acc[mt][nt2][0], acc[mt][nt2][1]);
            u32 h23 = packhf(acc[mt][nt2][2], acc[mt][nt2][3]);
            size_t o1 = ((size_t)b * T2 + row1) * FD + col;
            size_t o2 = o1 + (size_t)8 * FD;
            *(u32*)&g_B[o1] = h01;
            *(u32*)&g_B[o2] = h23;
        }
    }
}

// ---------------------------------------------------------------------------
// k_attn_mma: single-pass fp16 PV (P fp16 x Wh fp16). Single-barrier pipeline.
// ---------------------------------------------------------------------------
#define WHS_RB   528
#define PS_RB    144
#define WHS_BUF  33792
#define SM_PS    67584
#define PS_BUF   18432
#define SM_ZPART 104448
#define SM_ZFIN  106496
#define SM_ATTN_TOTAL 107008

__device__ __forceinline__ void stage_whs(u32 smb, int bsel,
                                          const __half* bh,
                                          int j0, int f0, int tid) {
    u32 base = smb + (u32)bsel * WHS_BUF;
    #pragma unroll
    for (int s = 0; s < 4; s++) {
        int u = tid + 512 * s;
        int row = u >> 5, fo = u & 31;
        cpa16(base + row * WHS_RB + fo * 16,
              bh + (size_t)(j0 + row) * FD + f0 + fo * 8);
    }
    asm volatile("cp.async.commit_group;" ::: "memory");
}

__device__ __forceinline__ void build_p(char* sm, int bufsel, int it, int qt,
                                        const int4* msk4, int j0,
                                        float w1i, u64 F1pk, u64 Fapk,
                                        const float* tw2g, const float* te1g,
                                        const float* teag, float& zsum) {
    char* base = sm + SM_PS + bufsel * PS_BUF;
    #pragma unroll
    for (int q = 0; q < 2; q++) {
        int j = qt + q * 8;
        int4 a0 = msk4[q * 2], a1 = msk4[q * 2 + 1];
        int msk[8] = {a0.x, a0.y, a0.z, a0.w, a1.x, a1.y, a1.z, a1.w};
        u32 hw[4];
        #pragma unroll
        for (int e2 = 0; e2 < 4; e2++) {
            int jj = j0 + j + e2 * 2;
            float2 w2p = *(const float2*)(tw2g + jj);
            u64 e1u = *(const u64*)(te1g + jj);
            u64 eau = *(const u64*)(teag + jj);
            float2 v1 = u2f2(mul2(F1pk, e1u));
            float2 va = u2f2(mul2(Fapk, eau));
            float p0 = (w1i + w2p.x > 0.f) ? v1.x : va.x;
            float p1 = (w1i + w2p.y > 0.f) ? v1.y : va.y;
            p0 = (msk[e2 * 2] > 0) ? p0 : 0.f;
            p1 = (msk[e2 * 2 + 1] > 0) ? p1 : 0.f;
            zsum += p0 + p1;
            hw[e2] = packhf(p0, p1);
        }
        u32 po = (u32)it * PS_RB + (u32)j * 2;
        *(uint4*)(base + po) = make_uint4(hw[0], hw[1], hw[2], hw[3]);
    }
}

__global__ __launch_bounds__(512, 1) void k_attn_mma(const int* __restrict__ adj,
                                                     float* __restrict__ out) {
    extern __shared__ char sm[];
    const u32 smb = smem_u32(sm);
    const int tid = threadIdx.x;
    const int lane = tid & 31, wid = tid >> 5;
    const int wm = wid & 3, wn = wid >> 2;   // 4 x 4 warp grid
    const int b  = blockIdx.z;
    const int i0 = blockIdx.x * MI;
    const int f0 = blockIdx.y * NF;

    const __half* bhsrc = g_B + (size_t)b * T2 * FD;
    const float* tw2g = g_w2 + b * T2;
    const float* te1g = g_E1 + b * T2;
    const float* teag = g_Ea + b * T2;

    stage_whs(smb, 0, bhsrc, 0, f0, tid);

    const int it = tid >> 2, qt = (tid & 3) * 16;
    const int gi = b * T2 + i0 + it;
    const float w1i = g_w1[gi];
    const u64 F1pk = pk2(g_F1[gi]);
    const u64 Fapk = pk2(g_Fa[gi]);
    float zsum = 0.f;
    const int* adjrow = adj + ((size_t)(b * T2 + i0 + it)) * T2 + qt;

    float acc[2][8][4];
    #pragma unroll
    for (int m = 0; m < 2; m++)
        #pragma unroll
        for (int n = 0; n < 8; n++)
            #pragma unroll
            for (int e = 0; e < 4; e++) acc[m][n][e] = 0.f;

    const u32 a_lane = (u32)(lane & 15) * PS_RB + (u32)(lane >> 4) * 16;
    const u32 b_lane = (u32)(lane & 15) * WHS_RB + (u32)(lane >> 4) * 16;
    const u32 pa_base = smb + SM_PS + (u32)(wm * 32) * PS_RB + a_lane;

    // prologue: build P(0)
    {
        int4 pre[4];
        pre[0] = *(const int4*)(adjrow);
        pre[1] = *(const int4*)(adjrow + 4);
        pre[2] = *(const int4*)(adjrow + 8);
        pre[3] = *(const int4*)(adjrow + 12);
        build_p(sm, 0, it, qt, pre, 0, w1i, F1pk, Fapk, tw2g, te1g, teag, zsum);
    }
    asm volatile("cp.async.wait_group 0;" ::: "memory");
    __syncthreads();

    for (int c = 0; c < NCHUNK; c++) {
        const int j0 = c * KC;
        if (c) __syncthreads();

        int4 pre[4];
        if (c + 1 < NCHUNK) {
            stage_whs(smb, (c + 1) & 1, bhsrc, j0 + KC, f0, tid);
            const int* ap = adjrow + j0 + KC;
            pre[0] = *(const int4*)(ap);
            pre[1] = *(const int4*)(ap + 4);
            pre[2] = *(const int4*)(ap + 8);
            pre[3] = *(const int4*)(ap + 12);
        }

        const u32 pa = pa_base + (u32)(c & 1) * PS_BUF;
        const u32 wb = smb + (u32)(c & 1) * WHS_BUF + (u32)(wn * 64) * 2 + b_lane;
        #pragma unroll
        for (int kk = 0; kk < 4; kk++) {
            u32 ap_[2][4];
            ldsm_x4(ap_[0], pa + kk * 32);
            ldsm_x4(ap_[1], pa + kk * 32 + 16 * PS_RB);
            #pragma unroll
            for (int nt = 0; nt < 4; nt++) {
                u32 bhv[4];
                ldsm_x4t(bhv, wb + (u32)kk * 16 * WHS_RB + (u32)nt * 32);
                #pragma unroll
                for (int mt = 0; mt < 2; mt++) {
                    mma_f16(acc[mt][2 * nt],     ap_[mt], bhv[0], bhv[1]);
                    mma_f16(acc[mt][2 * nt + 1], ap_[mt], bhv[2], bhv[3]);
                }
            }
        }

        if (c + 1 < NCHUNK)
            build_p(sm, (c + 1) & 1, it, qt, pre, j0 + KC,
                    w1i, F1pk, Fapk, tw2g, te1g, teag, zsum);

        asm volatile("cp.async.wait_group 0;" ::: "memory");
    }

    // Z reduction: 4 threads per row
    float* zpart = (float*)(sm + SM_ZPART);
    float* zfin  = (float*)(sm + SM_ZFIN);
    __syncthreads();
    zpart[tid] = zsum;
    __syncthreads();
    if (tid < 128)
        zfin[tid] = (zpart[4 * tid] + zpart[4 * tid + 1]) +
                    (zpart[4 * tid + 2] + zpart[4 * tid + 3]);
    __syncthreads();

    // epilogue: normalize, elu, split-write
    #pragma unroll
    for (int mt = 0; mt < 2; mt++) {
        int il = wm * 32 + mt * 16 + (lane >> 2);
        int g1 = i0 + il, g2 = g1 + 8;
        float inv1 = 1.f / zfin[il];
        float inv2 = 1.f / zfin[il + 8];
        size_t base1 = (g1 < TT) ? ((size_t)b * TT + g1) * FD
                                 : ((size_t)BS * TT + (size_t)b * TT + (g1 - TT)) * FD;
        size_t base2 = (g2 < TT) ? ((size_t)b * TT + g2) * FD
                                 : ((size_t)BS * TT + (size_t)b * TT + (g2 - TT)) * FD;
        #pragma unroll
        for (int nt = 0; nt < 8; nt++) {
            int col = f0 + wn * 64 + nt * 8 + (lane & 3) * 2;
            float2 v1, v2;
            float x;
            x = acc[mt][nt][0] * inv1; v1.x = x > 0.f ? x : expm1f(x);
            x = acc[mt][nt][1] * inv1; v1.y = x > 0.f ? x : expm1f(x);
            x = acc[mt][nt][2] * inv2; v2.x = x > 0.f ? x : expm1f(x);
            x = acc[mt][nt][3] * inv2; v2.y = x > 0.f ? x : expm1f(x);
            *(float2*)&out[base1 + col] = v1;
            *(float2*)&out[base2 + col] = v2;
        }
    }
}

// ---------------------------------------------------------------------------
extern "C" void kernel_launch(void* const* d_in, const int* in_sizes, int n_in,
                              void* d_out, int out_size) {
    const float* xa  = (const float*)d_in[0];
    const float* xv  = (const float*)d_in[1];
    const int*   adj = (const int*)d_in[2];
    const float* W   = (const float*)d_in[3];
    const float* a   = (const float*)d_in[4];
    float* out = (float*)d_out;

    cudaFuncSetAttribute(k_wh_mma, cudaFuncAttributeMaxDynamicSharedMemorySize,
                         SW_TOTAL);
    cudaFuncSetAttribute(k_attn_mma, cudaFuncAttributeMaxDynamicSharedMemorySize,
                         SM_ATTN_TOTAL);

    k_u<<<FD / 8, 256>>>(W, a);
    k_w12<<<BS * T2 / 8, 256>>>(xa, xv);
    k_prep<<<BS, 256>>>();
    dim3 gA(FD / 128, T2 / 128, BS);         // 1024 blocks
    k_wh_mma<<<gA, 256, SW_TOTAL>>>(xa, xv, W);
    dim3 gC(T2 / MI, FD / NF, BS);           // 512 blocks x 512 threads
    k_attn_mma<<<gC, 512, SM_ATTN_TOTAL>>>(adj, out);
}

// round 11
// speedup vs baseline: 6.2789x; 1.0357x over previous
#include <cuda_runtime.h>
#include <cuda_fp16.h>
#include <math.h>
#include <stdint.h>

#define BS 16
#define TT 1024
#define T2 2048
#define FD 512
#define ALPHA 0.1f
#define KC 64
#define NCHUNK (T2 / KC)   // 32
#define MI 128
#define NF 128

typedef unsigned long long u64;
typedef unsigned int u32;

// ---------------- device scratch (no cudaMalloc allowed) --------------------
static __device__ __half g_B[(size_t)BS * T2 * FD];   // Wh (fp16), [b][j][f]
static __device__ u32 g_adjm[(size_t)BS * T2 * (T2 / 32)];  // adj bitmask, 8MB
static __device__ float g_uvec[2 * FD];    // W@a1, W@a2
static __device__ float g_w1[BS * T2];
static __device__ float g_w2[BS * T2];
static __device__ float g_F1[BS * T2];
static __device__ float g_Fa[BS * T2];
static __device__ float g_E1[BS * T2];
static __device__ float g_Ea[BS * T2];

// ---------------- helpers ----------------------------------------------------
__device__ __forceinline__ u64 pk2(float x) {
    u64 r; asm("mov.b64 %0, {%1, %1};" : "=l"(r) : "f"(x)); return r;
}
__device__ __forceinline__ u64 mul2(u64 a, u64 b) {
    u64 d; asm("mul.rn.f32x2 %0, %1, %2;" : "=l"(d) : "l"(a), "l"(b)); return d;
}
__device__ __forceinline__ float2 u2f2(u64 v) {
    float2 r; asm("mov.b64 {%0, %1}, %2;" : "=f"(r.x), "=f"(r.y) : "l"(v)); return r;
}
// packed f16x2 convert: low16 = f16(lo), high16 = f16(hi)
__device__ __forceinline__ u32 packhf(float lo, float hi) {
    u32 r; asm("cvt.rn.f16x2.f32 %0, %1, %2;" : "=r"(r) : "f"(hi), "f"(lo)); return r;
}
__device__ __forceinline__ u32 smem_u32(const void* p) {
    u32 a; asm("{ .reg .u64 t; cvta.to.shared.u64 t, %1; cvt.u32.u64 %0, t; }"
               : "=r"(a) : "l"(p));
    return a;
}
__device__ __forceinline__ void ldsm_x4(u32* r, u32 addr) {
    asm volatile("ldmatrix.sync.aligned.m8n8.x4.shared.b16 {%0,%1,%2,%3}, [%4];"
                 : "=r"(r[0]), "=r"(r[1]), "=r"(r[2]), "=r"(r[3]) : "r"(addr));
}
__device__ __forceinline__ void ldsm_x4t(u32* r, u32 addr) {
    asm volatile("ldmatrix.sync.aligned.m8n8.x4.trans.shared.b16 {%0,%1,%2,%3}, [%4];"
                 : "=r"(r[0]), "=r"(r[1]), "=r"(r[2]), "=r"(r[3]) : "r"(addr));
}
__device__ __forceinline__ void mma_f16(float* d, const u32* a, u32 b0, u32 b1) {
    asm volatile(
        "mma.sync.aligned.m16n8k16.row.col.f32.f16.f16.f32 "
        "{%0,%1,%2,%3}, {%4,%5,%6,%7}, {%8,%9}, {%0,%1,%2,%3};"
        : "+f"(d[0]), "+f"(d[1]), "+f"(d[2]), "+f"(d[3])
        : "r"(a[0]), "r"(a[1]), "r"(a[2]), "r"(a[3]), "r"(b0), "r"(b1));
}
__device__ __forceinline__ void cpa16(u32 dst, const void* src) {
    asm volatile("{ .reg .u64 g; cvta.to.global.u64 g, %1; "
                 "cp.async.cg.shared.global [%0], [g], 16; }"
                 :: "r"(dst), "l"(src) : "memory");
}

// ---------------------------------------------------------------------------
// k_pack: adj (int32) -> bitmask. One u32 (32 adj) per thread.
// ---------------------------------------------------------------------------
__global__ __launch_bounds__(256) void k_pack(const int* __restrict__ adj) {
    size_t o = (size_t)blockIdx.x * 256 + threadIdx.x;   // word index
    const int* src = adj + o * 32;
    u32 m = 0;
    #pragma unroll
    for (int q = 0; q < 8; q++) {
        int4 v = *(const int4*)(src + q * 4);
        m |= (v.x > 0 ? 1u : 0u) << (q * 4);
        m |= (v.y > 0 ? 1u : 0u) << (q * 4 + 1);
        m |= (v.z > 0 ? 1u : 0u) << (q * 4 + 2);
        m |= (v.w > 0 ? 1u : 0u) << (q * 4 + 3);
    }
    g_adjm[o] = m;
}

// ---------------------------------------------------------------------------
// k_u: u1 = W @ a1, u2 = W @ a2. warp per k-row.
// ---------------------------------------------------------------------------
__global__ __launch_bounds__(256) void k_u(const float* __restrict__ W,
                                           const float* __restrict__ avec) {
    int k = blockIdx.x * 8 + (threadIdx.x >> 5);
    int lane = threadIdx.x & 31;
    const float* wr = W + (size_t)k * FD;
    float s1 = 0.f, s2 = 0.f;
    #pragma unroll
    for (int q = 0; q < 4; q++) {
        int f4 = lane + 32 * q;
        float4 w = *(const float4*)&wr[f4 * 4];
        float4 a1 = *(const float4*)&avec[f4 * 4];
        float4 a2 = *(const float4*)&avec[FD + f4 * 4];
        s1 += w.x * a1.x + w.y * a1.y + w.z * a1.z + w.w * a1.w;
        s2 += w.x * a2.x + w.y * a2.y + w.z * a2.z + w.w * a2.w;
    }
    #pragma unroll
    for (int o = 16; o > 0; o >>= 1) {
        s1 += __shfl_xor_sync(0xffffffffu, s1, o);
        s2 += __shfl_xor_sync(0xffffffffu, s2, o);
    }
    if (lane == 0) { g_uvec[k] = s1; g_uvec[FD + k] = s2; }
}

// ---------------------------------------------------------------------------
// k_w12: w1[row] = h_row · u1, w2[row] = h_row · u2  (exact fp32, associativity)
// ---------------------------------------------------------------------------
__global__ __launch_bounds__(256) void k_w12(const float* __restrict__ xa,
                                             const float* __restrict__ xv) {
    int row  = blockIdx.x * 8 + (threadIdx.x >> 5);
    int lane = threadIdx.x & 31;
    int b = row >> 11, r = row & (T2 - 1);
    const float* h = (r < TT) ? xa + ((size_t)b * TT + r) * FD
                              : xv + ((size_t)b * TT + (r - TT)) * FD;
    float s1 = 0.f, s2 = 0.f;
    #pragma unroll
    for (int q = 0; q < 4; q++) {
        int f4 = lane + 32 * q;
        float4 v  = *(const float4*)&h[f4 * 4];
        float4 a1 = *(const float4*)&g_uvec[f4 * 4];
        float4 a2 = *(const float4*)&g_uvec[FD + f4 * 4];
        s1 += v.x * a1.x + v.y * a1.y + v.z * a1.z + v.w * a1.w;
        s2 += v.x * a2.x + v.y * a2.y + v.z * a2.z + v.w * a2.w;
    }
    #pragma unroll
    for (int o = 16; o > 0; o >>= 1) {
        s1 += __shfl_xor_sync(0xffffffffu, s1, o);
        s2 += __shfl_xor_sync(0xffffffffu, s2, o);
    }
    if (lane == 0) { g_w1[row] = s1; g_w2[row] = s2; }
}

// ---------------------------------------------------------------------------
// k_prep: factorized-softmax tables.
// ---------------------------------------------------------------------------
__global__ __launch_bounds__(256) void k_prep() {
    __shared__ float red[256];
    __shared__ float Msh;
    int b = blockIdx.x, tid = threadIdx.x;
    const float* w2 = g_w2 + b * T2;
    float m = -1e30f;
    for (int i = tid; i < T2; i += 256) m = fmaxf(m, w2[i]);
    red[tid] = m; __syncthreads();
    for (int s = 128; s > 0; s >>= 1) {
        if (tid < s) red[tid] = fmaxf(red[tid], red[tid + s]);
        __syncthreads();
    }
    if (tid == 0) Msh = red[0];
    __syncthreads();
    float M = Msh;
    const float* w1 = g_w1 + b * T2;
    for (int i = tid; i < T2; i += 256) {
        float v1 = w1[i], v2 = w2[i];
        float s  = v1 + M;
        float mi = s > 0.f ? s : ALPHA * s;
        g_F1[b * T2 + i] = expf(v1 - mi);
        g_Fa[b * T2 + i] = expf(ALPHA * v1 - mi);
        g_E1[b * T2 + i] = expf(v2);
        g_Ea[b * T2 + i] = expf(ALPHA * v2);
    }
}

// ---------------------------------------------------------------------------
// k_wh_mma: Wh = fl16(h) @ fl16(W), single fp16 pass (~1.9e-4 RMS added).
// Writes fp16 Wh to g_B [b][j][f].
// ---------------------------------------------------------------------------
#define WA_RB 144
#define WW_RB 272
#define SW_A 0                      // 128*144 = 18432
#define SW_W 18432                  // 64*272 = 17408
#define SW_TOTAL 35840

__global__ __launch_bounds__(256, 2) void k_wh_mma(const float* __restrict__ xa,
                                                   const float* __restrict__ xv,
                                                   const float* __restrict__ W) {
    extern __shared__ char sm[];
    const u32 smb = smem_u32(sm);
    const int tid = threadIdx.x, lane = tid & 31, wid = tid >> 5;
    const int wm = wid & 3, wn = wid >> 2;
    const int b  = blockIdx.z;
    const int r0 = blockIdx.y * 128;
    const int f0 = blockIdx.x * 128;
    const float* __restrict__ h = (r0 < TT)
        ? (xa + ((size_t)b * TT + r0) * FD)
        : (xv + ((size_t)b * TT + (r0 - TT)) * FD);

    float acc[2][8][4];
    #pragma unroll
    for (int m = 0; m < 2; m++)
        #pragma unroll
        for (int n = 0; n < 8; n++)
            #pragma unroll
            for (int e = 0; e < 4; e++) acc[m][n][e] = 0.f;

    const u32 a_lane = (u32)(lane & 15) * WA_RB + (u32)(lane >> 4) * 16;
    const u32 b_lane = (u32)(lane & 15) * WW_RB + (u32)(lane >> 4) * 16;
    const u32 pa = smb + SW_A + (u32)(wm * 32) * WA_RB + a_lane;
    const u32 pb = smb + SW_W + (u32)(wn * 64) * 2 + b_lane;

    for (int k0 = 0; k0 < FD; k0 += KC) {
        if (k0) __syncthreads();
        #pragma unroll
        for (int s = 0; s < 8; s++) {
            int u = tid + 256 * s;
            int row = u >> 4, kq = u & 15;
            float4 v = *(const float4*)(h + (size_t)row * FD + k0 + kq * 4);
            uint2 qh = make_uint2(packhf(v.x, v.y), packhf(v.z, v.w));
            *(uint2*)(sm + SW_A + row * WA_RB + kq * 8) = qh;
        }
        #pragma unroll
        for (int s = 0; s < 8; s++) {
            int u = tid + 256 * s;
            int row = u >> 5, fq = u & 31;
            float4 v = *(const float4*)(W + (size_t)(k0 + row) * FD + f0 + fq * 4);
            uint2 qh = make_uint2(packhf(v.x, v.y), packhf(v.z, v.w));
            *(uint2*)(sm + SW_W + row * WW_RB + fq * 8) = qh;
        }
        __syncthreads();
        #pragma unroll
        for (int kk = 0; kk < 4; kk++) {
            u32 ahi[2][4];
            ldsm_x4(ahi[0], pa + kk * 32);
            ldsm_x4(ahi[1], pa + kk * 32 + 16 * WA_RB);
            #pragma unroll
            for (int nt = 0; nt < 4; nt++) {
                u32 bhv[4];
                ldsm_x4t(bhv, pb + (u32)kk * 16 * WW_RB + (u32)nt * 32);
                #pragma unroll
                for (int mt = 0; mt < 2; mt++) {
                    mma_f16(acc[mt][2 * nt],     ahi[mt], bhv[0], bhv[1]);
                    mma_f16(acc[mt][2 * nt + 1], ahi[mt], bhv[2], bhv[3]);
                }
            }
        }
    }

    // epilogue: round fp32 result to fp16, write [b][j][f]
    #pragma unroll
    for (int mt = 0; mt < 2; mt++) {
        int row1 = r0 + wm * 32 + mt * 16 + (lane >> 2);
        #pragma unroll
        for (int nt2 = 0; nt2 < 8; nt2++) {
            int col = f0 + wn * 64 + nt2 * 8 + (lane & 3) * 2;
            u32 h01 = packhf(acc[mt][nt2][0], acc[mt][nt2][1]);
            u32 h23 = packhf(acc[mt][nt2][2], acc[mt][nt2][3]);
            size_t o1 = ((size_t)b * T2 + row1) * FD + col;
            size_t o2 = o1 + (size_t)8 * FD;
            *(u32*)&g_B[o1] = h01;
            *(u32*)&g_B[o2] = h23;
        }
    }
}

// ---------------------------------------------------------------------------
// k_attn_mma: 256 thr, 2 CTAs/SM, block tile 128x128, single-barrier pipeline.
// P from bitmask (g_adjm) + factorized-softmax tables.
// ---------------------------------------------------------------------------
#define WHS_RB   272                // 128 f x 2B + 16 pad
#define PS_RB    144                // 64 j x 2B + 16 pad
#define WHS_BUF  17408              // 64 rows x 272
#define SM_PS    34816
#define PS_BUF   18432              // 128 rows x 144
#define SM_ZPART 71680              // 256*4
#define SM_ZFIN  72704              // 128*4
#define SM_ATTN_TOTAL 73216

__device__ __forceinline__ void stage_whs(u32 smb, int bsel,
                                          const __half* bh,
                                          int j0, int f0, int tid) {
    u32 base = smb + (u32)bsel * WHS_BUF;
    #pragma unroll
    for (int s = 0; s < 4; s++) {
        int u = tid + 256 * s;
        int row = u >> 4, fo = u & 15;
        cpa16(base + row * WHS_RB + fo * 16,
              bh + (size_t)(j0 + row) * FD + f0 + fo * 8);
    }
    asm volatile("cp.async.commit_group;" ::: "memory");
}

__device__ __forceinline__ void build_p(char* sm, int bufsel, int it, int qt,
                                        u32 mask, int j0, float w1i,
                                        u64 F1pk, u64 Fapk,
                                        const float* tw2g, const float* te1g,
                                        const float* teag, float& zsum) {
    char* base = sm + SM_PS + bufsel * PS_BUF;
    #pragma unroll
    for (int q = 0; q < 4; q++) {
        int j = qt + q * 8;
        u32 hw[4];
        #pragma unroll
        for (int e2 = 0; e2 < 4; e2++) {
            int jj = j0 + j + e2 * 2;
            float2 w2p = *(const float2*)(tw2g + jj);
            u64 e1u = *(const u64*)(te1g + jj);
            u64 eau = *(const u64*)(teag + jj);
            float2 v1 = u2f2(mul2(F1pk, e1u));
            float2 va = u2f2(mul2(Fapk, eau));
            float p0 = (w1i + w2p.x > 0.f) ? v1.x : va.x;
            float p1 = (w1i + w2p.y > 0.f) ? v1.y : va.y;
            int bi = q * 8 + e2 * 2;
            p0 = ((mask >> bi) & 1u) ? p0 : 0.f;
            p1 = ((mask >> (bi + 1)) & 1u) ? p1 : 0.f;
            zsum += p0 + p1;
            hw[e2] = packhf(p0, p1);
        }
        u32 po = (u32)it * PS_RB + (u32)j * 2;
        *(uint4*)(base + po) = make_uint4(hw[0], hw[1], hw[2], hw[3]);
    }
}

__global__ __launch_bounds__(256, 2) void k_attn_mma(float* __restrict__ out) {
    extern __shared__ char sm[];
    const u32 smb = smem_u32(sm);
    const int tid = threadIdx.x;
    const int lane = tid & 31, wid = tid >> 5;
    const int wm = wid & 3, wn = wid >> 2;   // 4 x 2 warp grid
    const int b  = blockIdx.z;
    const int i0 = blockIdx.x * MI;
    const int f0 = blockIdx.y * NF;

    const __half* bhsrc = g_B + (size_t)b * T2 * FD;
    const float* tw2g = g_w2 + b * T2;
    const float* te1g = g_E1 + b * T2;
    const float* teag = g_Ea + b * T2;

    stage_whs(smb, 0, bhsrc, 0, f0, tid);

    // P-build mapping: thread owns (i = tid>>1, 32 contiguous j per chunk)
    const int it = tid >> 1, qt = (tid & 1) * 32;
    const int gi = b * T2 + i0 + it;
    const float w1i = g_w1[gi];
    const u64 F1pk = pk2(g_F1[gi]);
    const u64 Fapk = pk2(g_Fa[gi]);
    float zsum = 0.f;
    const u32* amrow = g_adjm + ((size_t)(b * T2 + i0 + it)) * (T2 / 32) + (qt >> 5);

    float acc[2][8][4];
    #pragma unroll
    for (int m = 0; m < 2; m++)
        #pragma unroll
        for (int n = 0; n < 8; n++)
            #pragma unroll
            for (int e = 0; e < 4; e++) acc[m][n][e] = 0.f;

    const u32 a_lane = (u32)(lane & 15) * PS_RB + (u32)(lane >> 4) * 16;
    const u32 b_lane = (u32)(lane & 15) * WHS_RB + (u32)(lane >> 4) * 16;
    const u32 pa_base = smb + SM_PS + (u32)(wm * 32) * PS_RB + a_lane;

    // prologue: build P(0) into buffer 0
    build_p(sm, 0, it, qt, amrow[0], 0, w1i, F1pk, Fapk, tw2g, te1g, teag, zsum);
    asm volatile("cp.async.wait_group 0;" ::: "memory");
    __syncthreads();

    for (int c = 0; c < NCHUNK; c++) {
        const int j0 = c * KC;
        if (c) __syncthreads();

        u32 nmask = 0;
        if (c + 1 < NCHUNK) {
            stage_whs(smb, (c + 1) & 1, bhsrc, j0 + KC, f0, tid);
            nmask = amrow[(c + 1) * 2];       // 2 u32 words per 64-j chunk
        }

        const u32 pa = pa_base + (u32)(c & 1) * PS_BUF;
        const u32 wb = smb + (u32)(c & 1) * WHS_BUF + (u32)(wn * 64) * 2 + b_lane;
        #pragma unroll
        for (int kk = 0; kk < 4; kk++) {
            u32 ap_[2][4];
            ldsm_x4(ap_[0], pa + kk * 32);
            ldsm_x4(ap_[1], pa + kk * 32 + 16 * PS_RB);
            #pragma unroll
            for (int nt = 0; nt < 4; nt++) {
                u32 bhv[4];
                ldsm_x4t(bhv, wb + (u32)kk * 16 * WHS_RB + (u32)nt * 32);
                #pragma unroll
                for (int mt = 0; mt < 2; mt++) {
                    mma_f16(acc[mt][2 * nt],     ap_[mt], bhv[0], bhv[1]);
                    mma_f16(acc[mt][2 * nt + 1], ap_[mt], bhv[2], bhv[3]);
                }
            }
        }

        if (c + 1 < NCHUNK)
            build_p(sm, (c + 1) & 1, it, qt, nmask, j0 + KC,
                    w1i, F1pk, Fapk, tw2g, te1g, teag, zsum);

        asm volatile("cp.async.wait_group 0;" ::: "memory");
    }

    // Z reduction: 2 threads per row
    float* zpart = (float*)(sm + SM_ZPART);
    float* zfin  = (float*)(sm + SM_ZFIN);
    __syncthreads();
    zpart[tid] = zsum;
    __syncthreads();
    if (tid < 128) zfin[tid] = zpart[2 * tid] + zpart[2 * tid + 1];
    __syncthreads();

    // epilogue: normalize, elu, split-write
    #pragma unroll
    for (int mt = 0; mt < 2; mt++) {
        int il = wm * 32 + mt * 16 + (lane >> 2);
        int g1 = i0 + il, g2 = g1 + 8;
        float inv1 = 1.f / zfin[il];
        float inv2 = 1.f / zfin[il + 8];
        size_t base1 = (g1 < TT) ? ((size_t)b * TT + g1) * FD
                                 : ((size_t)BS * TT + (size_t)b * TT + (g1 - TT)) * FD;
        size_t base2 = (g2 < TT) ? ((size_t)b * TT + g2) * FD
                                 : ((size_t)BS * TT + (size_t)b * TT + (g2 - TT)) * FD;
        #pragma unroll
        for (int nt = 0; nt < 8; nt++) {
            int col = f0 + wn * 64 + nt * 8 + (lane & 3) * 2;
            float2 v1, v2;
            float x;
            x = acc[mt][nt][0] * inv1; v1.x = x > 0.f ? x : expm1f(x);
            x = acc[mt][nt][1] * inv1; v1.y = x > 0.f ? x : expm1f(x);
            x = acc[mt][nt][2] * inv2; v2.x = x > 0.f ? x : expm1f(x);
            x = acc[mt][nt][3] * inv2; v2.y = x > 0.f ? x : expm1f(x);
            *(float2*)&out[base1 + col] = v1;
            *(float2*)&out[base2 + col] = v2;
        }
    }
}

// ---------------------------------------------------------------------------
extern "C" void kernel_launch(void* const* d_in, const int* in_sizes, int n_in,
                              void* d_out, int out_size) {
    const float* xa  = (const float*)d_in[0];
    const float* xv  = (const float*)d_in[1];
    const int*   adj = (const int*)d_in[2];
    const float* W   = (const float*)d_in[3];
    const float* a   = (const float*)d_in[4];
    float* out = (float*)d_out;

    cudaFuncSetAttribute(k_wh_mma, cudaFuncAttributeMaxDynamicSharedMemorySize,
                         SW_TOTAL);
    cudaFuncSetAttribute(k_attn_mma, cudaFuncAttributeMaxDynamicSharedMemorySize,
                         SM_ATTN_TOTAL);

    k_pack<<<BS * T2 * (T2 / 32) / 256, 256>>>(adj);   // 8192 blocks
    k_u<<<FD / 8, 256>>>(W, a);
    k_w12<<<BS * T2 / 8, 256>>>(xa, xv);
    k_prep<<<BS, 256>>>();
    dim3 gA(FD / 128, T2 / 128, BS);         // 1024 blocks
    k_wh_mma<<<gA, 256, SW_TOTAL>>>(xa, xv, W);
    dim3 gC(T2 / MI, FD / NF, BS);           // 16 x 4 x 16 = 1024 blocks
    k_attn_mma<<<gC, 256, SM_ATTN_TOTAL>>>(out);
}

// round 12
// speedup vs baseline: 6.8760x; 1.0951x over previous
#include <cuda_runtime.h>
#include <cuda_fp16.h>
#include <math.h>
#include <stdint.h>

#define BS 16
#define TT 1024
#define T2 2048
#define FD 512
#define ALPHA 0.1f
#define KC 64
#define NCHUNK (T2 / KC)   // 32
#define MI 128
#define NF 128

typedef unsigned long long u64;
typedef unsigned int u32;

// ---------------- device scratch (no cudaMalloc allowed) --------------------
static __device__ __half g_B[(size_t)BS * T2 * FD];   // Wh (fp16), [b][j][f]
static __device__ u32 g_adjm[(size_t)BS * T2 * (T2 / 32)];  // adj bitmask, 8MB
static __device__ uint4 g_tbl[(size_t)BS * (T2 / 2)];  // {w2h2,E1h2,Eah2,0} per 2j
static __device__ float g_uvec[2 * FD];    // W@a1, W@a2
static __device__ float g_w1[BS * T2];
static __device__ float g_w2[BS * T2];
static __device__ float g_F1[BS * T2];
static __device__ float g_Fa[BS * T2];

// ---------------- helpers ----------------------------------------------------
// packed f16x2 convert: low16 = f16(lo), high16 = f16(hi)
__device__ __forceinline__ u32 packhf(float lo, float hi) {
    u32 r; asm("cvt.rn.f16x2.f32 %0, %1, %2;" : "=r"(r) : "f"(hi), "f"(lo)); return r;
}
__device__ __forceinline__ u32 hadd2u(u32 a, u32 b) {
    u32 d; asm("add.rn.f16x2 %0, %1, %2;" : "=r"(d) : "r"(a), "r"(b)); return d;
}
__device__ __forceinline__ u32 hmul2u(u32 a, u32 b) {
    u32 d; asm("mul.rn.f16x2 %0, %1, %2;" : "=r"(d) : "r"(a), "r"(b)); return d;
}
__device__ __forceinline__ u32 hsetgt2(u32 a, u32 b) {
    u32 d; asm("set.gt.u32.f16x2 %0, %1, %2;" : "=r"(d) : "r"(a), "r"(b)); return d;
}
// (a & c) | (b & ~c)
__device__ __forceinline__ u32 lop3e4(u32 a, u32 b, u32 c) {
    u32 d; asm("lop3.b32 %0, %1, %2, %3, 0xE4;" : "=r"(d) : "r"(a), "r"(b), "r"(c));
    return d;
}
__device__ __forceinline__ u32 smem_u32(const void* p) {
    u32 a; asm("{ .reg .u64 t; cvta.to.shared.u64 t, %1; cvt.u32.u64 %0, t; }"
               : "=r"(a) : "l"(p));
    return a;
}
__device__ __forceinline__ void ldsm_x4(u32* r, u32 addr) {
    asm volatile("ldmatrix.sync.aligned.m8n8.x4.shared.b16 {%0,%1,%2,%3}, [%4];"
                 : "=r"(r[0]), "=r"(r[1]), "=r"(r[2]), "=r"(r[3]) : "r"(addr));
}
__device__ __forceinline__ void ldsm_x4t(u32* r, u32 addr) {
    asm volatile("ldmatrix.sync.aligned.m8n8.x4.trans.shared.b16 {%0,%1,%2,%3}, [%4];"
                 : "=r"(r[0]), "=r"(r[1]), "=r"(r[2]), "=r"(r[3]) : "r"(addr));
}
__device__ __forceinline__ void mma_f16(float* d, const u32* a, u32 b0, u32 b1) {
    asm volatile(
        "mma.sync.aligned.m16n8k16.row.col.f32.f16.f16.f32 "
        "{%0,%1,%2,%3}, {%4,%5,%6,%7}, {%8,%9}, {%0,%1,%2,%3};"
        : "+f"(d[0]), "+f"(d[1]), "+f"(d[2]), "+f"(d[3])
        : "r"(a[0]), "r"(a[1]), "r"(a[2]), "r"(a[3]), "r"(b0), "r"(b1));
}
__device__ __forceinline__ void cpa16(u32 dst, const void* src) {
    asm volatile("{ .reg .u64 g; cvta.to.global.u64 g, %1; "
                 "cp.async.cg.shared.global [%0], [g], 16; }"
                 :: "r"(dst), "l"(src) : "memory");
}

// ---------------------------------------------------------------------------
// k_pack: adj (int32) -> bitmask.
// ---------------------------------------------------------------------------
__global__ __launch_bounds__(256) void k_pack(const int* __restrict__ adj) {
    size_t o = (size_t)blockIdx.x * 256 + threadIdx.x;
    const int* src = adj + o * 32;
    u32 m = 0;
    #pragma unroll
    for (int q = 0; q < 8; q++) {
        int4 v = *(const int4*)(src + q * 4);
        m |= (v.x > 0 ? 1u : 0u) << (q * 4);
        m |= (v.y > 0 ? 1u : 0u) << (q * 4 + 1);
        m |= (v.z > 0 ? 1u : 0u) << (q * 4 + 2);
        m |= (v.w > 0 ? 1u : 0u) << (q * 4 + 3);
    }
    g_adjm[o] = m;
}

// ---------------------------------------------------------------------------
// k_u: u1 = W @ a1, u2 = W @ a2.
// ---------------------------------------------------------------------------
__global__ __launch_bounds__(256) void k_u(const float* __restrict__ W,
                                           const float* __restrict__ avec) {
    int k = blockIdx.x * 8 + (threadIdx.x >> 5);
    int lane = threadIdx.x & 31;
    const float* wr = W + (size_t)k * FD;
    float s1 = 0.f, s2 = 0.f;
    #pragma unroll
    for (int q = 0; q < 4; q++) {
        int f4 = lane + 32 * q;
        float4 w = *(const float4*)&wr[f4 * 4];
        float4 a1 = *(const float4*)&avec[f4 * 4];
        float4 a2 = *(const float4*)&avec[FD + f4 * 4];
        s1 += w.x * a1.x + w.y * a1.y + w.z * a1.z + w.w * a1.w;
        s2 += w.x * a2.x + w.y * a2.y + w.z * a2.z + w.w * a2.w;
    }
    #pragma unroll
    for (int o = 16; o > 0; o >>= 1) {
        s1 += __shfl_xor_sync(0xffffffffu, s1, o);
        s2 += __shfl_xor_sync(0xffffffffu, s2, o);
    }
    if (lane == 0) { g_uvec[k] = s1; g_uvec[FD + k] = s2; }
}

// ---------------------------------------------------------------------------
// k_w12: w1/w2 exact fp32 via associativity.
// ---------------------------------------------------------------------------
__global__ __launch_bounds__(256) void k_w12(const float* __restrict__ xa,
                                             const float* __restrict__ xv) {
    int row  = blockIdx.x * 8 + (threadIdx.x >> 5);
    int lane = threadIdx.x & 31;
    int b = row >> 11, r = row & (T2 - 1);
    const float* h = (r < TT) ? xa + ((size_t)b * TT + r) * FD
                              : xv + ((size_t)b * TT + (r - TT)) * FD;
    float s1 = 0.f, s2 = 0.f;
    #pragma unroll
    for (int q = 0; q < 4; q++) {
        int f4 = lane + 32 * q;
        float4 v  = *(const float4*)&h[f4 * 4];
        float4 a1 = *(const float4*)&g_uvec[f4 * 4];
        float4 a2 = *(const float4*)&g_uvec[FD + f4 * 4];
        s1 += v.x * a1.x + v.y * a1.y + v.z * a1.z + v.w * a1.w;
        s2 += v.x * a2.x + v.y * a2.y + v.z * a2.z + v.w * a2.w;
    }
    #pragma unroll
    for (int o = 16; o > 0; o >>= 1) {
        s1 += __shfl_xor_sync(0xffffffffu, s1, o);
        s2 += __shfl_xor_sync(0xffffffffu, s2, o);
    }
    if (lane == 0) { g_w1[row] = s1; g_w2[row] = s2; }
}

// ---------------------------------------------------------------------------
// k_prep: max-shifted fp16 tables. All values <= 1 (overflow-safe), products
// reproduce p exactly:  p(pos)=F1*E1=exp(w1+w2-mi), p(neg)=Fa*Ea.
// ---------------------------------------------------------------------------
__global__ __launch_bounds__(256) void k_prep() {
    __shared__ float red[256];
    __shared__ float Msh;
    int b = blockIdx.x, tid = threadIdx.x;
    const float* w2 = g_w2 + b * T2;
    float m = -1e30f;
    for (int i = tid; i < T2; i += 256) m = fmaxf(m, w2[i]);
    red[tid] = m; __syncthreads();
    for (int s = 128; s > 0; s >>= 1) {
        if (tid < s) red[tid] = fmaxf(red[tid], red[tid + s]);
        __syncthreads();
    }
    if (tid == 0) Msh = red[0];
    __syncthreads();
    float M = Msh;
    for (int j2 = tid; j2 < T2 / 2; j2 += 256) {
        int j = 2 * j2;
        float w2a = w2[j], w2b = w2[j + 1];
        float e1a = expf(w2a - M), e1b = expf(w2b - M);
        float eaa = expf(ALPHA * (w2a - M)), eab = expf(ALPHA * (w2b - M));
        g_tbl[(size_t)b * (T2 / 2) + j2] =
            make_uint4(packhf(w2a, w2b), packhf(e1a, e1b), packhf(eaa, eab), 0);
    }
    const float* w1 = g_w1 + b * T2;
    for (int i = tid; i < T2; i += 256) {
        float v1 = w1[i];
        float s  = v1 + M;
        float mi = s > 0.f ? s : ALPHA * s;
        g_F1[b * T2 + i] = expf(s - mi);           // exp(w1 + M - mi) <= 1
        g_Fa[b * T2 + i] = expf(ALPHA * s - mi);   // exp(0.1(w1+M) - mi) <= 1
    }
}

// ---------------------------------------------------------------------------
// k_wh_mma: Wh = fl16(h) @ fl16(W), single fp16 pass. (unchanged, validated)
// ---------------------------------------------------------------------------
#define WA_RB 144
#define WW_RB 272
#define SW_A 0
#define SW_W 18432
#define SW_TOTAL 35840

__global__ __launch_bounds__(256, 2) void k_wh_mma(const float* __restrict__ xa,
                                                   const float* __restrict__ xv,
                                                   const float* __restrict__ W) {
    extern __shared__ char sm[];
    const u32 smb = smem_u32(sm);
    const int tid = threadIdx.x, lane = tid & 31, wid = tid >> 5;
    const int wm = wid & 3, wn = wid >> 2;
    const int b  = blockIdx.z;
    const int r0 = blockIdx.y * 128;
    const int f0 = blockIdx.x * 128;
    const float* __restrict__ h = (r0 < TT)
        ? (xa + ((size_t)b * TT + r0) * FD)
        : (xv + ((size_t)b * TT + (r0 - TT)) * FD);

    float acc[2][8][4];
    #pragma unroll
    for (int m = 0; m < 2; m++)
        #pragma unroll
        for (int n = 0; n < 8; n++)
            #pragma unroll
            for (int e = 0; e < 4; e++) acc[m][n][e] = 0.f;

    const u32 a_lane = (u32)(lane & 15) * WA_RB + (u32)(lane >> 4) * 16;
    const u32 b_lane = (u32)(lane & 15) * WW_RB + (u32)(lane >> 4) * 16;
    const u32 pa = smb + SW_A + (u32)(wm * 32) * WA_RB + a_lane;
    const u32 pb = smb + SW_W + (u32)(wn * 64) * 2 + b_lane;

    for (int k0 = 0; k0 < FD; k0 += KC) {
        if (k0) __syncthreads();
        #pragma unroll
        for (int s = 0; s < 8; s++) {
            int u = tid + 256 * s;
            int row = u >> 4, kq = u & 15;
            float4 v = *(const float4*)(h + (size_t)row * FD + k0 + kq * 4);
            uint2 qh = make_uint2(packhf(v.x, v.y), packhf(v.z, v.w));
            *(uint2*)(sm + SW_A + row * WA_RB + kq * 8) = qh;
        }
        #pragma unroll
        for (int s = 0; s < 8; s++) {
            int u = tid + 256 * s;
            int row = u >> 5, fq = u & 31;
            float4 v = *(const float4*)(W + (size_t)(k0 + row) * FD + f0 + fq * 4);
            uint2 qh = make_uint2(packhf(v.x, v.y), packhf(v.z, v.w));
            *(uint2*)(sm + SW_W + row * WW_RB + fq * 8) = qh;
        }
        __syncthreads();
        #pragma unroll
        for (int kk = 0; kk < 4; kk++) {
            u32 ahi[2][4];
            ldsm_x4(ahi[0], pa + kk * 32);
            ldsm_x4(ahi[1], pa + kk * 32 + 16 * WA_RB);
            #pragma unroll
            for (int nt = 0; nt < 4; nt++) {
                u32 bhv[4];
                ldsm_x4t(bhv, pb + (u32)kk * 16 * WW_RB + (u32)nt * 32);
                #pragma unroll
                for (int mt = 0; mt < 2; mt++) {
                    mma_f16(acc[mt][2 * nt],     ahi[mt], bhv[0], bhv[1]);
                    mma_f16(acc[mt][2 * nt + 1], ahi[mt], bhv[2], bhv[3]);
                }
            }
        }
    }

    #pragma unroll
    for (int mt = 0; mt < 2; mt++) {
        int row1 = r0 + wm * 32 + mt * 16 + (lane >> 2);
        #pragma unroll
        for (int nt2 = 0; nt2 < 8; nt2++) {
            int col = f0 + wn * 64 + nt2 * 8 + (lane & 3) * 2;
            u32 h01 = packhf(acc[mt][nt2][0], acc[mt][nt2][1]);
            u32 h23 = packhf(acc[mt][nt2][2], acc[mt][nt2][3]);
            size_t o1 = ((size_t)b * T2 + row1) * FD + col;
            size_t o2 = o1 + (size_t)8 * FD;
            *(u32*)&g_B[o1] = h01;
            *(u32*)&g_B[o2] = h23;
        }
    }
}

// ---------------------------------------------------------------------------
// k_attn_mma: 256 thr, 2 CTAs/SM, 128x128 tile, 3-deep cp.async pipeline,
// fp16-packed P-build, Z computed by MMA against constant ones fragment.
// ---------------------------------------------------------------------------
#define WHS_RB   272                // 128 f x 2B + 16 pad
#define PS_RB    144                // 64 j x 2B + 16 pad
#define WHS_BUF  17408              // 64 rows x 272
#define SM_PS    52224              // 3 * WHS_BUF
#define PS_BUF   18432              // 128 rows x 144
#define SM_ATTN_TOTAL 89088         // SM_PS + 2*PS_BUF
#define ONESF 0x3C003C00u

__device__ __forceinline__ void stage_whs(u32 smb, int bsel,
                                          const __half* bh,
                                          int j0, int f0, int tid) {
    u32 base = smb + (u32)bsel * WHS_BUF;
    #pragma unroll
    for (int s = 0; s < 4; s++) {
        int u = tid + 256 * s;
        int row = u >> 4, fo = u & 15;
        cpa16(base + row * WHS_RB + fo * 16,
              bh + (size_t)(j0 + row) * FD + f0 + fo * 8);
    }
    asm volatile("cp.async.commit_group;" ::: "memory");
}

__device__ __forceinline__ void build_p(char* sm, int bufsel, int it, int qt,
                                        u32 mask, const uint4* tblrow,
                                        u32 w1h2, u32 F1h2, u32 Fah2) {
    char* base = sm + SM_PS + bufsel * PS_BUF;
    #pragma unroll
    for (int q = 0; q < 4; q++) {
        u32 hw[4];
        #pragma unroll
        for (int e2 = 0; e2 < 4; e2++) {
            int pj = q * 4 + e2;
            uint4 t = tblrow[pj];
            u32 s = hadd2u(w1h2, t.x);
            u32 m = hsetgt2(s, 0u);
            u32 e = lop3e4(t.y, t.z, m);
            u32 f = lop3e4(F1h2, Fah2, m);
            u32 p = hmul2u(f, e);
            int bi = pj * 2;
            u32 am = (((mask >> bi) & 1u) * 0xFFFFu)
                   | (((mask >> (bi + 1)) & 1u) * 0xFFFF0000u);
            hw[e2] = p & am;
        }
        u32 po = (u32)it * PS_RB + (u32)(qt + q * 8) * 2;
        *(uint4*)(base + po) = make_uint4(hw[0], hw[1], hw[2], hw[3]);
    }
}

__global__ __launch_bounds__(256, 2) void k_attn_mma(float* __restrict__ out) {
    extern __shared__ char sm[];
    const u32 smb = smem_u32(sm);
    const int tid = threadIdx.x;
    const int lane = tid & 31, wid = tid >> 5;
    const int wm = wid & 3, wn = wid >> 2;   // 4 x 2 warp grid
    const int b  = blockIdx.z;
    const int i0 = blockIdx.x * MI;
    const int f0 = blockIdx.y * NF;

    const __half* bhsrc = g_B + (size_t)b * T2 * FD;

    stage_whs(smb, 0, bhsrc, 0, f0, tid);
    stage_whs(smb, 1, bhsrc, KC, f0, tid);

    // P-build mapping: thread owns (i = tid>>1, 32 contiguous j per chunk)
    const int it = tid >> 1, qt = (tid & 1) * 32;
    const int gi = b * T2 + i0 + it;
    const float w1f = g_w1[gi];
    const u32 w1h2 = packhf(w1f, w1f);
    const float f1f = g_F1[gi], faf = g_Fa[gi];
    const u32 F1h2 = packhf(f1f, f1f);
    const u32 Fah2 = packhf(faf, faf);
    const u32* amrow = g_adjm + ((size_t)(b * T2 + i0 + it)) * (T2 / 32) + (qt >> 5);
    const uint4* tblb = g_tbl + (size_t)b * (T2 / 2) + (qt >> 1);

    float acc[2][8][4];
    #pragma unroll
    for (int m = 0; m < 2; m++)
        #pragma unroll
        for (int n = 0; n < 8; n++)
            #pragma unroll
            for (int e = 0; e < 4; e++) acc[m][n][e] = 0.f;
    float zacc[2][4];
    #pragma unroll
    for (int m = 0; m < 2; m++)
        #pragma unroll
        for (int e = 0; e < 4; e++) zacc[m][e] = 0.f;

    const u32 a_lane = (u32)(lane & 15) * PS_RB + (u32)(lane >> 4) * 16;
    const u32 b_lane = (u32)(lane & 15) * WHS_RB + (u32)(lane >> 4) * 16;
    const u32 pa_base = smb + SM_PS + (u32)(wm * 32) * PS_RB + a_lane;

    // prologue: build P(0)
    build_p(sm, 0, it, qt, amrow[0], tblb, w1h2, F1h2, Fah2);
    asm volatile("cp.async.wait_group 1;" ::: "memory");
    __syncthreads();

    for (int c = 0; c < NCHUNK; c++) {
        u32 nmask = 0;
        if (c + 2 < NCHUNK)
            stage_whs(smb, (c + 2) % 3, bhsrc, (c + 2) * KC, f0, tid);
        if (c + 1 < NCHUNK)
            nmask = amrow[(c + 1) * 2];

        const u32 pa = pa_base + (u32)(c & 1) * PS_BUF;
        const u32 wb = smb + (u32)(c % 3) * WHS_BUF + (u32)(wn * 64) * 2 + b_lane;
        #pragma unroll
        for (int kk = 0; kk < 4; kk++) {
            u32 ap_[2][4];
            ldsm_x4(ap_[0], pa + kk * 32);
            ldsm_x4(ap_[1], pa + kk * 32 + 16 * PS_RB);
            mma_f16(zacc[0], ap_[0], ONESF, ONESF);
            mma_f16(zacc[1], ap_[1], ONESF, ONESF);
            #pragma unroll
            for (int nt = 0; nt < 4; nt++) {
                u32 bhv[4];
                ldsm_x4t(bhv, wb + (u32)kk * 16 * WHS_RB + (u32)nt * 32);
                #pragma unroll
                for (int mt = 0; mt < 2; mt++) {
                    mma_f16(acc[mt][2 * nt],     ap_[mt], bhv[0], bhv[1]);
                    mma_f16(acc[mt][2 * nt + 1], ap_[mt], bhv[2], bhv[3]);
                }
            }
        }

        if (c + 1 < NCHUNK)
            build_p(sm, (c + 1) & 1, it, qt, nmask,
                    tblb + (c + 1) * 32, w1h2, F1h2, Fah2);

        if (c + 2 < NCHUNK)
            asm volatile("cp.async.wait_group 1;" ::: "memory");
        else
            asm volatile("cp.async.wait_group 0;" ::: "memory");
        __syncthreads();
    }

    // epilogue: Z sits in zacc (cols identical), normalize, elu, split-write
    #pragma unroll
    for (int mt = 0; mt < 2; mt++) {
        int il = wm * 32 + mt * 16 + (lane >> 2);
        int g1 = i0 + il, g2 = g1 + 8;
        float inv1 = 1.f / zacc[mt][0];
        float inv2 = 1.f / zacc[mt][2];
        size_t base1 = (g1 < TT) ? ((size_t)b * TT + g1) * FD
                                 : ((size_t)BS * TT + (size_t)b * TT + (g1 - TT)) * FD;
        size_t base2 = (g2 < TT) ? ((size_t)b * TT + g2) * FD
                                 : ((size_t)BS * TT + (size_t)b * TT + (g2 - TT)) * FD;
        #pragma unroll
        for (int nt = 0; nt < 8; nt++) {
            int col = f0 + wn * 64 + nt * 8 + (lane & 3) * 2;
            float2 v1, v2;
            float x;
            x = acc[mt][nt][0] * inv1; v1.x = x > 0.f ? x : expm1f(x);
            x = acc[mt][nt][1] * inv1; v1.y = x > 0.f ? x : expm1f(x);
            x = acc[mt][nt][2] * inv2; v2.x = x > 0.f ? x : expm1f(x);
            x = acc[mt][nt][3] * inv2; v2.y = x > 0.f ? x : expm1f(x);
            *(float2*)&out[base1 + col] = v1;
            *(float2*)&out[base2 + col] = v2;
        }
    }
}

// ---------------------------------------------------------------------------
extern "C" void kernel_launch(void* const* d_in, const int* in_sizes, int n_in,
                              void* d_out, int out_size) {
    const float* xa  = (const float*)d_in[0];
    const float* xv  = (const float*)d_in[1];
    const int*   adj = (const int*)d_in[2];
    const float* W   = (const float*)d_in[3];
    const float* a   = (const float*)d_in[4];
    float* out = (float*)d_out;

    cudaFuncSetAttribute(k_wh_mma, cudaFuncAttributeMaxDynamicSharedMemorySize,
                         SW_TOTAL);
    cudaFuncSetAttribute(k_attn_mma, cudaFuncAttributeMaxDynamicSharedMemorySize,
                         SM_ATTN_TOTAL);

    k_pack<<<BS * T2 * (T2 / 32) / 256, 256>>>(adj);
    k_u<<<FD / 8, 256>>>(W, a);
    k_w12<<<BS * T2 / 8, 256>>>(xa, xv);
    k_prep<<<BS, 256>>>();
    dim3 gA(FD / 128, T2 / 128, BS);
    k_wh_mma<<<gA, 256, SW_TOTAL>>>(xa, xv, W);
    dim3 gC(T2 / MI, FD / NF, BS);           // 16 x 4 x 16 = 1024 blocks
    k_attn_mma<<<gC, 256, SM_ATTN_TOTAL>>>(out);
}

// round 13
// speedup vs baseline: 7.5565x; 1.0990x over previous
#include <cuda_runtime.h>
#include <cuda_fp16.h>
#include <math.h>
#include <stdint.h>

#define BS 16
#define TT 1024
#define T2 2048
#define FD 512
#define ALPHA 0.1f
#define KC 64
#define NCHUNK (T2 / KC)   // 32
#define MI 128
#define NF 128

typedef unsigned long long u64;
typedef unsigned int u32;

// ---------------- device scratch (no cudaMalloc allowed) --------------------
static __device__ __half g_B[(size_t)BS * T2 * FD];        // Wh fp16 [b][j][f]
static __device__ __half g_P[(size_t)BS * T2 * T2];        // P fp16 [b][i][j], 128MB
static __device__ float g_Z[BS * T2];                      // softmax denominators
static __device__ u32 g_adjm[(size_t)BS * T2 * (T2 / 32)]; // adj bitmask
static __device__ uint4 g_tbl[(size_t)BS * (T2 / 2)];      // {w2h2,E1h2,Eah2,0}/2j
static __device__ float g_uvec[2 * FD];
static __device__ float g_w1[BS * T2];
static __device__ float g_w2[BS * T2];
static __device__ float g_F1[BS * T2];
static __device__ float g_Fa[BS * T2];

// ---------------- helpers ----------------------------------------------------
__device__ __forceinline__ u32 packhf(float lo, float hi) {
    u32 r; asm("cvt.rn.f16x2.f32 %0, %1, %2;" : "=r"(r) : "f"(hi), "f"(lo)); return r;
}
__device__ __forceinline__ u32 hadd2u(u32 a, u32 b) {
    u32 d; asm("add.rn.f16x2 %0, %1, %2;" : "=r"(d) : "r"(a), "r"(b)); return d;
}
__device__ __forceinline__ u32 hmul2u(u32 a, u32 b) {
    u32 d; asm("mul.rn.f16x2 %0, %1, %2;" : "=r"(d) : "r"(a), "r"(b)); return d;
}
__device__ __forceinline__ u32 hsetgt2(u32 a, u32 b) {
    u32 d; asm("set.gt.u32.f16x2 %0, %1, %2;" : "=r"(d) : "r"(a), "r"(b)); return d;
}
// (a & c) | (b & ~c)
__device__ __forceinline__ u32 lop3e4(u32 a, u32 b, u32 c) {
    u32 d; asm("lop3.b32 %0, %1, %2, %3, 0xE4;" : "=r"(d) : "r"(a), "r"(b), "r"(c));
    return d;
}
__device__ __forceinline__ u32 smem_u32(const void* p) {
    u32 a; asm("{ .reg .u64 t; cvta.to.shared.u64 t, %1; cvt.u32.u64 %0, t; }"
               : "=r"(a) : "l"(p));
    return a;
}
__device__ __forceinline__ void ldsm_x4(u32* r, u32 addr) {
    asm volatile("ldmatrix.sync.aligned.m8n8.x4.shared.b16 {%0,%1,%2,%3}, [%4];"
                 : "=r"(r[0]), "=r"(r[1]), "=r"(r[2]), "=r"(r[3]) : "r"(addr));
}
__device__ __forceinline__ void ldsm_x4t(u32* r, u32 addr) {
    asm volatile("ldmatrix.sync.aligned.m8n8.x4.trans.shared.b16 {%0,%1,%2,%3}, [%4];"
                 : "=r"(r[0]), "=r"(r[1]), "=r"(r[2]), "=r"(r[3]) : "r"(addr));
}
__device__ __forceinline__ void mma_f16(float* d, const u32* a, u32 b0, u32 b1) {
    asm volatile(
        "mma.sync.aligned.m16n8k16.row.col.f32.f16.f16.f32 "
        "{%0,%1,%2,%3}, {%4,%5,%6,%7}, {%8,%9}, {%0,%1,%2,%3};"
        : "+f"(d[0]), "+f"(d[1]), "+f"(d[2]), "+f"(d[3])
        : "r"(a[0]), "r"(a[1]), "r"(a[2]), "r"(a[3]), "r"(b0), "r"(b1));
}
__device__ __forceinline__ void cpa16(u32 dst, const void* src) {
    asm volatile("{ .reg .u64 g; cvta.to.global.u64 g, %1; "
                 "cp.async.cg.shared.global [%0], [g], 16; }"
                 :: "r"(dst), "l"(src) : "memory");
}

// ---------------------------------------------------------------------------
// k_pack: adj (int32) -> bitmask.
// ---------------------------------------------------------------------------
__global__ __launch_bounds__(256) void k_pack(const int* __restrict__ adj) {
    size_t o = (size_t)blockIdx.x * 256 + threadIdx.x;
    const int* src = adj + o * 32;
    u32 m = 0;
    #pragma unroll
    for (int q = 0; q < 8; q++) {
        int4 v = *(const int4*)(src + q * 4);
        m |= (v.x > 0 ? 1u : 0u) << (q * 4);
        m |= (v.y > 0 ? 1u : 0u) << (q * 4 + 1);
        m |= (v.z > 0 ? 1u : 0u) << (q * 4 + 2);
        m |= (v.w > 0 ? 1u : 0u) << (q * 4 + 3);
    }
    g_adjm[o] = m;
}

// ---------------------------------------------------------------------------
// k_u: u1 = W @ a1, u2 = W @ a2.
// ---------------------------------------------------------------------------
__global__ __launch_bounds__(256) void k_u(const float* __restrict__ W,
                                           const float* __restrict__ avec) {
    int k = blockIdx.x * 8 + (threadIdx.x >> 5);
    int lane = threadIdx.x & 31;
    const float* wr = W + (size_t)k * FD;
    float s1 = 0.f, s2 = 0.f;
    #pragma unroll
    for (int q = 0; q < 4; q++) {
        int f4 = lane + 32 * q;
        float4 w = *(const float4*)&wr[f4 * 4];
        float4 a1 = *(const float4*)&avec[f4 * 4];
        float4 a2 = *(const float4*)&avec[FD + f4 * 4];
        s1 += w.x * a1.x + w.y * a1.y + w.z * a1.z + w.w * a1.w;
        s2 += w.x * a2.x + w.y * a2.y + w.z * a2.z + w.w * a2.w;
    }
    #pragma unroll
    for (int o = 16; o > 0; o >>= 1) {
        s1 += __shfl_xor_sync(0xffffffffu, s1, o);
        s2 += __shfl_xor_sync(0xffffffffu, s2, o);
    }
    if (lane == 0) { g_uvec[k] = s1; g_uvec[FD + k] = s2; }
}

// ---------------------------------------------------------------------------
// k_w12: w1/w2 exact fp32 via associativity.
// ---------------------------------------------------------------------------
__global__ __launch_bounds__(256) void k_w12(const float* __restrict__ xa,
                                             const float* __restrict__ xv) {
    int row  = blockIdx.x * 8 + (threadIdx.x >> 5);
    int lane = threadIdx.x & 31;
    int b = row >> 11, r = row & (T2 - 1);
    const float* h = (r < TT) ? xa + ((size_t)b * TT + r) * FD
                              : xv + ((size_t)b * TT + (r - TT)) * FD;
    float s1 = 0.f, s2 = 0.f;
    #pragma unroll
    for (int q = 0; q < 4; q++) {
        int f4 = lane + 32 * q;
        float4 v  = *(const float4*)&h[f4 * 4];
        float4 a1 = *(const float4*)&g_uvec[f4 * 4];
        float4 a2 = *(const float4*)&g_uvec[FD + f4 * 4];
        s1 += v.x * a1.x + v.y * a1.y + v.z * a1.z + v.w * a1.w;
        s2 += v.x * a2.x + v.y * a2.y + v.z * a2.z + v.w * a2.w;
    }
    #pragma unroll
    for (int o = 16; o > 0; o >>= 1) {
        s1 += __shfl_xor_sync(0xffffffffu, s1, o);
        s2 += __shfl_xor_sync(0xffffffffu, s2, o);
    }
    if (lane == 0) { g_w1[row] = s1; g_w2[row] = s2; }
}

// ---------------------------------------------------------------------------
// k_prep: max-shifted fp16 tables (all values <= 1, overflow-safe).
// ---------------------------------------------------------------------------
__global__ __launch_bounds__(256) void k_prep() {
    __shared__ float red[256];
    __shared__ float Msh;
    int b = blockIdx.x, tid = threadIdx.x;
    const float* w2 = g_w2 + b * T2;
    float m = -1e30f;
    for (int i = tid; i < T2; i += 256) m = fmaxf(m, w2[i]);
    red[tid] = m; __syncthreads();
    for (int s = 128; s > 0; s >>= 1) {
        if (tid < s) red[tid] = fmaxf(red[tid], red[tid + s]);
        __syncthreads();
    }
    if (tid == 0) Msh = red[0];
    __syncthreads();
    float M = Msh;
    for (int j2 = tid; j2 < T2 / 2; j2 += 256) {
        int j = 2 * j2;
        float w2a = w2[j], w2b = w2[j + 1];
        float e1a = expf(w2a - M), e1b = expf(w2b - M);
        float eaa = expf(ALPHA * (w2a - M)), eab = expf(ALPHA * (w2b - M));
        g_tbl[(size_t)b * (T2 / 2) + j2] =
            make_uint4(packhf(w2a, w2b), packhf(e1a, e1b), packhf(eaa, eab), 0);
    }
    const float* w1 = g_w1 + b * T2;
    for (int i = tid; i < T2; i += 256) {
        float v1 = w1[i];
        float s  = v1 + M;
        float mi = s > 0.f ? s : ALPHA * s;
        g_F1[b * T2 + i] = expf(s - mi);
        g_Fa[b * T2 + i] = expf(ALPHA * s - mi);
    }
}

// ---------------------------------------------------------------------------
// k_p: materialize P fp16 [b][i][j] + exact fp32 row sums Z. Block = one row.
// ---------------------------------------------------------------------------
__global__ __launch_bounds__(256) void k_p() {
    __shared__ float red[8];
    const int row = blockIdx.x;          // b*T2 + i
    const int b = row >> 11;
    const int t = threadIdx.x;
    const int lane = t & 31, wid = t >> 5;

    const float w1f = g_w1[row];
    const float f1f = g_F1[row], faf = g_Fa[row];
    const u32 w1h2 = packhf(w1f, w1f);
    const u32 F1h2 = packhf(f1f, f1f);
    const u32 Fah2 = packhf(faf, faf);

    u32 mw = g_adjm[(size_t)row * (T2 / 32) + (t >> 2)];
    u32 mbits = (mw >> ((t & 3) * 8)) & 0xFFu;
    const uint4* tb = g_tbl + (size_t)b * (T2 / 2) + t * 4;

    u32 hw[4];
    float zs = 0.f;
    #pragma unroll
    for (int e2 = 0; e2 < 4; e2++) {
        uint4 tt = tb[e2];
        u32 s = hadd2u(w1h2, tt.x);
        u32 m = hsetgt2(s, 0u);
        u32 e = lop3e4(tt.y, tt.z, m);
        u32 f = lop3e4(F1h2, Fah2, m);
        u32 p = hmul2u(f, e);
        u32 am = (((mbits >> (e2 * 2)) & 1u) * 0xFFFFu)
               | (((mbits >> (e2 * 2 + 1)) & 1u) * 0xFFFF0000u);
        p &= am;
        hw[e2] = p;
        float2 pf = __half22float2(*reinterpret_cast<__half2*>(&p));
        zs += pf.x + pf.y;
    }
    *(uint4*)&g_P[(size_t)row * T2 + t * 8] = make_uint4(hw[0], hw[1], hw[2], hw[3]);

    #pragma unroll
    for (int o = 16; o > 0; o >>= 1) zs += __shfl_xor_sync(0xffffffffu, zs, o);
    if (lane == 0) red[wid] = zs;
    __syncthreads();
    if (t == 0) {
        float z = 0.f;
        #pragma unroll
        for (int w = 0; w < 8; w++) z += red[w];
        g_Z[row] = z;
    }
}

// ---------------------------------------------------------------------------
// k_wh_mma: Wh = fl16(h) @ fl16(W), single fp16 pass. (validated)
// ---------------------------------------------------------------------------
#define WA_RB 144
#define WW_RB 272
#define SW_A 0
#define SW_W 18432
#define SW_TOTAL 35840

__global__ __launch_bounds__(256, 2) void k_wh_mma(const float* __restrict__ xa,
                                                   const float* __restrict__ xv,
                                                   const float* __restrict__ W) {
    extern __shared__ char sm[];
    const u32 smb = smem_u32(sm);
    const int tid = threadIdx.x, lane = tid & 31, wid = tid >> 5;
    const int wm = wid & 3, wn = wid >> 2;
    const int b  = blockIdx.z;
    const int r0 = blockIdx.y * 128;
    const int f0 = blockIdx.x * 128;
    const float* __restrict__ h = (r0 < TT)
        ? (xa + ((size_t)b * TT + r0) * FD)
        : (xv + ((size_t)b * TT + (r0 - TT)) * FD);

    float acc[2][8][4];
    #pragma unroll
    for (int m = 0; m < 2; m++)
        #pragma unroll
        for (int n = 0; n < 8; n++)
            #pragma unroll
            for (int e = 0; e < 4; e++) acc[m][n][e] = 0.f;

    const u32 a_lane = (u32)(lane & 15) * WA_RB + (u32)(lane >> 4) * 16;
    const u32 b_lane = (u32)(lane & 15) * WW_RB + (u32)(lane >> 4) * 16;
    const u32 pa = smb + SW_A + (u32)(wm * 32) * WA_RB + a_lane;
    const u32 pb = smb + SW_W + (u32)(wn * 64) * 2 + b_lane;

    for (int k0 = 0; k0 < FD; k0 += KC) {
        if (k0) __syncthreads();
        #pragma unroll
        for (int s = 0; s < 8; s++) {
            int u = tid + 256 * s;
            int row = u >> 4, kq = u & 15;
            float4 v = *(const float4*)(h + (size_t)row * FD + k0 + kq * 4);
            uint2 qh = make_uint2(packhf(v.x, v.y), packhf(v.z, v.w));
            *(uint2*)(sm + SW_A + row * WA_RB + kq * 8) = qh;
        }
        #pragma unroll
        for (int s = 0; s < 8; s++) {
            int u = tid + 256 * s;
            int row = u >> 5, fq = u & 31;
            float4 v = *(const float4*)(W + (size_t)(k0 + row) * FD + f0 + fq * 4);
            uint2 qh = make_uint2(packhf(v.x, v.y), packhf(v.z, v.w));
            *(uint2*)(sm + SW_W + row * WW_RB + fq * 8) = qh;
        }
        __syncthreads();
        #pragma unroll
        for (int kk = 0; kk < 4; kk++) {
            u32 ahi[2][4];
            ldsm_x4(ahi[0], pa + kk * 32);
            ldsm_x4(ahi[1], pa + kk * 32 + 16 * WA_RB);
            #pragma unroll
            for (int nt = 0; nt < 4; nt++) {
                u32 bhv[4];
                ldsm_x4t(bhv, pb + (u32)kk * 16 * WW_RB + (u32)nt * 32);
                #pragma unroll
                for (int mt = 0; mt < 2; mt++) {
                    mma_f16(acc[mt][2 * nt],     ahi[mt], bhv[0], bhv[1]);
                    mma_f16(acc[mt][2 * nt + 1], ahi[mt], bhv[2], bhv[3]);
                }
            }
        }
    }

    #pragma unroll
    for (int mt = 0; mt < 2; mt++) {
        int row1 = r0 + wm * 32 + mt * 16 + (lane >> 2);
        #pragma unroll
        for (int nt2 = 0; nt2 < 8; nt2++) {
            int col = f0 + wn * 64 + nt2 * 8 + (lane & 3) * 2;
            u32 h01 = packhf(acc[mt][nt2][0], acc[mt][nt2][1]);
            u32 h23 = packhf(acc[mt][nt2][2], acc[mt][nt2][3]);
            size_t o1 = ((size_t)b * T2 + row1) * FD + col;
            size_t o2 = o1 + (size_t)8 * FD;
            *(u32*)&g_B[o1] = h01;
            *(u32*)&g_B[o2] = h23;
        }
    }
}

// ---------------------------------------------------------------------------
// k_attn_mma: pure staged GEMM. C[128i x 128f] = P[i, 2048] @ Wh[2048, f].
// Both operands cp.async, 3-deep pipeline, 2 CTAs/SM. Z from g_Z.
// ---------------------------------------------------------------------------
#define WHS_RB   272                // 128 f x 2B + 16 pad
#define PS_RB    144                // 64 j x 2B + 16 pad
#define WHS_BUF  17408              // 64 rows x 272
#define PS_BUF   18432              // 128 rows x 144
#define SM_PS    52224              // 3 * WHS_BUF
#define SM_ATTN_TOTAL 107520        // SM_PS + 3*PS_BUF

__device__ __forceinline__ void stage_tiles(u32 smb, int bsel,
                                            const __half* bh, const __half* prow,
                                            int j0, int f0, int tid) {
    u32 wbase = smb + (u32)bsel * WHS_BUF;
    #pragma unroll
    for (int s = 0; s < 4; s++) {
        int u = tid + 256 * s;
        int row = u >> 4, fo = u & 15;
        cpa16(wbase + row * WHS_RB + fo * 16,
              bh + (size_t)(j0 + row) * FD + f0 + fo * 8);
    }
    u32 pbase = smb + SM_PS + (u32)bsel * PS_BUF;
    #pragma unroll
    for (int s = 0; s < 4; s++) {
        int u = tid + 256 * s;
        int row = u >> 3, jo = u & 7;
        cpa16(pbase + row * PS_RB + jo * 16,
              prow + (size_t)row * T2 + j0 + jo * 8);
    }
    asm volatile("cp.async.commit_group;" ::: "memory");
}

__global__ __launch_bounds__(256, 2) void k_attn_mma(float* __restrict__ out) {
    extern __shared__ char sm[];
    const u32 smb = smem_u32(sm);
    const int tid = threadIdx.x;
    const int lane = tid & 31, wid = tid >> 5;
    const int wm = wid & 3, wn = wid >> 2;   // 4 x 2 warp grid
    const int b  = blockIdx.z;
    const int i0 = blockIdx.x * MI;
    const int f0 = blockIdx.y * NF;

    const __half* bhsrc = g_B + (size_t)b * T2 * FD;
    const __half* prow  = g_P + ((size_t)(b * T2 + i0)) * T2;

    stage_tiles(smb, 0, bhsrc, prow, 0, f0, tid);
    stage_tiles(smb, 1, bhsrc, prow, KC, f0, tid);

    float acc[2][8][4];
    #pragma unroll
    for (int m = 0; m < 2; m++)
        #pragma unroll
        for (int n = 0; n < 8; n++)
            #pragma unroll
            for (int e = 0; e < 4; e++) acc[m][n][e] = 0.f;

    const u32 a_lane = (u32)(lane & 15) * PS_RB + (u32)(lane >> 4) * 16;
    const u32 b_lane = (u32)(lane & 15) * WHS_RB + (u32)(lane >> 4) * 16;
    const u32 pa_base = smb + SM_PS + (u32)(wm * 32) * PS_RB + a_lane;

    asm volatile("cp.async.wait_group 1;" ::: "memory");
    __syncthreads();

    for (int c = 0; c < NCHUNK; c++) {
        if (c + 2 < NCHUNK)
            stage_tiles(smb, (c + 2) % 3, bhsrc, prow, (c + 2) * KC, f0, tid);

        const u32 pa = pa_base + (u32)(c % 3) * PS_BUF;
        const u32 wb = smb + (u32)(c % 3) * WHS_BUF + (u32)(wn * 64) * 2 + b_lane;
        #pragma unroll
        for (int kk = 0; kk < 4; kk++) {
            u32 ap_[2][4];
            ldsm_x4(ap_[0], pa + kk * 32);
            ldsm_x4(ap_[1], pa + kk * 32 + 16 * PS_RB);
            #pragma unroll
            for (int nt = 0; nt < 4; nt++) {
                u32 bhv[4];
                ldsm_x4t(bhv, wb + (u32)kk * 16 * WHS_RB + (u32)nt * 32);
                #pragma unroll
                for (int mt = 0; mt < 2; mt++) {
                    mma_f16(acc[mt][2 * nt],     ap_[mt], bhv[0], bhv[1]);
                    mma_f16(acc[mt][2 * nt + 1], ap_[mt], bhv[2], bhv[3]);
                }
            }
        }

        if (c + 2 < NCHUNK)
            asm volatile("cp.async.wait_group 1;" ::: "memory");
        else
            asm volatile("cp.async.wait_group 0;" ::: "memory");
        __syncthreads();
    }

    // epilogue: normalize (Z from g_Z), elu, split-write
    #pragma unroll
    for (int mt = 0; mt < 2; mt++) {
        int il = wm * 32 + mt * 16 + (lane >> 2);
        int g1 = i0 + il, g2 = g1 + 8;
        float inv1 = 1.f / g_Z[b * T2 + g1];
        float inv2 = 1.f / g_Z[b * T2 + g2];
        size_t base1 = (g1 < TT) ? ((size_t)b * TT + g1) * FD
                                 : ((size_t)BS * TT + (size_t)b * TT + (g1 - TT)) * FD;
        size_t base2 = (g2 < TT) ? ((size_t)b * TT + g2) * FD
                                 : ((size_t)BS * TT + (size_t)b * TT + (g2 - TT)) * FD;
        #pragma unroll
        for (int nt = 0; nt < 8; nt++) {
            int col = f0 + wn * 64 + nt * 8 + (lane & 3) * 2;
            float2 v1, v2;
            float x;
            x = acc[mt][nt][0] * inv1; v1.x = x > 0.f ? x : expm1f(x);
            x = acc[mt][nt][1] * inv1; v1.y = x > 0.f ? x : expm1f(x);
            x = acc[mt][nt][2] * inv2; v2.x = x > 0.f ? x : expm1f(x);
            x = acc[mt][nt][3] * inv2; v2.y = x > 0.f ? x : expm1f(x);
            *(float2*)&out[base1 + col] = v1;
            *(float2*)&out[base2 + col] = v2;
        }
    }
}

// ---------------------------------------------------------------------------
extern "C" void kernel_launch(void* const* d_in, const int* in_sizes, int n_in,
                              void* d_out, int out_size) {
    const float* xa  = (const float*)d_in[0];
    const float* xv  = (const float*)d_in[1];
    const int*   adj = (const int*)d_in[2];
    const float* W   = (const float*)d_in[3];
    const float* a   = (const float*)d_in[4];
    float* out = (float*)d_out;

    cudaFuncSetAttribute(k_wh_mma, cudaFuncAttributeMaxDynamicSharedMemorySize,
                         SW_TOTAL);
    cudaFuncSetAttribute(k_attn_mma, cudaFuncAttributeMaxDynamicSharedMemorySize,
                         SM_ATTN_TOTAL);

    k_pack<<<BS * T2 * (T2 / 32) / 256, 256>>>(adj);
    k_u<<<FD / 8, 256>>>(W, a);
    k_w12<<<BS * T2 / 8, 256>>>(xa, xv);
    k_prep<<<BS, 256>>>();
    k_p<<<BS * T2, 256>>>();                 // 32768 blocks, one row each
    dim3 gA(FD / 128, T2 / 128, BS);
    k_wh_mma<<<gA, 256, SW_TOTAL>>>(xa, xv, W);
    dim3 gC(T2 / MI, FD / NF, BS);           // 16 x 4 x 16 = 1024 blocks
    k_attn_mma<<<gC, 256, SM_ATTN_TOTAL>>>(out);
}